// round 1
// baseline (speedup 1.0000x reference)
#include <cuda_runtime.h>
#include <cuda_bf16.h>
#include <cstdint>

#define BATCH 16
#define DIM 256
#define HH 56
#define WW 56
#define HWX (HH*WW)          // 3136
#define HEADS 8
#define DH 32
#define HP1 28
#define HW1 (HP1*HP1)        // 784
#define HP2 14
#define HWP (HP2*HP2)        // 196
#define BN_EPS 1e-5f

// ---------------- scratch (device globals; no allocations allowed) ----------------
__device__ float g_qlocal[BATCH*DIM*HWX];
__device__ float g_p0[BATCH*DIM*HW1];
__device__ float g_pmid[BATCH*DIM*HW1];
__device__ float g_pfin[BATCH*DIM*HWP];
__device__ float g_kv[BATCH*2*DIM*HWP];
__device__ float g_gf[BATCH*DIM*HWX];
__device__ float g_mix[BATCH*DIM*HWX];

// ---------------- 1x1 conv as batched SGEMM: Y[b] = W(CO x CI) @ X[b](CI x HW) + bias ----------------
// grid: (ceil(HW/64), CO/64, BATCH), block 256, each thread 4x4 micro-tile.
__global__ __launch_bounds__(256) void conv1x1_kernel(
    const float* __restrict__ Wt, const float* __restrict__ X,
    const float* __restrict__ bias, float* __restrict__ Y,
    int CO, int CI, int HW) {
  __shared__ float Ws[16][64];
  __shared__ float Xs[16][64];
  int tid = threadIdx.x;
  int tx = tid & 15, ty = tid >> 4;
  int m0 = blockIdx.y * 64, n0 = blockIdx.x * 64;
  int b = blockIdx.z;
  const float* Xb = X + (size_t)b * CI * HW;
  float* Yb = Y + (size_t)b * CO * HW;
  float acc[4][4] = {};
  for (int k0 = 0; k0 < CI; k0 += 16) {
#pragma unroll
    for (int i = 0; i < 4; i++) {
      int idx = tid + i * 256;            // 1024 = 64m x 16k
      int m = idx >> 4, k = idx & 15;
      Ws[k][m] = Wt[(size_t)(m0 + m) * CI + k0 + k];
    }
#pragma unroll
    for (int i = 0; i < 4; i++) {
      int idx = tid + i * 256;            // 1024 = 16k x 64n
      int k = idx >> 6, n = idx & 63;
      int gn = n0 + n;
      Xs[k][n] = (gn < HW) ? Xb[(size_t)(k0 + k) * HW + gn] : 0.f;
    }
    __syncthreads();
#pragma unroll
    for (int k = 0; k < 16; k++) {
      float4 av = *(const float4*)&Ws[k][ty * 4];
      float4 xv = *(const float4*)&Xs[k][tx * 4];
      float a[4] = {av.x, av.y, av.z, av.w};
      float xr[4] = {xv.x, xv.y, xv.z, xv.w};
#pragma unroll
      for (int i = 0; i < 4; i++)
#pragma unroll
        for (int j = 0; j < 4; j++) acc[i][j] += a[i] * xr[j];
    }
    __syncthreads();
  }
#pragma unroll
  for (int i = 0; i < 4; i++) {
    int m = m0 + ty * 4 + i;
    float bsv = bias[m];
#pragma unroll
    for (int j = 0; j < 4; j++) {
      int n = n0 + tx * 4 + j;
      if (n < HW) Yb[(size_t)m * HW + n] = acc[i][j] + bsv;
    }
  }
}

// ---------------- depthwise 5x5 stride2 pad2 + BatchNorm ----------------
__global__ __launch_bounds__(256) void dw_s2_bn_kernel(
    const float* __restrict__ X, const float* __restrict__ Wd,
    const float* __restrict__ bias, const float* __restrict__ gam,
    const float* __restrict__ bet, const float* __restrict__ mu,
    const float* __restrict__ var, float* __restrict__ Y,
    int Hin, int Win, int Hout, int Wout) {
  int idx = blockIdx.x * 256 + threadIdx.x;
  int total = BATCH * DIM * Hout * Wout;
  if (idx >= total) return;
  int ox = idx % Wout; int t = idx / Wout;
  int oy = t % Hout; t /= Hout;
  int c = t % DIM; int b = t / DIM;
  const float* xp = X + (size_t)(b * DIM + c) * Hin * Win;
  const float* wp = Wd + c * 25;
  float s = 0.f;
#pragma unroll
  for (int ky = 0; ky < 5; ky++) {
    int iy = oy * 2 - 2 + ky;
    if (iy < 0 || iy >= Hin) continue;
#pragma unroll
    for (int kx = 0; kx < 5; kx++) {
      int ix = ox * 2 - 2 + kx;
      if (ix < 0 || ix >= Win) continue;
      s += xp[iy * Win + ix] * wp[ky * 5 + kx];
    }
  }
  s += bias[c];
  float sc = gam[c] * rsqrtf(var[c] + BN_EPS);
  Y[idx] = (s - mu[c]) * sc + bet[c];
}

// ---------------- attention: warp-per-query, K/V resident in smem ----------------
// scores over 196 keys (padded to 224), softmax, P@V. gf layout [b][c][hw].
__global__ __launch_bounds__(256) void attn_kernel(
    const float* __restrict__ Q, const float* __restrict__ KV,
    float* __restrict__ GF) {
  extern __shared__ float sm[];
  float* Ks = sm;                    // [32 d][224 j]
  float* Vs = sm + 32 * 224;         // [224 j][33 pad, d in 0..31]
  float* Tr = Vs + 224 * 33;         // per-warp: q-tile [32][33] + out-tile [32][33]
  int tid = threadIdx.x;
  int bh = blockIdx.x; int b = bh >> 3, h = bh & 7;
  const float* kvb = KV + (size_t)b * (2 * DIM * HWP);
  for (int i = tid; i < 32 * 224; i += 256) {
    int d = i / 224, j = i % 224;
    float kvk = 0.f, kvv = 0.f;
    if (j < HWP) {
      kvk = kvb[(size_t)(h * 32 + d) * HWP + j];
      kvv = kvb[(size_t)(DIM + h * 32 + d) * HWP + j];
    }
    Ks[d * 224 + j] = kvk;
    Vs[j * 33 + d] = kvv;
  }
  __syncthreads();
  int warp = tid >> 5, lane = tid & 31;
  int q0 = blockIdx.y * 256 + warp * 32;
  if (q0 >= HWX) return;
  const float* qb = Q + ((size_t)b * DIM + h * 32) * HWX;
  float* trq = Tr + warp * 2112;
  float* tro = trq + 1056;
#pragma unroll
  for (int d = 0; d < 32; d++) trq[d * 33 + lane] = qb[(size_t)d * HWX + q0 + lane];
  __syncwarp();
  const float scal = 0.17677669529663687f;  // 32^-0.5
  for (int qq = 0; qq < 32; qq++) {
    float qv = trq[lane * 33 + qq];
    float sc[7];
#pragma unroll
    for (int t = 0; t < 7; t++) sc[t] = 0.f;
#pragma unroll
    for (int d = 0; d < 32; d++) {
      float qd = __shfl_sync(0xffffffffu, qv, d);
#pragma unroll
      for (int t = 0; t < 7; t++) sc[t] += qd * Ks[d * 224 + t * 32 + lane];
    }
    float mx = -1e30f;
#pragma unroll
    for (int t = 0; t < 7; t++) {
      sc[t] *= scal;
      if (t * 32 + lane >= HWP) sc[t] = -1e30f;
      mx = fmaxf(mx, sc[t]);
    }
#pragma unroll
    for (int o = 16; o > 0; o >>= 1) mx = fmaxf(mx, __shfl_xor_sync(0xffffffffu, mx, o));
    float sum = 0.f;
#pragma unroll
    for (int t = 0; t < 7; t++) { sc[t] = __expf(sc[t] - mx); sum += sc[t]; }
#pragma unroll
    for (int o = 16; o > 0; o >>= 1) sum += __shfl_xor_sync(0xffffffffu, sum, o);
    float acc = 0.f;
#pragma unroll
    for (int t = 0; t < 7; t++) {
#pragma unroll
      for (int jj = 0; jj < 32; jj++) {
        float p = __shfl_sync(0xffffffffu, sc[t], jj);
        acc += p * Vs[(t * 32 + jj) * 33 + lane];
      }
    }
    tro[lane * 33 + qq] = acc / sum;
  }
  __syncwarp();
  float* gfb = GF + ((size_t)b * DIM + h * 32) * HWX;
#pragma unroll
  for (int d = 0; d < 32; d++) gfb[(size_t)d * HWX + q0 + lane] = tro[d * 33 + lane];
}

// ---------------- local mixer: dw5x5 s1 pad2 on q_local, SiLU, gate by sigmoid(gf), * gf ----------------
__global__ __launch_bounds__(256) void local_gate_kernel(
    const float* __restrict__ Q, const float* __restrict__ Wd,
    const float* __restrict__ bias, const float* __restrict__ G,
    float* __restrict__ Out) {
  int idx = blockIdx.x * 256 + threadIdx.x;
  int total = BATCH * DIM * HWX;
  if (idx >= total) return;
  int ox = idx % WW; int t = idx / WW;
  int oy = t % HH; t /= HH;
  int c = t % DIM; int b = t / DIM;
  const float* xp = Q + (size_t)(b * DIM + c) * HWX;
  const float* wp = Wd + c * 25;
  float s = 0.f;
#pragma unroll
  for (int ky = 0; ky < 5; ky++) {
    int iy = oy + ky - 2;
    if (iy < 0 || iy >= HH) continue;
#pragma unroll
    for (int kx = 0; kx < 5; kx++) {
      int ix = ox + kx - 2;
      if (ix < 0 || ix >= WW) continue;
      s += xp[iy * WW + ix] * wp[ky * 5 + kx];
    }
  }
  s += bias[c];
  float lf = s / (1.f + __expf(-s));          // SiLU
  float gv = G[idx];
  float sg = 1.f / (1.f + __expf(-gv));       // sigmoid(global)
  Out[idx] = lf * sg * gv;
}

extern "C" void kernel_launch(void* const* d_in, const int* in_sizes, int n_in,
                              void* d_out, int out_size) {
  const float* x     = (const float*)d_in[0];
  const float* q_w   = (const float*)d_in[1];
  const float* q_b   = (const float*)d_in[2];
  const float* kv_w  = (const float*)d_in[3];
  const float* kv_b  = (const float*)d_in[4];
  const float* p0_w  = (const float*)d_in[5];
  const float* p0_b  = (const float*)d_in[6];
  const float* bn0_g = (const float*)d_in[7];
  const float* bn0_b = (const float*)d_in[8];
  const float* bn0_m = (const float*)d_in[9];
  const float* bn0_v = (const float*)d_in[10];
  const float* pl0_w = (const float*)d_in[11];
  const float* pl0_b = (const float*)d_in[12];
  const float* p1_w  = (const float*)d_in[13];
  const float* p1_b  = (const float*)d_in[14];
  const float* bn1_g = (const float*)d_in[15];
  const float* bn1_b = (const float*)d_in[16];
  const float* bn1_m = (const float*)d_in[17];
  const float* bn1_v = (const float*)d_in[18];
  const float* loc_w = (const float*)d_in[19];
  const float* loc_b = (const float*)d_in[20];
  const float* mix_w = (const float*)d_in[21];
  const float* mix_b = (const float*)d_in[22];
  float* out = (float*)d_out;

  float *qlocal, *p0buf, *pmid, *pfin, *kvbuf, *gf, *mixbuf;
  cudaGetSymbolAddress((void**)&qlocal, g_qlocal);
  cudaGetSymbolAddress((void**)&p0buf,  g_p0);
  cudaGetSymbolAddress((void**)&pmid,   g_pmid);
  cudaGetSymbolAddress((void**)&pfin,   g_pfin);
  cudaGetSymbolAddress((void**)&kvbuf,  g_kv);
  cudaGetSymbolAddress((void**)&gf,     g_gf);
  cudaGetSymbolAddress((void**)&mixbuf, g_mix);

  static int smem_set = 0;
  const int attn_smem = (32 * 224 + 224 * 33 + 8 * 2112) * 4;  // 125,920 B
  // idempotent; host-side attribute set is capture-safe
  cudaFuncSetAttribute(attn_kernel, cudaFuncAttributeMaxDynamicSharedMemorySize, attn_smem);
  (void)smem_set;

  // 1. q_local = conv1x1(x, q_w) + q_b
  conv1x1_kernel<<<dim3((HWX + 63) / 64, DIM / 64, BATCH), 256>>>(q_w, x, q_b, qlocal, DIM, DIM, HWX);
  // 2. p0 = BN0(dw5x5_s2(x))
  dw_s2_bn_kernel<<<(BATCH * DIM * HW1 + 255) / 256, 256>>>(x, p0_w, p0_b, bn0_g, bn0_b, bn0_m, bn0_v,
                                                            p0buf, HH, WW, HP1, HP1);
  // 3. pmid = conv1x1(p0, pl0_w)
  conv1x1_kernel<<<dim3((HW1 + 63) / 64, DIM / 64, BATCH), 256>>>(pl0_w, p0buf, pl0_b, pmid, DIM, DIM, HW1);
  // 4. pfin = BN1(dw5x5_s2(pmid))
  dw_s2_bn_kernel<<<(BATCH * DIM * HWP + 255) / 256, 256>>>(pmid, p1_w, p1_b, bn1_g, bn1_b, bn1_m, bn1_v,
                                                            pfin, HP1, HP1, HP2, HP2);
  // 5. kv = conv1x1(pfin, kv_w)
  conv1x1_kernel<<<dim3((HWP + 63) / 64, (2 * DIM) / 64, BATCH), 256>>>(kv_w, pfin, kv_b, kvbuf, 2 * DIM, DIM, HWP);
  // 6. attention -> gf
  attn_kernel<<<dim3(BATCH * HEADS, (HWX + 255) / 256), 256, attn_smem>>>(qlocal, kvbuf, gf);
  // 7. local mixer + gating -> mixbuf
  local_gate_kernel<<<(BATCH * DIM * HWX + 255) / 256, 256>>>(qlocal, loc_w, loc_b, gf, mixbuf);
  // 8. out = conv1x1(mixbuf, mix_w)
  conv1x1_kernel<<<dim3((HWX + 63) / 64, DIM / 64, BATCH), 256>>>(mix_w, mixbuf, mix_b, out, DIM, DIM, HWX);
}

// round 2
// speedup vs baseline: 1.6198x; 1.6198x over previous
#include <cuda_runtime.h>
#include <cuda_bf16.h>
#include <cstdint>

#define BATCH 16
#define DIM 256
#define HH 56
#define WW 56
#define HWX (HH*WW)          // 3136
#define HEADS 8
#define DH 32
#define HP1 28
#define HW1 (HP1*HP1)        // 784
#define HP2 14
#define HWP (HP2*HP2)        // 196
#define BN_EPS 1e-5f

// packed f32x2 fused multiply-add: d = a*b + d (2 MACs per instruction)
#define FFMA2(acc, a, b) asm("fma.rn.f32x2 %0, %1, %2, %0;" : "+l"(acc) : "l"(a), "l"(b))

typedef unsigned long long ull;

__device__ __forceinline__ float f2lo(ull v) { return __uint_as_float((unsigned)v); }
__device__ __forceinline__ float f2hi(ull v) { return __uint_as_float((unsigned)(v >> 32)); }

// ---------------- scratch (device globals; no allocations allowed) ----------------
__device__ float g_qlocal[BATCH*DIM*HWX];
__device__ float g_p0[BATCH*DIM*HW1];
__device__ float g_pmid[BATCH*DIM*HW1];
__device__ float g_pfin[BATCH*DIM*HWP];
__device__ float g_kv[BATCH*2*DIM*HWP];
__device__ float g_gf[BATCH*DIM*HWX];
__device__ float g_mix[BATCH*DIM*HWX];

// ---------------- 1x1 conv as batched SGEMM with FFMA2 ----------------
// Y[b] = W(CO x CI) @ X[b](CI x HW) + bias. Tile 128m x 128n, 256 threads,
// 8x8 micro-tile per thread, accumulators are f32x2 pairs along n.
// W is staged in smem DUPLICATED ((w,w) pairs) so the broadcast operand of
// fma.rn.f32x2 needs no packing instructions.
__global__ __launch_bounds__(256, 2) void conv1x1_f2_kernel(
    const float* __restrict__ Wt, const float* __restrict__ X,
    const float* __restrict__ bias, float* __restrict__ Y,
    int CO, int CI, int HW) {
  __shared__ float Wd[16][256];   // [k][2m] duplicated
  __shared__ float Xs[16][128];
  int tid = threadIdx.x;
  int tx = tid & 15, ty = tid >> 4;
  int m0 = blockIdx.y * 128, n0 = blockIdx.x * 128;
  const float* Xb = X + (size_t)blockIdx.z * CI * HW;
  float* Yb = Y + (size_t)blockIdx.z * CO * HW;

  ull acc[8][4];
#pragma unroll
  for (int i = 0; i < 8; i++)
#pragma unroll
    for (int j = 0; j < 4; j++) acc[i][j] = 0ULL;

  int wm = tid >> 1;            // 0..127 (m within tile)
  int wk = (tid & 1) * 8;       // 0 or 8 (k half)
  const float* wsrc = Wt + (size_t)(m0 + wm) * CI + wk;
  int xk = tid >> 4;            // 0..15
  int xn = (tid & 15) * 8;      // 0..120

  for (int k0 = 0; k0 < CI; k0 += 16) {
    // stage W duplicated: Wd[k][2m] = Wd[k][2m+1] = W[m0+m][k0+k]
    float4 w0 = *(const float4*)&wsrc[k0];
    float4 w1 = *(const float4*)&wsrc[k0 + 4];
    float wv[8] = {w0.x, w0.y, w0.z, w0.w, w1.x, w1.y, w1.z, w1.w};
#pragma unroll
    for (int j = 0; j < 8; j++)
      *(float2*)&Wd[wk + j][2 * wm] = make_float2(wv[j], wv[j]);
    // stage X
#pragma unroll
    for (int c = 0; c < 2; c++) {
      int n = n0 + xn + c * 4;
      float4 v = make_float4(0.f, 0.f, 0.f, 0.f);
      if (n + 3 < HW) v = *(const float4*)&Xb[(size_t)(k0 + xk) * HW + n];
      *(float4*)&Xs[xk][xn + c * 4] = v;
    }
    __syncthreads();
#pragma unroll
    for (int k = 0; k < 16; k++) {
      ulonglong2 a01 = *(const ulonglong2*)&Wd[k][ty * 16];
      ulonglong2 a23 = *(const ulonglong2*)&Wd[k][ty * 16 + 4];
      ulonglong2 a45 = *(const ulonglong2*)&Wd[k][ty * 16 + 8];
      ulonglong2 a67 = *(const ulonglong2*)&Wd[k][ty * 16 + 12];
      ulonglong2 x03 = *(const ulonglong2*)&Xs[k][tx * 8];
      ulonglong2 x47 = *(const ulonglong2*)&Xs[k][tx * 8 + 4];
      ull av[8] = {a01.x, a01.y, a23.x, a23.y, a45.x, a45.y, a67.x, a67.y};
      ull xv[4] = {x03.x, x03.y, x47.x, x47.y};
#pragma unroll
      for (int i = 0; i < 8; i++)
#pragma unroll
        for (int j = 0; j < 4; j++) FFMA2(acc[i][j], av[i], xv[j]);
    }
    __syncthreads();
  }
#pragma unroll
  for (int i = 0; i < 8; i++) {
    int m = m0 + ty * 8 + i;
    float bv = bias[m];
    float o[8];
#pragma unroll
    for (int j = 0; j < 4; j++) { o[2*j] = f2lo(acc[i][j]) + bv; o[2*j+1] = f2hi(acc[i][j]) + bv; }
#pragma unroll
    for (int c = 0; c < 2; c++) {
      int n = n0 + tx * 8 + c * 4;
      if (n + 3 < HW)
        *(float4*)&Yb[(size_t)m * HW + n] = make_float4(o[c*4], o[c*4+1], o[c*4+2], o[c*4+3]);
    }
  }
}

// ---------------- depthwise 5x5 stride2 pad2 + BatchNorm ----------------
__global__ __launch_bounds__(256) void dw_s2_bn_kernel(
    const float* __restrict__ X, const float* __restrict__ Wd,
    const float* __restrict__ bias, const float* __restrict__ gam,
    const float* __restrict__ bet, const float* __restrict__ mu,
    const float* __restrict__ var, float* __restrict__ Y,
    int Hin, int Win, int Hout, int Wout) {
  int idx = blockIdx.x * 256 + threadIdx.x;
  int total = BATCH * DIM * Hout * Wout;
  if (idx >= total) return;
  int ox = idx % Wout; int t = idx / Wout;
  int oy = t % Hout; t /= Hout;
  int c = t % DIM; int b = t / DIM;
  const float* xp = X + (size_t)(b * DIM + c) * Hin * Win;
  const float* wp = Wd + c * 25;
  float s = 0.f;
#pragma unroll
  for (int ky = 0; ky < 5; ky++) {
    int iy = oy * 2 - 2 + ky;
    if (iy < 0 || iy >= Hin) continue;
#pragma unroll
    for (int kx = 0; kx < 5; kx++) {
      int ix = ox * 2 - 2 + kx;
      if (ix < 0 || ix >= Win) continue;
      s += xp[iy * Win + ix] * wp[ky * 5 + kx];
    }
  }
  s += bias[c];
  float sc = gam[c] * rsqrtf(var[c] + BN_EPS);
  Y[idx] = (s - mu[c]) * sc + bet[c];
}

// ---------------- attention v2: warp-per-32-queries, FFMA2 everywhere ----------------
// smem layout (floats):
//  KD  [32d][8t][32lane] dup pairs  : 16384 floats (64KB)
//  VS  [32d][228 (196 keys padded)] : 7296  floats (29KB)
//  QS  per-warp [32d][36 (32q+pad)] : 1152*8 floats (37KB)
//  PW  per-warp [8q][200 keys]      : 1600*8 floats (51KB)
#define AT_KD 0
#define AT_VS 16384
#define AT_QS (AT_VS + 7296)
#define AT_PW (AT_QS + 1152*8)
#define AT_FLOATS (AT_PW + 1600*8)
#define AT_BYTES (AT_FLOATS * 4)

__global__ __launch_bounds__(256, 1) void attn2_kernel(
    const float* __restrict__ Q, const float* __restrict__ KV,
    float* __restrict__ GF) {
  extern __shared__ float sm[];
  int tid = threadIdx.x, lane = tid & 31, warp = tid >> 5;
  int bh = blockIdx.x, b = bh >> 3, h = bh & 7;
  const float* kvb = KV + (size_t)b * (2 * DIM * HWP);

  // stage K duplicated: KD[d][t][l] = (k,k) where key j = l*8+t (zero-pad j>=196)
  for (int idx = tid; idx < 32 * 256; idx += 256) {
    int d = idx >> 8, j = idx & 255;
    float kvk = (j < HWP) ? kvb[(size_t)(h * 32 + d) * HWP + j] : 0.f;
    int l = j >> 3, t = j & 7;
    *(float2*)&sm[AT_KD + ((d * 8 + t) * 32 + l) * 2] = make_float2(kvk, kvk);
  }
  // stage V: VS[d][j]
  for (int idx = tid; idx < 32 * HWP; idx += 256) {
    int d = idx / HWP, j = idx - d * HWP;
    sm[AT_VS + d * 228 + j] = kvb[(size_t)(DIM + h * 32 + d) * HWP + j];
  }
  __syncthreads();

  int q0 = blockIdx.y * 256 + warp * 32;
  if (q0 >= HWX) return;
  float* QS = sm + AT_QS + warp * 1152;
  float* PW = sm + AT_PW + warp * 1600;
  const float scal = 0.17677669529663687f;  // 32^-0.5, folded into Q

  {  // stage Q tile (lane = d), pre-scaled
    const float* qrow = Q + ((size_t)(b * DIM + h * 32 + lane)) * HWX + q0;
#pragma unroll
    for (int c = 0; c < 8; c++) {
      float4 v = *(const float4*)&qrow[c * 4];
      v.x *= scal; v.y *= scal; v.z *= scal; v.w *= scal;
      *(float4*)&QS[lane * 36 + c * 4] = v;
    }
  }
  __syncwarp();

  float* gfb = GF + ((size_t)(b * DIM + h * 32 + lane)) * HWX + q0;
  int nv = HWP - lane * 8;                 // valid keys for this lane
  nv = nv < 0 ? 0 : (nv > 8 ? 8 : nv);

  for (int qc = 0; qc < 4; qc++) {         // 4 chunks of 8 queries
    // ---- QK: acc[qpair][t], pair = 2 adjacent queries, lane owns keys lane*8+t
    ull acc[4][8];
#pragma unroll
    for (int i = 0; i < 4; i++)
#pragma unroll
      for (int t = 0; t < 8; t++) acc[i][t] = 0ULL;
    for (int d = 0; d < 32; d++) {
      ulonglong2 qA = *(const ulonglong2*)&QS[d * 36 + qc * 8];
      ulonglong2 qB = *(const ulonglong2*)&QS[d * 36 + qc * 8 + 4];
      const float* kp = &sm[AT_KD + d * 512 + lane * 2];
#pragma unroll
      for (int t = 0; t < 8; t++) {
        ull kd = *(const ull*)&kp[t * 64];
        FFMA2(acc[0][t], qA.x, kd);
        FFMA2(acc[1][t], qA.y, kd);
        FFMA2(acc[2][t], qB.x, kd);
        FFMA2(acc[3][t], qB.y, kd);
      }
    }
    // ---- softmax (per query, keys spread across lanes) + stage P
    float r[8];
#pragma unroll
    for (int qp = 0; qp < 4; qp++) {
      float slo[8], shi[8];
#pragma unroll
      for (int t = 0; t < 8; t++) { slo[t] = f2lo(acc[qp][t]); shi[t] = f2hi(acc[qp][t]); }
      float mx0 = -1e30f, mx1 = -1e30f;
#pragma unroll
      for (int t = 0; t < 8; t++)
        if (t < nv) { mx0 = fmaxf(mx0, slo[t]); mx1 = fmaxf(mx1, shi[t]); }
#pragma unroll
      for (int o = 16; o > 0; o >>= 1) {
        mx0 = fmaxf(mx0, __shfl_xor_sync(0xffffffffu, mx0, o));
        mx1 = fmaxf(mx1, __shfl_xor_sync(0xffffffffu, mx1, o));
      }
      float s0 = 0.f, s1 = 0.f;
#pragma unroll
      for (int t = 0; t < 8; t++) {
        float e0 = (t < nv) ? __expf(slo[t] - mx0) : 0.f;
        float e1 = (t < nv) ? __expf(shi[t] - mx1) : 0.f;
        slo[t] = e0; shi[t] = e1; s0 += e0; s1 += e1;
      }
#pragma unroll
      for (int o = 16; o > 0; o >>= 1) {
        s0 += __shfl_xor_sync(0xffffffffu, s0, o);
        s1 += __shfl_xor_sync(0xffffffffu, s1, o);
      }
      r[2 * qp] = 1.f / s0; r[2 * qp + 1] = 1.f / s1;
      if (lane < 25) {  // lanes 25+ would overflow the 200-float P row (all masked anyway)
        *(float4*)&PW[(2*qp) * 200 + lane * 8]     = make_float4(slo[0], slo[1], slo[2], slo[3]);
        *(float4*)&PW[(2*qp) * 200 + lane * 8 + 4] = make_float4(slo[4], slo[5], slo[6], slo[7]);
        *(float4*)&PW[(2*qp+1) * 200 + lane * 8]     = make_float4(shi[0], shi[1], shi[2], shi[3]);
        *(float4*)&PW[(2*qp+1) * 200 + lane * 8 + 4] = make_float4(shi[4], shi[5], shi[6], shi[7]);
      }
    }
    __syncwarp();
    // ---- PV: lane = d, f32x2 pairs along keys, 4 keys per iteration
    ull pacc[8];
#pragma unroll
    for (int qi = 0; qi < 8; qi++) pacc[qi] = 0ULL;
    for (int jj = 0; jj < 49; jj++) {
      ulonglong2 vv = *(const ulonglong2*)&sm[AT_VS + lane * 228 + jj * 4];
#pragma unroll
      for (int qi = 0; qi < 8; qi++) {
        ulonglong2 pp = *(const ulonglong2*)&PW[qi * 200 + jj * 4];
        FFMA2(pacc[qi], pp.x, vv.x);
        FFMA2(pacc[qi], pp.y, vv.y);
      }
    }
    float o[8];
#pragma unroll
    for (int qi = 0; qi < 8; qi++) o[qi] = (f2lo(pacc[qi]) + f2hi(pacc[qi])) * r[qi];
    *(float4*)&gfb[qc * 8]     = make_float4(o[0], o[1], o[2], o[3]);
    *(float4*)&gfb[qc * 8 + 4] = make_float4(o[4], o[5], o[6], o[7]);
    __syncwarp();
  }
}

// ---------------- local mixer: dw5x5 s1 pad2, SiLU, gate by sigmoid(gf), * gf ----------------
__global__ __launch_bounds__(256) void local_gate_kernel(
    const float* __restrict__ Q, const float* __restrict__ Wd,
    const float* __restrict__ bias, const float* __restrict__ G,
    float* __restrict__ Out) {
  int idx = blockIdx.x * 256 + threadIdx.x;
  int total = BATCH * DIM * HWX;
  if (idx >= total) return;
  int ox = idx % WW; int t = idx / WW;
  int oy = t % HH; t /= HH;
  int c = t % DIM; int b = t / DIM;
  const float* xp = Q + (size_t)(b * DIM + c) * HWX;
  const float* wp = Wd + c * 25;
  float s = 0.f;
#pragma unroll
  for (int ky = 0; ky < 5; ky++) {
    int iy = oy + ky - 2;
    if (iy < 0 || iy >= HH) continue;
#pragma unroll
    for (int kx = 0; kx < 5; kx++) {
      int ix = ox + kx - 2;
      if (ix < 0 || ix >= WW) continue;
      s += xp[iy * WW + ix] * wp[ky * 5 + kx];
    }
  }
  s += bias[c];
  float lf = s / (1.f + __expf(-s));          // SiLU
  float gv = G[idx];
  float sg = 1.f / (1.f + __expf(-gv));       // sigmoid(global)
  Out[idx] = lf * sg * gv;
}

extern "C" void kernel_launch(void* const* d_in, const int* in_sizes, int n_in,
                              void* d_out, int out_size) {
  const float* x     = (const float*)d_in[0];
  const float* q_w   = (const float*)d_in[1];
  const float* q_b   = (const float*)d_in[2];
  const float* kv_w  = (const float*)d_in[3];
  const float* kv_b  = (const float*)d_in[4];
  const float* p0_w  = (const float*)d_in[5];
  const float* p0_b  = (const float*)d_in[6];
  const float* bn0_g = (const float*)d_in[7];
  const float* bn0_b = (const float*)d_in[8];
  const float* bn0_m = (const float*)d_in[9];
  const float* bn0_v = (const float*)d_in[10];
  const float* pl0_w = (const float*)d_in[11];
  const float* pl0_b = (const float*)d_in[12];
  const float* p1_w  = (const float*)d_in[13];
  const float* p1_b  = (const float*)d_in[14];
  const float* bn1_g = (const float*)d_in[15];
  const float* bn1_b = (const float*)d_in[16];
  const float* bn1_m = (const float*)d_in[17];
  const float* bn1_v = (const float*)d_in[18];
  const float* loc_w = (const float*)d_in[19];
  const float* loc_b = (const float*)d_in[20];
  const float* mix_w = (const float*)d_in[21];
  const float* mix_b = (const float*)d_in[22];
  float* out = (float*)d_out;

  float *qlocal, *p0buf, *pmid, *pfin, *kvbuf, *gf, *mixbuf;
  cudaGetSymbolAddress((void**)&qlocal, g_qlocal);
  cudaGetSymbolAddress((void**)&p0buf,  g_p0);
  cudaGetSymbolAddress((void**)&pmid,   g_pmid);
  cudaGetSymbolAddress((void**)&pfin,   g_pfin);
  cudaGetSymbolAddress((void**)&kvbuf,  g_kv);
  cudaGetSymbolAddress((void**)&gf,     g_gf);
  cudaGetSymbolAddress((void**)&mixbuf, g_mix);

  cudaFuncSetAttribute(attn2_kernel, cudaFuncAttributeMaxDynamicSharedMemorySize, AT_BYTES);

  // 1. q_local = conv1x1(x, q_w) + q_b
  conv1x1_f2_kernel<<<dim3((HWX + 127) / 128, DIM / 128, BATCH), 256>>>(q_w, x, q_b, qlocal, DIM, DIM, HWX);
  // 2. p0 = BN0(dw5x5_s2(x))
  dw_s2_bn_kernel<<<(BATCH * DIM * HW1 + 255) / 256, 256>>>(x, p0_w, p0_b, bn0_g, bn0_b, bn0_m, bn0_v,
                                                            p0buf, HH, WW, HP1, HP1);
  // 3. pmid = conv1x1(p0, pl0_w)
  conv1x1_f2_kernel<<<dim3((HW1 + 127) / 128, DIM / 128, BATCH), 256>>>(pl0_w, p0buf, pl0_b, pmid, DIM, DIM, HW1);
  // 4. pfin = BN1(dw5x5_s2(pmid))
  dw_s2_bn_kernel<<<(BATCH * DIM * HWP + 255) / 256, 256>>>(pmid, p1_w, p1_b, bn1_g, bn1_b, bn1_m, bn1_v,
                                                            pfin, HP1, HP1, HP2, HP2);
  // 5. kv = conv1x1(pfin, kv_w)
  conv1x1_f2_kernel<<<dim3((HWP + 127) / 128, (2 * DIM) / 128, BATCH), 256>>>(kv_w, pfin, kv_b, kvbuf, 2 * DIM, DIM, HWP);
  // 6. attention -> gf
  attn2_kernel<<<dim3(BATCH * HEADS, (HWX + 255) / 256), 256, AT_BYTES>>>(qlocal, kvbuf, gf);
  // 7. local mixer + gating -> mixbuf
  local_gate_kernel<<<(BATCH * DIM * HWX + 255) / 256, 256>>>(qlocal, loc_w, loc_b, gf, mixbuf);
  // 8. out = conv1x1(mixbuf, mix_w)
  conv1x1_f2_kernel<<<dim3((HWX + 127) / 128, DIM / 128, BATCH), 256>>>(mix_w, mixbuf, mix_b, out, DIM, DIM, HWX);
}

// round 4
// speedup vs baseline: 1.6855x; 1.0406x over previous
#include <cuda_runtime.h>
#include <cuda_bf16.h>
#include <cstdint>

#define BATCH 16
#define DIM 256
#define HH 56
#define WW 56
#define HWX (HH*WW)          // 3136
#define HEADS 8
#define DH 32
#define HP1 28
#define HW1 (HP1*HP1)        // 784
#define HP2 14
#define HWP (HP2*HP2)        // 196
#define BN_EPS 1e-5f

// packed f32x2 fused multiply-add: d = a*b + d (2 MACs per instruction)
#define FFMA2(acc, a, b) asm("fma.rn.f32x2 %0, %1, %2, %0;" : "+l"(acc) : "l"(a), "l"(b))
typedef unsigned long long ull;
__device__ __forceinline__ float f2lo(ull v) { return __uint_as_float((unsigned)v); }
__device__ __forceinline__ float f2hi(ull v) { return __uint_as_float((unsigned)(v >> 32)); }

#define SW128(x) ((x) ^ (((x) >> 3) & 0x70))

__device__ __forceinline__ uint32_t smem_u32(const void* p) {
  uint32_t a;
  asm("{ .reg .u64 t; cvta.to.shared.u64 t, %1; cvt.u32.u64 %0, t; }" : "=r"(a) : "l"(p));
  return a;
}
__device__ __forceinline__ void ldmA(uint32_t a[4], uint32_t addr) {
  asm volatile("ldmatrix.sync.aligned.m8n8.x4.shared.b16 {%0,%1,%2,%3}, [%4];"
               : "=r"(a[0]), "=r"(a[1]), "=r"(a[2]), "=r"(a[3]) : "r"(addr));
}
__device__ __forceinline__ void ldmB(uint32_t b[2], uint32_t addr) {
  asm volatile("ldmatrix.sync.aligned.m8n8.x2.shared.b16 {%0,%1}, [%2];"
               : "=r"(b[0]), "=r"(b[1]) : "r"(addr));
}
__device__ __forceinline__ void mma16816(float d[4], const uint32_t a[4], const uint32_t b[2]) {
  asm volatile("mma.sync.aligned.m16n8k16.row.col.f32.bf16.bf16.f32 "
               "{%0,%1,%2,%3}, {%4,%5,%6,%7}, {%8,%9}, {%0,%1,%2,%3};"
               : "+f"(d[0]), "+f"(d[1]), "+f"(d[2]), "+f"(d[3])
               : "r"(a[0]), "r"(a[1]), "r"(a[2]), "r"(a[3]), "r"(b[0]), "r"(b[1]));
}

// ---------------- scratch (device globals; no allocations allowed) ----------------
__device__ float g_qlocal[BATCH*DIM*HWX];
__device__ float g_p0[BATCH*DIM*HW1];
__device__ float g_pmid[BATCH*DIM*HW1];
__device__ float g_pfin[BATCH*DIM*HWP];
__device__ float g_kv[BATCH*2*DIM*HWP];
__device__ float g_gf[BATCH*DIM*HWX];
__device__ float g_mix[BATCH*DIM*HWX];

// ---------------- 1x1 conv: split-bf16 HMMA (mma.sync m16n8k16) ----------------
// Y[b](CO x HW) = W(CO x CI) @ X[b](CI x HW) + bias.
// Block tile 128m x 128n, 8 warps (4m x 2n), each warp 32m x 64n.
// K chunks of 64. A = W[m][k] hi/lo bf16, B = X^T[n][k] hi/lo bf16.
// Rows are 64 bf16 = 128B, SW128-swizzled for conflict-free ldmatrix.
// 3 passes: Ah*Bh + Al*Bh + Ah*Bl (lo*lo dropped; ~1e-5 rel err).
#define CV_SMEM 65536

__global__ __launch_bounds__(256) void conv1x1_mma_kernel(
    const float* __restrict__ Wt, const float* __restrict__ X,
    const float* __restrict__ bias, float* __restrict__ Y,
    int CO, int CI, int HW) {
  extern __shared__ __align__(1024) char smem[];
  char* Ahi = smem;
  char* Alo = smem + 16384;
  char* Bhi = smem + 32768;
  char* Blo = smem + 49152;
  uint32_t sAhi = smem_u32(Ahi), sAlo = smem_u32(Alo);
  uint32_t sBhi = smem_u32(Bhi), sBlo = smem_u32(Blo);
  int tid = threadIdx.x, lane = tid & 31, wid = tid >> 5;
  int m0 = blockIdx.y * 128, n0 = blockIdx.x * 128;
  const float* Xb = X + (size_t)blockIdx.z * CI * HW;
  float* Yb = Y + (size_t)blockIdx.z * CO * HW;
  int mw = (wid & 3) * 32, nw = (wid >> 2) * 64;

  float acc[2][8][4];
#pragma unroll
  for (int i = 0; i < 2; i++)
#pragma unroll
    for (int j = 0; j < 8; j++)
#pragma unroll
      for (int l = 0; l < 4; l++) acc[i][j][l] = 0.f;

  for (int k0 = 0; k0 < CI; k0 += 64) {
    // ---- stage A (weights) hi/lo: [m][k], 8 k-elems per thread, vector 16B stores
#pragma unroll
    for (int i = 0; i < 4; i++) {
      int t = tid + i * 256;           // 1024 tasks: 128m x 8 kgroups
      int m = t >> 3, kg = (t & 7) * 8;
      const float* src = &Wt[(size_t)(m0 + m) * CI + k0 + kg];
      float4 v0 = *(const float4*)src;
      float4 v1 = *(const float4*)(src + 4);
      float v[8] = {v0.x, v0.y, v0.z, v0.w, v1.x, v1.y, v1.z, v1.w};
      __nv_bfloat16 hb[8], lb[8];
#pragma unroll
      for (int j = 0; j < 8; j++) {
        hb[j] = __float2bfloat16(v[j]);
        lb[j] = __float2bfloat16(v[j] - __bfloat162float(hb[j]));
      }
      uint32_t off = SW128(m * 128 + kg * 2);
      *(uint4*)(Ahi + off) = *(uint4*)hb;
      *(uint4*)(Alo + off) = *(uint4*)lb;
    }
    // ---- stage B (activations transposed) hi/lo: [n][k]
#pragma unroll
    for (int i = 0; i < 8; i++) {
      int t = tid + i * 256;           // 2048 tasks: 64k x 32 ngroups(4)
      int k = t >> 5, n = (t & 31) * 4;
      int gn = n0 + n;
      float4 v = make_float4(0.f, 0.f, 0.f, 0.f);
      if (gn + 3 < HW) {
        v = *(const float4*)&Xb[(size_t)(k0 + k) * HW + gn];
      } else {
        float* pv = (float*)&v;
#pragma unroll
        for (int j = 0; j < 4; j++)
          if (gn + j < HW) pv[j] = Xb[(size_t)(k0 + k) * HW + gn + j];
      }
      float* pv = (float*)&v;
#pragma unroll
      for (int j = 0; j < 4; j++) {
        __nv_bfloat16 hb = __float2bfloat16(pv[j]);
        __nv_bfloat16 lb = __float2bfloat16(pv[j] - __bfloat162float(hb));
        uint32_t off = SW128((n + j) * 128 + k * 2);
        *(__nv_bfloat16*)(Bhi + off) = hb;
        *(__nv_bfloat16*)(Blo + off) = lb;
      }
    }
    __syncthreads();
    // ---- 4 k16 steps of HMMA
#pragma unroll
    for (int s = 0; s < 4; s++) {
      uint32_t ah[2][4], al[2][4], bh[8][2], bl[8][2];
#pragma unroll
      for (int tm = 0; tm < 2; tm++) {
        uint32_t off = SW128((mw + tm * 16 + (lane & 15)) * 128 + s * 32 + (lane >> 4) * 16);
        ldmA(ah[tm], sAhi + off);
        ldmA(al[tm], sAlo + off);
      }
#pragma unroll
      for (int tn = 0; tn < 8; tn++) {
        int l = lane & 15;
        uint32_t off = SW128((nw + tn * 8 + (l & 7)) * 128 + s * 32 + (l >> 3) * 16);
        ldmB(bh[tn], sBhi + off);
        ldmB(bl[tn], sBlo + off);
      }
#pragma unroll
      for (int tm = 0; tm < 2; tm++)
#pragma unroll
        for (int tn = 0; tn < 8; tn++) {
          mma16816(acc[tm][tn], ah[tm], bh[tn]);
          mma16816(acc[tm][tn], al[tm], bh[tn]);
          mma16816(acc[tm][tn], ah[tm], bl[tn]);
        }
    }
    __syncthreads();
  }
  // ---- epilogue: fragment rows -> gmem, + bias
#pragma unroll
  for (int tm = 0; tm < 2; tm++) {
    int r0 = m0 + mw + tm * 16 + (lane >> 2);
    float b0 = bias[r0], b1 = bias[r0 + 8];
#pragma unroll
    for (int tn = 0; tn < 8; tn++) {
      int col = n0 + nw + tn * 8 + (lane & 3) * 2;
      if (col < HW) {
        *(float2*)&Yb[(size_t)r0 * HW + col] =
            make_float2(acc[tm][tn][0] + b0, acc[tm][tn][1] + b0);
        *(float2*)&Yb[(size_t)(r0 + 8) * HW + col] =
            make_float2(acc[tm][tn][2] + b1, acc[tm][tn][3] + b1);
      }
    }
  }
}

// ---------------- depthwise 5x5 stride2 pad2 + BatchNorm ----------------
__global__ __launch_bounds__(256) void dw_s2_bn_kernel(
    const float* __restrict__ X, const float* __restrict__ Wd,
    const float* __restrict__ bias, const float* __restrict__ gam,
    const float* __restrict__ bet, const float* __restrict__ mu,
    const float* __restrict__ var, float* __restrict__ Y,
    int Hin, int Win, int Hout, int Wout) {
  int idx = blockIdx.x * 256 + threadIdx.x;
  int total = BATCH * DIM * Hout * Wout;
  if (idx >= total) return;
  int ox = idx % Wout; int t = idx / Wout;
  int oy = t % Hout; t /= Hout;
  int c = t % DIM; int b = t / DIM;
  const float* xp = X + (size_t)(b * DIM + c) * Hin * Win;
  const float* wp = Wd + c * 25;
  float s = 0.f;
#pragma unroll
  for (int ky = 0; ky < 5; ky++) {
    int iy = oy * 2 - 2 + ky;
    if (iy < 0 || iy >= Hin) continue;
#pragma unroll
    for (int kx = 0; kx < 5; kx++) {
      int ix = ox * 2 - 2 + kx;
      if (ix < 0 || ix >= Win) continue;
      s += xp[iy * Win + ix] * wp[ky * 5 + kx];
    }
  }
  s += bias[c];
  float sc = gam[c] * rsqrtf(var[c] + BN_EPS);
  Y[idx] = (s - mu[c]) * sc + bet[c];
}

// ---------------- attention: warp-per-32-queries, FFMA2 ----------------
#define AT_KD 0
#define AT_VS 16384
#define AT_QS (AT_VS + 7296)
#define AT_PW (AT_QS + 1152*8)
#define AT_FLOATS (AT_PW + 1600*8)
#define AT_BYTES (AT_FLOATS * 4)

__global__ __launch_bounds__(256, 1) void attn2_kernel(
    const float* __restrict__ Q, const float* __restrict__ KV,
    float* __restrict__ GF) {
  extern __shared__ float sm[];
  int tid = threadIdx.x, lane = tid & 31, warp = tid >> 5;
  int bh = blockIdx.x, b = bh >> 3, h = bh & 7;
  const float* kvb = KV + (size_t)b * (2 * DIM * HWP);

  for (int idx = tid; idx < 32 * 256; idx += 256) {
    int d = idx >> 8, j = idx & 255;
    float kvk = (j < HWP) ? kvb[(size_t)(h * 32 + d) * HWP + j] : 0.f;
    int l = j >> 3, t = j & 7;
    *(float2*)&sm[AT_KD + ((d * 8 + t) * 32 + l) * 2] = make_float2(kvk, kvk);
  }
  for (int idx = tid; idx < 32 * HWP; idx += 256) {
    int d = idx / HWP, j = idx - d * HWP;
    sm[AT_VS + d * 228 + j] = kvb[(size_t)(DIM + h * 32 + d) * HWP + j];
  }
  __syncthreads();

  int q0 = blockIdx.y * 256 + warp * 32;
  if (q0 >= HWX) return;
  float* QS = sm + AT_QS + warp * 1152;
  float* PW = sm + AT_PW + warp * 1600;
  const float scal = 0.17677669529663687f;

  {
    const float* qrow = Q + ((size_t)(b * DIM + h * 32 + lane)) * HWX + q0;
#pragma unroll
    for (int c = 0; c < 8; c++) {
      float4 v = *(const float4*)&qrow[c * 4];
      v.x *= scal; v.y *= scal; v.z *= scal; v.w *= scal;
      *(float4*)&QS[lane * 36 + c * 4] = v;
    }
  }
  __syncwarp();

  float* gfb = GF + ((size_t)(b * DIM + h * 32 + lane)) * HWX + q0;
  int nv = HWP - lane * 8;
  nv = nv < 0 ? 0 : (nv > 8 ? 8 : nv);

  for (int qc = 0; qc < 4; qc++) {
    ull acc[4][8];
#pragma unroll
    for (int i = 0; i < 4; i++)
#pragma unroll
      for (int t = 0; t < 8; t++) acc[i][t] = 0ULL;
    for (int d = 0; d < 32; d++) {
      ulonglong2 qA = *(const ulonglong2*)&QS[d * 36 + qc * 8];
      ulonglong2 qB = *(const ulonglong2*)&QS[d * 36 + qc * 8 + 4];
      const float* kp = &sm[AT_KD + d * 512 + lane * 2];
#pragma unroll
      for (int t = 0; t < 8; t++) {
        ull kd = *(const ull*)&kp[t * 64];
        FFMA2(acc[0][t], qA.x, kd);
        FFMA2(acc[1][t], qA.y, kd);
        FFMA2(acc[2][t], qB.x, kd);
        FFMA2(acc[3][t], qB.y, kd);
      }
    }
    float r[8];
#pragma unroll
    for (int qp = 0; qp < 4; qp++) {
      float slo[8], shi[8];
#pragma unroll
      for (int t = 0; t < 8; t++) { slo[t] = f2lo(acc[qp][t]); shi[t] = f2hi(acc[qp][t]); }
      float mx0 = -1e30f, mx1 = -1e30f;
#pragma unroll
      for (int t = 0; t < 8; t++)
        if (t < nv) { mx0 = fmaxf(mx0, slo[t]); mx1 = fmaxf(mx1, shi[t]); }
#pragma unroll
      for (int o = 16; o > 0; o >>= 1) {
        mx0 = fmaxf(mx0, __shfl_xor_sync(0xffffffffu, mx0, o));
        mx1 = fmaxf(mx1, __shfl_xor_sync(0xffffffffu, mx1, o));
      }
      float s0 = 0.f, s1 = 0.f;
#pragma unroll
      for (int t = 0; t < 8; t++) {
        float e0 = (t < nv) ? __expf(slo[t] - mx0) : 0.f;
        float e1 = (t < nv) ? __expf(shi[t] - mx1) : 0.f;
        slo[t] = e0; shi[t] = e1; s0 += e0; s1 += e1;
      }
#pragma unroll
      for (int o = 16; o > 0; o >>= 1) {
        s0 += __shfl_xor_sync(0xffffffffu, s0, o);
        s1 += __shfl_xor_sync(0xffffffffu, s1, o);
      }
      r[2 * qp] = 1.f / s0; r[2 * qp + 1] = 1.f / s1;
      if (lane < 25) {
        *(float4*)&PW[(2*qp) * 200 + lane * 8]     = make_float4(slo[0], slo[1], slo[2], slo[3]);
        *(float4*)&PW[(2*qp) * 200 + lane * 8 + 4] = make_float4(slo[4], slo[5], slo[6], slo[7]);
        *(float4*)&PW[(2*qp+1) * 200 + lane * 8]     = make_float4(shi[0], shi[1], shi[2], shi[3]);
        *(float4*)&PW[(2*qp+1) * 200 + lane * 8 + 4] = make_float4(shi[4], shi[5], shi[6], shi[7]);
      }
    }
    __syncwarp();
    ull pacc[8];
#pragma unroll
    for (int qi = 0; qi < 8; qi++) pacc[qi] = 0ULL;
    for (int jj = 0; jj < 49; jj++) {
      ulonglong2 vv = *(const ulonglong2*)&sm[AT_VS + lane * 228 + jj * 4];
#pragma unroll
      for (int qi = 0; qi < 8; qi++) {
        ulonglong2 pp = *(const ulonglong2*)&PW[qi * 200 + jj * 4];
        FFMA2(pacc[qi], pp.x, vv.x);
        FFMA2(pacc[qi], pp.y, vv.y);
      }
    }
    float o[8];
#pragma unroll
    for (int qi = 0; qi < 8; qi++) o[qi] = (f2lo(pacc[qi]) + f2hi(pacc[qi])) * r[qi];
    *(float4*)&gfb[qc * 8]     = make_float4(o[0], o[1], o[2], o[3]);
    *(float4*)&gfb[qc * 8 + 4] = make_float4(o[4], o[5], o[6], o[7]);
    __syncwarp();
  }
}

// ---------------- local mixer: dw5x5 s1 pad2, SiLU, gate by sigmoid(gf), * gf ----------------
__global__ __launch_bounds__(256) void local_gate_kernel(
    const float* __restrict__ Q, const float* __restrict__ Wd,
    const float* __restrict__ bias, const float* __restrict__ G,
    float* __restrict__ Out) {
  int idx = blockIdx.x * 256 + threadIdx.x;
  int total = BATCH * DIM * HWX;
  if (idx >= total) return;
  int ox = idx % WW; int t = idx / WW;
  int oy = t % HH; t /= HH;
  int c = t % DIM; int b = t / DIM;
  const float* xp = Q + (size_t)(b * DIM + c) * HWX;
  const float* wp = Wd + c * 25;
  float s = 0.f;
#pragma unroll
  for (int ky = 0; ky < 5; ky++) {
    int iy = oy + ky - 2;
    if (iy < 0 || iy >= HH) continue;
#pragma unroll
    for (int kx = 0; kx < 5; kx++) {
      int ix = ox + kx - 2;
      if (ix < 0 || ix >= WW) continue;
      s += xp[iy * WW + ix] * wp[ky * 5 + kx];
    }
  }
  s += bias[c];
  float lf = s / (1.f + __expf(-s));
  float gv = G[idx];
  float sg = 1.f / (1.f + __expf(-gv));
  Out[idx] = lf * sg * gv;
}

extern "C" void kernel_launch(void* const* d_in, const int* in_sizes, int n_in,
                              void* d_out, int out_size) {
  const float* x     = (const float*)d_in[0];
  const float* q_w   = (const float*)d_in[1];
  const float* q_b   = (const float*)d_in[2];
  const float* kv_w  = (const float*)d_in[3];
  const float* kv_b  = (const float*)d_in[4];
  const float* p0_w  = (const float*)d_in[5];
  const float* p0_b  = (const float*)d_in[6];
  const float* bn0_g = (const float*)d_in[7];
  const float* bn0_b = (const float*)d_in[8];
  const float* bn0_m = (const float*)d_in[9];
  const float* bn0_v = (const float*)d_in[10];
  const float* pl0_w = (const float*)d_in[11];
  const float* pl0_b = (const float*)d_in[12];
  const float* p1_w  = (const float*)d_in[13];
  const float* p1_b  = (const float*)d_in[14];
  const float* bn1_g = (const float*)d_in[15];
  const float* bn1_b = (const float*)d_in[16];
  const float* bn1_m = (const float*)d_in[17];
  const float* bn1_v = (const float*)d_in[18];
  const float* loc_w = (const float*)d_in[19];
  const float* loc_b = (const float*)d_in[20];
  const float* mix_w = (const float*)d_in[21];
  const float* mix_b = (const float*)d_in[22];
  float* out = (float*)d_out;

  float *qlocal, *p0buf, *pmid, *pfin, *kvbuf, *gf, *mixbuf;
  cudaGetSymbolAddress((void**)&qlocal, g_qlocal);
  cudaGetSymbolAddress((void**)&p0buf,  g_p0);
  cudaGetSymbolAddress((void**)&pmid,   g_pmid);
  cudaGetSymbolAddress((void**)&pfin,   g_pfin);
  cudaGetSymbolAddress((void**)&kvbuf,  g_kv);
  cudaGetSymbolAddress((void**)&gf,     g_gf);
  cudaGetSymbolAddress((void**)&mixbuf, g_mix);

  cudaFuncSetAttribute(attn2_kernel, cudaFuncAttributeMaxDynamicSharedMemorySize, AT_BYTES);
  cudaFuncSetAttribute(conv1x1_mma_kernel, cudaFuncAttributeMaxDynamicSharedMemorySize, CV_SMEM);

  // 1. q_local = conv1x1(x, q_w) + q_b
  conv1x1_mma_kernel<<<dim3((HWX + 127) / 128, DIM / 128, BATCH), 256, CV_SMEM>>>(q_w, x, q_b, qlocal, DIM, DIM, HWX);
  // 2. p0 = BN0(dw5x5_s2(x))
  dw_s2_bn_kernel<<<(BATCH * DIM * HW1 + 255) / 256, 256>>>(x, p0_w, p0_b, bn0_g, bn0_b, bn0_m, bn0_v,
                                                            p0buf, HH, WW, HP1, HP1);
  // 3. pmid = conv1x1(p0, pl0_w)
  conv1x1_mma_kernel<<<dim3((HW1 + 127) / 128, DIM / 128, BATCH), 256, CV_SMEM>>>(pl0_w, p0buf, pl0_b, pmid, DIM, DIM, HW1);
  // 4. pfin = BN1(dw5x5_s2(pmid))
  dw_s2_bn_kernel<<<(BATCH * DIM * HWP + 255) / 256, 256>>>(pmid, p1_w, p1_b, bn1_g, bn1_b, bn1_m, bn1_v,
                                                            pfin, HP1, HP1, HP2, HP2);
  // 5. kv = conv1x1(pfin, kv_w)
  conv1x1_mma_kernel<<<dim3((HWP + 127) / 128, (2 * DIM) / 128, BATCH), 256, CV_SMEM>>>(kv_w, pfin, kv_b, kvbuf, 2 * DIM, DIM, HWP);
  // 6. attention -> gf
  attn2_kernel<<<dim3(BATCH * HEADS, (HWX + 255) / 256), 256, AT_BYTES>>>(qlocal, kvbuf, gf);
  // 7. local mixer + gating -> mixbuf
  local_gate_kernel<<<(BATCH * DIM * HWX + 255) / 256, 256>>>(qlocal, loc_w, loc_b, gf, mixbuf);
  // 8. out = conv1x1(mixbuf, mix_w)
  conv1x1_mma_kernel<<<dim3((HWX + 127) / 128, DIM / 128, BATCH), 256, CV_SMEM>>>(mix_w, mixbuf, mix_b, out, DIM, DIM, HWX);
}

// round 5
// speedup vs baseline: 2.1289x; 1.2631x over previous
#include <cuda_runtime.h>
#include <cuda_bf16.h>
#include <cstdint>

#define BATCH 16
#define DIM 256
#define HH 56
#define WW 56
#define HWX (HH*WW)          // 3136
#define HEADS 8
#define DH 32
#define HP1 28
#define HW1 (HP1*HP1)        // 784
#define HP2 14
#define HWP (HP2*HP2)        // 196
#define BN_EPS 1e-5f

#define SW128(x) ((x) ^ (((x) >> 3) & 0x70))

__device__ __forceinline__ uint32_t smem_u32(const void* p) {
  uint32_t a;
  asm("{ .reg .u64 t; cvta.to.shared.u64 t, %1; cvt.u32.u64 %0, t; }" : "=r"(a) : "l"(p));
  return a;
}
__device__ __forceinline__ void ldmA(uint32_t a[4], uint32_t addr) {
  asm volatile("ldmatrix.sync.aligned.m8n8.x4.shared.b16 {%0,%1,%2,%3}, [%4];"
               : "=r"(a[0]), "=r"(a[1]), "=r"(a[2]), "=r"(a[3]) : "r"(addr));
}
__device__ __forceinline__ void ldmB(uint32_t b[2], uint32_t addr) {
  asm volatile("ldmatrix.sync.aligned.m8n8.x2.shared.b16 {%0,%1}, [%2];"
               : "=r"(b[0]), "=r"(b[1]) : "r"(addr));
}
__device__ __forceinline__ void mma16816(float d[4], const uint32_t a[4], const uint32_t b[2]) {
  asm volatile("mma.sync.aligned.m16n8k16.row.col.f32.bf16.bf16.f32 "
               "{%0,%1,%2,%3}, {%4,%5,%6,%7}, {%8,%9}, {%0,%1,%2,%3};"
               : "+f"(d[0]), "+f"(d[1]), "+f"(d[2]), "+f"(d[3])
               : "r"(a[0]), "r"(a[1]), "r"(a[2]), "r"(a[3]), "r"(b[0]), "r"(b[1]));
}

// ---------------- scratch (device globals; no allocations allowed) ----------------
__device__ float g_qlocal[BATCH*DIM*HWX];
__device__ float g_p0[BATCH*DIM*HW1];
__device__ float g_pmid[BATCH*DIM*HW1];
__device__ float g_pfin[BATCH*DIM*HWP];
__device__ float g_kv[BATCH*2*DIM*HWP];
__device__ float g_gf[BATCH*DIM*HWX];
__device__ float g_mix[BATCH*DIM*HWX];

// ---------------- 1x1 conv: split-bf16 HMMA (mma.sync m16n8k16) ----------------
#define CV_SMEM 65536

__global__ __launch_bounds__(256) void conv1x1_mma_kernel(
    const float* __restrict__ Wt, const float* __restrict__ X,
    const float* __restrict__ bias, float* __restrict__ Y,
    int CO, int CI, int HW) {
  extern __shared__ __align__(1024) char smem[];
  char* Ahi = smem;
  char* Alo = smem + 16384;
  char* Bhi = smem + 32768;
  char* Blo = smem + 49152;
  uint32_t sAhi = smem_u32(Ahi), sAlo = smem_u32(Alo);
  uint32_t sBhi = smem_u32(Bhi), sBlo = smem_u32(Blo);
  int tid = threadIdx.x, lane = tid & 31, wid = tid >> 5;
  int m0 = blockIdx.y * 128, n0 = blockIdx.x * 128;
  const float* Xb = X + (size_t)blockIdx.z * CI * HW;
  float* Yb = Y + (size_t)blockIdx.z * CO * HW;
  int mw = (wid & 3) * 32, nw = (wid >> 2) * 64;

  float acc[2][8][4];
#pragma unroll
  for (int i = 0; i < 2; i++)
#pragma unroll
    for (int j = 0; j < 8; j++)
#pragma unroll
      for (int l = 0; l < 4; l++) acc[i][j][l] = 0.f;

  for (int k0 = 0; k0 < CI; k0 += 64) {
#pragma unroll
    for (int i = 0; i < 4; i++) {
      int t = tid + i * 256;
      int m = t >> 3, kg = (t & 7) * 8;
      const float* src = &Wt[(size_t)(m0 + m) * CI + k0 + kg];
      float4 v0 = *(const float4*)src;
      float4 v1 = *(const float4*)(src + 4);
      float v[8] = {v0.x, v0.y, v0.z, v0.w, v1.x, v1.y, v1.z, v1.w};
      __nv_bfloat16 hb[8], lb[8];
#pragma unroll
      for (int j = 0; j < 8; j++) {
        hb[j] = __float2bfloat16(v[j]);
        lb[j] = __float2bfloat16(v[j] - __bfloat162float(hb[j]));
      }
      uint32_t off = SW128(m * 128 + kg * 2);
      *(uint4*)(Ahi + off) = *(uint4*)hb;
      *(uint4*)(Alo + off) = *(uint4*)lb;
    }
#pragma unroll
    for (int i = 0; i < 8; i++) {
      int t = tid + i * 256;
      int k = t >> 5, n = (t & 31) * 4;
      int gn = n0 + n;
      float4 v = make_float4(0.f, 0.f, 0.f, 0.f);
      if (gn + 3 < HW) {
        v = *(const float4*)&Xb[(size_t)(k0 + k) * HW + gn];
      } else {
        float* pv = (float*)&v;
#pragma unroll
        for (int j = 0; j < 4; j++)
          if (gn + j < HW) pv[j] = Xb[(size_t)(k0 + k) * HW + gn + j];
      }
      float* pv = (float*)&v;
#pragma unroll
      for (int j = 0; j < 4; j++) {
        __nv_bfloat16 hb = __float2bfloat16(pv[j]);
        __nv_bfloat16 lb = __float2bfloat16(pv[j] - __bfloat162float(hb));
        uint32_t off = SW128((n + j) * 128 + k * 2);
        *(__nv_bfloat16*)(Bhi + off) = hb;
        *(__nv_bfloat16*)(Blo + off) = lb;
      }
    }
    __syncthreads();
#pragma unroll
    for (int s = 0; s < 4; s++) {
      uint32_t ah[2][4], al[2][4], bh[8][2], bl[8][2];
#pragma unroll
      for (int tm = 0; tm < 2; tm++) {
        uint32_t off = SW128((mw + tm * 16 + (lane & 15)) * 128 + s * 32 + (lane >> 4) * 16);
        ldmA(ah[tm], sAhi + off);
        ldmA(al[tm], sAlo + off);
      }
#pragma unroll
      for (int tn = 0; tn < 8; tn++) {
        int l = lane & 15;
        uint32_t off = SW128((nw + tn * 8 + (l & 7)) * 128 + s * 32 + (l >> 3) * 16);
        ldmB(bh[tn], sBhi + off);
        ldmB(bl[tn], sBlo + off);
      }
#pragma unroll
      for (int tm = 0; tm < 2; tm++)
#pragma unroll
        for (int tn = 0; tn < 8; tn++) {
          mma16816(acc[tm][tn], ah[tm], bh[tn]);
          mma16816(acc[tm][tn], al[tm], bh[tn]);
          mma16816(acc[tm][tn], ah[tm], bl[tn]);
        }
    }
    __syncthreads();
  }
#pragma unroll
  for (int tm = 0; tm < 2; tm++) {
    int r0 = m0 + mw + tm * 16 + (lane >> 2);
    float b0 = bias[r0], b1 = bias[r0 + 8];
#pragma unroll
    for (int tn = 0; tn < 8; tn++) {
      int col = n0 + nw + tn * 8 + (lane & 3) * 2;
      if (col < HW) {
        *(float2*)&Yb[(size_t)r0 * HW + col] =
            make_float2(acc[tm][tn][0] + b0, acc[tm][tn][1] + b0);
        *(float2*)&Yb[(size_t)(r0 + 8) * HW + col] =
            make_float2(acc[tm][tn][2] + b1, acc[tm][tn][3] + b1);
      }
    }
  }
}

// ---------------- depthwise 5x5 stride2 pad2 + BatchNorm ----------------
__global__ __launch_bounds__(256) void dw_s2_bn_kernel(
    const float* __restrict__ X, const float* __restrict__ Wd,
    const float* __restrict__ bias, const float* __restrict__ gam,
    const float* __restrict__ bet, const float* __restrict__ mu,
    const float* __restrict__ var, float* __restrict__ Y,
    int Hin, int Win, int Hout, int Wout) {
  int idx = blockIdx.x * 256 + threadIdx.x;
  int total = BATCH * DIM * Hout * Wout;
  if (idx >= total) return;
  int ox = idx % Wout; int t = idx / Wout;
  int oy = t % Hout; t /= Hout;
  int c = t % DIM; int b = t / DIM;
  const float* xp = X + (size_t)(b * DIM + c) * Hin * Win;
  const float* wp = Wd + c * 25;
  float s = 0.f;
#pragma unroll
  for (int ky = 0; ky < 5; ky++) {
    int iy = oy * 2 - 2 + ky;
    if (iy < 0 || iy >= Hin) continue;
#pragma unroll
    for (int kx = 0; kx < 5; kx++) {
      int ix = ox * 2 - 2 + kx;
      if (ix < 0 || ix >= Win) continue;
      s += xp[iy * Win + ix] * wp[ky * 5 + kx];
    }
  }
  s += bias[c];
  float sc = gam[c] * rsqrtf(var[c] + BN_EPS);
  Y[idx] = (s - mu[c]) * sc + bet[c];
}

// ---------------- attention v3: persistent per (b,h), flash-style HMMA ----------------
// One block per (b,h). K/V staged once (split bf16 hi/lo), then 25 tiles of 128 queries:
// S = Q^T K via 3-pass mma.sync; softmax on fragments; P split bf16 -> smem;
// GF_tile = P @ V^T via 3-pass mma.sync; output transposed through smem bounce.
// smem layout (bytes):
#define AT_AQH 0            // 128 x 40 bf16       = 10240   (Obuf f32[32][132] overlays 0..16896)
#define AT_AQL 10240        // 128 x 40 bf16
#define AT_KH  20480        // 224 x 40 bf16       = 17920
#define AT_KL  38400
#define AT_VH  56320        // 32 x 232 bf16       = 14848
#define AT_VL  71168
#define AT_PH  86016        // 128 x 232 bf16      = 59392
#define AT_PL  145408
#define AT3_BYTES 204800

__global__ __launch_bounds__(256, 1) void attn_mma_kernel(
    const float* __restrict__ Q, const float* __restrict__ KV,
    float* __restrict__ GF) {
  extern __shared__ __align__(1024) char sm[];
  uint32_t sb = smem_u32(sm);
  int tid = threadIdx.x, lane = tid & 31, warp = tid >> 5;
  int b = blockIdx.x >> 3, h = blockIdx.x & 7;
  const float* kvK = KV + ((size_t)b * 2 * DIM + h * 32) * HWP;
  const float* kvV = kvK + (size_t)DIM * HWP;
  const float* Qb = Q + ((size_t)b * DIM + h * 32) * HWX;
  float* GFb = GF + ((size_t)b * DIM + h * 32) * HWX;
  const float scal = 0.17677669529663687f;  // 32^-0.5

  // ---- stage K (as [key][d], stride 40) and V (as [d][key], stride 232), hi/lo
  for (int idx = tid; idx < 32 * 224; idx += 256) {
    int d = idx / 224, j = idx - d * 224;
    float kv = (j < HWP) ? kvK[d * HWP + j] : 0.f;
    __nv_bfloat16 kh = __float2bfloat16(kv);
    __nv_bfloat16 kl = __float2bfloat16(kv - __bfloat162float(kh));
    *(__nv_bfloat16*)(sm + AT_KH + (j * 40 + d) * 2) = kh;
    *(__nv_bfloat16*)(sm + AT_KL + (j * 40 + d) * 2) = kl;
    float vv = (j < HWP) ? kvV[d * HWP + j] : 0.f;
    __nv_bfloat16 vh = __float2bfloat16(vv);
    __nv_bfloat16 vl = __float2bfloat16(vv - __bfloat162float(vh));
    *(__nv_bfloat16*)(sm + AT_VH + (d * 232 + j) * 2) = vh;
    *(__nv_bfloat16*)(sm + AT_VL + (d * 232 + j) * 2) = vl;
  }

  int mw = warp * 16;
  for (int it = 0; it < 25; it++) {
    int q0 = it * 128;
    __syncthreads();  // Obuf of prev iter fully read; K/V staged (iter 0)
    // ---- stage Q tile: Aq[m][d] hi/lo, scale folded
    for (int idx = tid; idx < 4096; idx += 256) {
      int d = idx >> 7, m = idx & 127;
      int q = q0 + m;
      float v = (q < HWX) ? Qb[(size_t)d * HWX + q] * scal : 0.f;
      __nv_bfloat16 hi = __float2bfloat16(v);
      __nv_bfloat16 lo = __float2bfloat16(v - __bfloat162float(hi));
      *(__nv_bfloat16*)(sm + AT_AQH + (m * 40 + d) * 2) = hi;
      *(__nv_bfloat16*)(sm + AT_AQL + (m * 40 + d) * 2) = lo;
    }
    __syncthreads();

    // ---- QK: each warp 16 queries x 224 keys
    float acc[28][4];
#pragma unroll
    for (int nt = 0; nt < 28; nt++)
#pragma unroll
      for (int c = 0; c < 4; c++) acc[nt][c] = 0.f;
#pragma unroll
    for (int s = 0; s < 2; s++) {
      uint32_t ah[4], al[4];
      uint32_t aoff = ((mw + (lane & 15)) * 40 + s * 16) * 2 + (lane >> 4) * 16;
      ldmA(ah, sb + AT_AQH + aoff);
      ldmA(al, sb + AT_AQL + aoff);
      int l = lane & 15;
#pragma unroll
      for (int nt = 0; nt < 28; nt++) {
        uint32_t bh[2], bl[2];
        uint32_t boff = ((nt * 8 + (l & 7)) * 40 + s * 16) * 2 + ((l >> 3) & 1) * 16;
        ldmB(bh, sb + AT_KH + boff);
        ldmB(bl, sb + AT_KL + boff);
        mma16816(acc[nt], ah, bh);
        mma16816(acc[nt], al, bh);
        mma16816(acc[nt], ah, bl);
      }
    }

    // ---- softmax on fragments; rows r1 = mw+(lane>>2), r2 = r1+8
    float mx1 = -1e30f, mx2 = -1e30f;
#pragma unroll
    for (int nt = 0; nt < 28; nt++) {
      int jb = nt * 8 + (lane & 3) * 2;
      if (jb >= HWP)     { acc[nt][0] = -1e30f; acc[nt][2] = -1e30f; }
      if (jb + 1 >= HWP) { acc[nt][1] = -1e30f; acc[nt][3] = -1e30f; }
      mx1 = fmaxf(mx1, fmaxf(acc[nt][0], acc[nt][1]));
      mx2 = fmaxf(mx2, fmaxf(acc[nt][2], acc[nt][3]));
    }
#pragma unroll
    for (int o = 1; o <= 2; o <<= 1) {
      mx1 = fmaxf(mx1, __shfl_xor_sync(0xffffffffu, mx1, o));
      mx2 = fmaxf(mx2, __shfl_xor_sync(0xffffffffu, mx2, o));
    }
    float sum1 = 0.f, sum2 = 0.f;
#pragma unroll
    for (int nt = 0; nt < 28; nt++) {
      acc[nt][0] = __expf(acc[nt][0] - mx1);
      acc[nt][1] = __expf(acc[nt][1] - mx1);
      acc[nt][2] = __expf(acc[nt][2] - mx2);
      acc[nt][3] = __expf(acc[nt][3] - mx2);
      sum1 += acc[nt][0] + acc[nt][1];
      sum2 += acc[nt][2] + acc[nt][3];
    }
#pragma unroll
    for (int o = 1; o <= 2; o <<= 1) {
      sum1 += __shfl_xor_sync(0xffffffffu, sum1, o);
      sum2 += __shfl_xor_sync(0xffffffffu, sum2, o);
    }
    float rec1 = 1.f / sum1, rec2 = 1.f / sum2;

    // ---- write P (hi/lo bf16) to smem: rows = queries, cols = keys, stride 232
    {
      int r1 = mw + (lane >> 2), r2 = r1 + 8;
      int cb = (lane & 3) * 2;
#pragma unroll
      for (int nt = 0; nt < 28; nt++) {
        int col = nt * 8 + cb;
        float e0 = acc[nt][0], e1 = acc[nt][1], e2 = acc[nt][2], e3 = acc[nt][3];
        __nv_bfloat162 h01 = __floats2bfloat162_rn(e0, e1);
        __nv_bfloat162 h23 = __floats2bfloat162_rn(e2, e3);
        __nv_bfloat162 l01 = __floats2bfloat162_rn(e0 - __bfloat162float(h01.x),
                                                   e1 - __bfloat162float(h01.y));
        __nv_bfloat162 l23 = __floats2bfloat162_rn(e2 - __bfloat162float(h23.x),
                                                   e3 - __bfloat162float(h23.y));
        *(__nv_bfloat162*)(sm + AT_PH + (r1 * 232 + col) * 2) = h01;
        *(__nv_bfloat162*)(sm + AT_PL + (r1 * 232 + col) * 2) = l01;
        *(__nv_bfloat162*)(sm + AT_PH + (r2 * 232 + col) * 2) = h23;
        *(__nv_bfloat162*)(sm + AT_PL + (r2 * 232 + col) * 2) = l23;
      }
    }
    __syncthreads();

    // ---- PV: D[m][d] = sum_j P[m][j] V[d][j]; warp = same 16 query rows, 32 d cols
    float acc2[4][4];
#pragma unroll
    for (int nt = 0; nt < 4; nt++)
#pragma unroll
      for (int c = 0; c < 4; c++) acc2[nt][c] = 0.f;
#pragma unroll
    for (int k = 0; k < 14; k++) {
      uint32_t ph[4], pl[4];
      uint32_t aoff = ((mw + (lane & 15)) * 232 + k * 16) * 2 + (lane >> 4) * 16;
      ldmA(ph, sb + AT_PH + aoff);
      ldmA(pl, sb + AT_PL + aoff);
      int l = lane & 15;
#pragma unroll
      for (int nt = 0; nt < 4; nt++) {
        uint32_t vh[2], vl[2];
        uint32_t boff = ((nt * 8 + (l & 7)) * 232 + k * 16) * 2 + ((l >> 3) & 1) * 16;
        ldmB(vh, sb + AT_VH + boff);
        ldmB(vl, sb + AT_VL + boff);
        mma16816(acc2[nt], ph, vh);
        mma16816(acc2[nt], pl, vh);
        mma16816(acc2[nt], ph, vl);
      }
    }

    // ---- normalize + transpose via Obuf (f32 [32 d][132]) overlaying AQ region
    float* Ob = (float*)sm;
    {
      int m1 = mw + (lane >> 2), m2 = m1 + 8;
      int cb = (lane & 3) * 2;
#pragma unroll
      for (int nt = 0; nt < 4; nt++) {
        int dcol = nt * 8 + cb;
        Ob[dcol * 132 + m1]       = acc2[nt][0] * rec1;
        Ob[(dcol + 1) * 132 + m1] = acc2[nt][1] * rec1;
        Ob[dcol * 132 + m2]       = acc2[nt][2] * rec2;
        Ob[(dcol + 1) * 132 + m2] = acc2[nt][3] * rec2;
      }
    }
    __syncthreads();
    // coalesced copy out: 32 d rows x 128 m
    {
      int nvq = HWX - q0; if (nvq > 128) nvq = 128;
      int row = tid >> 3, i0 = (tid & 7) * 16;
#pragma unroll
      for (int c = 0; c < 4; c++) {
        int i = i0 + c * 4;
        if (i < nvq) {
          float4 v = *(float4*)&Ob[row * 132 + i];
          *(float4*)&GFb[(size_t)row * HWX + q0 + i] = v;
        }
      }
    }
  }
}

// ---------------- local mixer: dw5x5 s1 pad2, SiLU, gate by sigmoid(gf), * gf ----------------
__global__ __launch_bounds__(256) void local_gate_kernel(
    const float* __restrict__ Q, const float* __restrict__ Wd,
    const float* __restrict__ bias, const float* __restrict__ G,
    float* __restrict__ Out) {
  int idx = blockIdx.x * 256 + threadIdx.x;
  int total = BATCH * DIM * HWX;
  if (idx >= total) return;
  int ox = idx % WW; int t = idx / WW;
  int oy = t % HH; t /= HH;
  int c = t % DIM; int b = t / DIM;
  const float* xp = Q + (size_t)(b * DIM + c) * HWX;
  const float* wp = Wd + c * 25;
  float s = 0.f;
#pragma unroll
  for (int ky = 0; ky < 5; ky++) {
    int iy = oy + ky - 2;
    if (iy < 0 || iy >= HH) continue;
#pragma unroll
    for (int kx = 0; kx < 5; kx++) {
      int ix = ox + kx - 2;
      if (ix < 0 || ix >= WW) continue;
      s += xp[iy * WW + ix] * wp[ky * 5 + kx];
    }
  }
  s += bias[c];
  float lf = s / (1.f + __expf(-s));
  float gv = G[idx];
  float sg = 1.f / (1.f + __expf(-gv));
  Out[idx] = lf * sg * gv;
}

extern "C" void kernel_launch(void* const* d_in, const int* in_sizes, int n_in,
                              void* d_out, int out_size) {
  const float* x     = (const float*)d_in[0];
  const float* q_w   = (const float*)d_in[1];
  const float* q_b   = (const float*)d_in[2];
  const float* kv_w  = (const float*)d_in[3];
  const float* kv_b  = (const float*)d_in[4];
  const float* p0_w  = (const float*)d_in[5];
  const float* p0_b  = (const float*)d_in[6];
  const float* bn0_g = (const float*)d_in[7];
  const float* bn0_b = (const float*)d_in[8];
  const float* bn0_m = (const float*)d_in[9];
  const float* bn0_v = (const float*)d_in[10];
  const float* pl0_w = (const float*)d_in[11];
  const float* pl0_b = (const float*)d_in[12];
  const float* p1_w  = (const float*)d_in[13];
  const float* p1_b  = (const float*)d_in[14];
  const float* bn1_g = (const float*)d_in[15];
  const float* bn1_b = (const float*)d_in[16];
  const float* bn1_m = (const float*)d_in[17];
  const float* bn1_v = (const float*)d_in[18];
  const float* loc_w = (const float*)d_in[19];
  const float* loc_b = (const float*)d_in[20];
  const float* mix_w = (const float*)d_in[21];
  const float* mix_b = (const float*)d_in[22];
  float* out = (float*)d_out;

  float *qlocal, *p0buf, *pmid, *pfin, *kvbuf, *gf, *mixbuf;
  cudaGetSymbolAddress((void**)&qlocal, g_qlocal);
  cudaGetSymbolAddress((void**)&p0buf,  g_p0);
  cudaGetSymbolAddress((void**)&pmid,   g_pmid);
  cudaGetSymbolAddress((void**)&pfin,   g_pfin);
  cudaGetSymbolAddress((void**)&kvbuf,  g_kv);
  cudaGetSymbolAddress((void**)&gf,     g_gf);
  cudaGetSymbolAddress((void**)&mixbuf, g_mix);

  cudaFuncSetAttribute(attn_mma_kernel, cudaFuncAttributeMaxDynamicSharedMemorySize, AT3_BYTES);
  cudaFuncSetAttribute(conv1x1_mma_kernel, cudaFuncAttributeMaxDynamicSharedMemorySize, CV_SMEM);

  // 1. q_local = conv1x1(x, q_w) + q_b
  conv1x1_mma_kernel<<<dim3((HWX + 127) / 128, DIM / 128, BATCH), 256, CV_SMEM>>>(q_w, x, q_b, qlocal, DIM, DIM, HWX);
  // 2. p0 = BN0(dw5x5_s2(x))
  dw_s2_bn_kernel<<<(BATCH * DIM * HW1 + 255) / 256, 256>>>(x, p0_w, p0_b, bn0_g, bn0_b, bn0_m, bn0_v,
                                                            p0buf, HH, WW, HP1, HP1);
  // 3. pmid = conv1x1(p0, pl0_w)
  conv1x1_mma_kernel<<<dim3((HW1 + 127) / 128, DIM / 128, BATCH), 256, CV_SMEM>>>(pl0_w, p0buf, pl0_b, pmid, DIM, DIM, HW1);
  // 4. pfin = BN1(dw5x5_s2(pmid))
  dw_s2_bn_kernel<<<(BATCH * DIM * HWP + 255) / 256, 256>>>(pmid, p1_w, p1_b, bn1_g, bn1_b, bn1_m, bn1_v,
                                                            pfin, HP1, HP1, HP2, HP2);
  // 5. kv = conv1x1(pfin, kv_w)
  conv1x1_mma_kernel<<<dim3((HWP + 127) / 128, (2 * DIM) / 128, BATCH), 256, CV_SMEM>>>(kv_w, pfin, kv_b, kvbuf, 2 * DIM, DIM, HWP);
  // 6. attention -> gf  (one block per (b,h), persistent over query tiles)
  attn_mma_kernel<<<BATCH * HEADS, 256, AT3_BYTES>>>(qlocal, kvbuf, gf);
  // 7. local mixer + gating -> mixbuf
  local_gate_kernel<<<(BATCH * DIM * HWX + 255) / 256, 256>>>(qlocal, loc_w, loc_b, gf, mixbuf);
  // 8. out = conv1x1(mixbuf, mix_w)
  conv1x1_mma_kernel<<<dim3((HWX + 127) / 128, DIM / 128, BATCH), 256, CV_SMEM>>>(mix_w, mixbuf, mix_b, out, DIM, DIM, HWX);
}

// round 6
// speedup vs baseline: 2.1474x; 1.0087x over previous
#include <cuda_runtime.h>
#include <cuda_bf16.h>
#include <cstdint>

#define BATCH 16
#define DIM 256
#define HH 56
#define WW 56
#define HWX (HH*WW)          // 3136
#define HEADS 8
#define DH 32
#define HP1 28
#define HW1 (HP1*HP1)        // 784
#define HP2 14
#define HWP (HP2*HP2)        // 196
#define BN_EPS 1e-5f

#define SW128(x) ((x) ^ (((x) >> 3) & 0x70))

typedef __nv_bfloat16 bf16;
typedef __nv_bfloat162 bf162;

__device__ __forceinline__ uint32_t smem_u32(const void* p) {
  uint32_t a;
  asm("{ .reg .u64 t; cvta.to.shared.u64 t, %1; cvt.u32.u64 %0, t; }" : "=r"(a) : "l"(p));
  return a;
}
__device__ __forceinline__ void ldmA(uint32_t a[4], uint32_t addr) {
  asm volatile("ldmatrix.sync.aligned.m8n8.x4.shared.b16 {%0,%1,%2,%3}, [%4];"
               : "=r"(a[0]), "=r"(a[1]), "=r"(a[2]), "=r"(a[3]) : "r"(addr));
}
__device__ __forceinline__ void ldmB(uint32_t b[2], uint32_t addr) {
  asm volatile("ldmatrix.sync.aligned.m8n8.x2.shared.b16 {%0,%1}, [%2];"
               : "=r"(b[0]), "=r"(b[1]) : "r"(addr));
}
__device__ __forceinline__ void ldmBT(uint32_t b[2], uint32_t addr) {
  asm volatile("ldmatrix.sync.aligned.m8n8.x2.trans.shared.b16 {%0,%1}, [%2];"
               : "=r"(b[0]), "=r"(b[1]) : "r"(addr));
}
__device__ __forceinline__ void mma16816(float d[4], const uint32_t a[4], const uint32_t b[2]) {
  asm volatile("mma.sync.aligned.m16n8k16.row.col.f32.bf16.bf16.f32 "
               "{%0,%1,%2,%3}, {%4,%5,%6,%7}, {%8,%9}, {%0,%1,%2,%3};"
               : "+f"(d[0]), "+f"(d[1]), "+f"(d[2]), "+f"(d[3])
               : "r"(a[0]), "r"(a[1]), "r"(a[2]), "r"(a[3]), "r"(b[0]), "r"(b[1]));
}
__device__ __forceinline__ uint32_t bfpack(float a, float b) {
  bf162 t = __floats2bfloat162_rn(a, b);
  return *(uint32_t*)&t;
}
__device__ __forceinline__ uint32_t bfpack_res(float a, float b, uint32_t hp) {
  bf162 h = *(bf162*)&hp;
  return bfpack(a - __bfloat162float(h.x), b - __bfloat162float(h.y));
}

// ---------------- scratch (device globals; no allocations allowed) ----------------
__device__ float g_qlocal[BATCH*DIM*HWX];
__device__ float g_pmid[BATCH*DIM*HW1];
__device__ float g_gf[BATCH*DIM*HWX];
// bf16 hi/lo split buffers
#define NX (BATCH*DIM*HWX)
#define NP0 (BATCH*DIM*HW1)
#define NPF (BATCH*DIM*HWP)
#define NKV (BATCH*2*DIM*HWP)
#define WOFF_Q 0
#define WOFF_PL 65536
#define WOFF_KV 131072
#define WOFF_MIX 262144
#define NW 327680
__device__ bf16 g_xh[NX],  g_xl[NX];
__device__ bf16 g_qh[NX],  g_ql[NX];
__device__ bf16 g_mh[NX],  g_ml[NX];
__device__ bf16 g_p0h[NP0], g_p0l[NP0];
__device__ bf16 g_pfh[NPF], g_pfl[NPF];
__device__ bf16 g_kvh[NKV], g_kvl[NKV];
__device__ bf16 g_wh[NW],  g_wl[NW];

// ---------------- f32 -> bf16 hi/lo split (vectorized) ----------------
__global__ __launch_bounds__(256) void cvt_hl_kernel(
    const float* __restrict__ s, bf16* __restrict__ h, bf16* __restrict__ l, int n4) {
  int i = blockIdx.x * 256 + threadIdx.x;
  if (i >= n4) return;
  float4 v = ((const float4*)s)[i];
  bf162 h0 = __floats2bfloat162_rn(v.x, v.y);
  bf162 h1 = __floats2bfloat162_rn(v.z, v.w);
  bf162 l0 = __floats2bfloat162_rn(v.x - __bfloat162float(h0.x), v.y - __bfloat162float(h0.y));
  bf162 l1 = __floats2bfloat162_rn(v.z - __bfloat162float(h1.x), v.w - __bfloat162float(h1.y));
  ((bf162*)h)[2*i] = h0; ((bf162*)h)[2*i+1] = h1;
  ((bf162*)l)[2*i] = l0; ((bf162*)l)[2*i+1] = l1;
}

// ---------------- 1x1 conv: split-bf16 HMMA, pre-converted inputs ----------------
// A (weights) [CO][CI] bf16 hi/lo; B (acts) [CI][HW] bf16 hi/lo.
// smem A [m][64k] 128B rows SW128; B [k][128n] 256B rows, XOR-chunk swizzle, ldmatrix.trans.
#define CV_SMEM 65536

__global__ __launch_bounds__(256) void conv1x1_bf_kernel(
    const bf16* __restrict__ Ah, const bf16* __restrict__ Al,
    const bf16* __restrict__ Bh, const bf16* __restrict__ Bl,
    const float* __restrict__ bias, float* __restrict__ Yf,
    bf16* __restrict__ Yh, bf16* __restrict__ Yl,
    int CO, int CI, int HW) {
  extern __shared__ __align__(1024) char smem[];
  char* sAh = smem;         char* sAl = smem + 16384;
  char* sBh = smem + 32768; char* sBl = smem + 49152;
  uint32_t aAh = smem_u32(sAh), aAl = smem_u32(sAl);
  uint32_t aBh = smem_u32(sBh), aBl = smem_u32(sBl);
  int tid = threadIdx.x, lane = tid & 31, wid = tid >> 5;
  int m0 = blockIdx.y * 128, n0 = blockIdx.x * 128;
  const bf16* Bhb = Bh + (size_t)blockIdx.z * CI * HW;
  const bf16* Blb = Bl + (size_t)blockIdx.z * CI * HW;
  int mw = (wid & 3) * 32, nw = (wid >> 2) * 64;

  float acc[2][8][4];
#pragma unroll
  for (int i = 0; i < 2; i++)
#pragma unroll
    for (int j = 0; j < 8; j++)
#pragma unroll
      for (int c = 0; c < 4; c++) acc[i][j][c] = 0.f;

  for (int k0 = 0; k0 < CI; k0 += 64) {
    // A stage: 1024 tasks (128 m x 8 kg), 16B copies
#pragma unroll
    for (int i = 0; i < 4; i++) {
      int t = tid + i * 256;
      int m = t >> 3, kg = t & 7;
      size_t src = (size_t)(m0 + m) * CI + k0 + kg * 8;
      uint32_t dst = SW128(m * 128 + kg * 16);
      *(uint4*)(sAh + dst) = *(const uint4*)(Ah + src);
      *(uint4*)(sAl + dst) = *(const uint4*)(Al + src);
    }
    // B stage: 1024 tasks (64 k x 16 chunks of 8 n), [k][n] rows + XOR swizzle
#pragma unroll
    for (int i = 0; i < 4; i++) {
      int t = tid + i * 256;
      int k = t & 63, c = t >> 6;
      int gn = n0 + c * 8;
      uint4 vh, vl;
      if (gn + 8 <= HW) {
        const char* ph = (const char*)(Bhb + (size_t)(k0 + k) * HW + gn);
        const char* pl = (const char*)(Blb + (size_t)(k0 + k) * HW + gn);
        uint2 h0 = *(const uint2*)ph, h1 = *(const uint2*)(ph + 8);
        uint2 l0 = *(const uint2*)pl, l1 = *(const uint2*)(pl + 8);
        vh = make_uint4(h0.x, h0.y, h1.x, h1.y);
        vl = make_uint4(l0.x, l0.y, l1.x, l1.y);
      } else {
        bf16 th[8], tl[8];
#pragma unroll
        for (int j = 0; j < 8; j++) {
          int g = gn + j;
          th[j] = (g < HW) ? Bhb[(size_t)(k0 + k) * HW + g] : __float2bfloat16(0.f);
          tl[j] = (g < HW) ? Blb[(size_t)(k0 + k) * HW + g] : __float2bfloat16(0.f);
        }
        vh = *(uint4*)th; vl = *(uint4*)tl;
      }
      uint32_t dst = k * 256 + ((c ^ (k & 15)) << 4);
      *(uint4*)(sBh + dst) = vh;
      *(uint4*)(sBl + dst) = vl;
    }
    __syncthreads();
#pragma unroll
    for (int s = 0; s < 4; s++) {
      uint32_t ah[2][4], al[2][4];
#pragma unroll
      for (int tm = 0; tm < 2; tm++) {
        uint32_t off = SW128((mw + tm * 16 + (lane & 15)) * 128 + s * 32 + (lane >> 4) * 16);
        ldmA(ah[tm], aAh + off);
        ldmA(al[tm], aAl + off);
      }
      int l = lane & 15;
      int kk = s * 16 + l;
#pragma unroll
      for (int nt = 0; nt < 8; nt++) {
        uint32_t boff = kk * 256 + ((((nw >> 3) + nt) ^ (kk & 15)) << 4);
        uint32_t bh[2], bl[2];
        ldmBT(bh, aBh + boff);
        ldmBT(bl, aBl + boff);
#pragma unroll
        for (int tm = 0; tm < 2; tm++) {
          mma16816(acc[tm][nt], ah[tm], bh);
          mma16816(acc[tm][nt], al[tm], bh);
          mma16816(acc[tm][nt], ah[tm], bl);
        }
      }
    }
    __syncthreads();
  }
  // epilogue
#pragma unroll
  for (int tm = 0; tm < 2; tm++) {
    int r0 = m0 + mw + tm * 16 + (lane >> 2);
    float b0 = bias[r0], b1 = bias[r0 + 8];
#pragma unroll
    for (int tn = 0; tn < 8; tn++) {
      int col = n0 + nw + tn * 8 + (lane & 3) * 2;
      if (col < HW) {
        float o0 = acc[tm][tn][0] + b0, o1 = acc[tm][tn][1] + b0;
        float o2 = acc[tm][tn][2] + b1, o3 = acc[tm][tn][3] + b1;
        size_t i0 = (size_t)blockIdx.z * CO * HW + (size_t)r0 * HW + col;
        size_t i1 = i0 + (size_t)8 * HW;
        if (Yf) {
          *(float2*)&Yf[i0] = make_float2(o0, o1);
          *(float2*)&Yf[i1] = make_float2(o2, o3);
        }
        if (Yh) {
          bf162 h0 = __floats2bfloat162_rn(o0, o1);
          bf162 h1 = __floats2bfloat162_rn(o2, o3);
          bf162 l0 = __floats2bfloat162_rn(o0 - __bfloat162float(h0.x), o1 - __bfloat162float(h0.y));
          bf162 l1 = __floats2bfloat162_rn(o2 - __bfloat162float(h1.x), o3 - __bfloat162float(h1.y));
          *(bf162*)&Yh[i0] = h0; *(bf162*)&Yh[i1] = h1;
          *(bf162*)&Yl[i0] = l0; *(bf162*)&Yl[i1] = l1;
        }
      }
    }
  }
}

// ---------------- depthwise 5x5 stride2 pad2 + BatchNorm -> bf16 hi/lo ----------------
__global__ __launch_bounds__(256) void dw_s2_bn_bf_kernel(
    const float* __restrict__ X, const float* __restrict__ Wd,
    const float* __restrict__ bias, const float* __restrict__ gam,
    const float* __restrict__ bet, const float* __restrict__ mu,
    const float* __restrict__ var, bf16* __restrict__ Yh, bf16* __restrict__ Yl,
    int Hin, int Win, int Hout, int Wout) {
  int idx = blockIdx.x * 256 + threadIdx.x;
  int total = BATCH * DIM * Hout * Wout;
  if (idx >= total) return;
  int ox = idx % Wout; int t = idx / Wout;
  int oy = t % Hout; t /= Hout;
  int c = t % DIM; int b = t / DIM;
  const float* xp = X + (size_t)(b * DIM + c) * Hin * Win;
  const float* wp = Wd + c * 25;
  float s = 0.f;
#pragma unroll
  for (int ky = 0; ky < 5; ky++) {
    int iy = oy * 2 - 2 + ky;
    if (iy < 0 || iy >= Hin) continue;
#pragma unroll
    for (int kx = 0; kx < 5; kx++) {
      int ix = ox * 2 - 2 + kx;
      if (ix < 0 || ix >= Win) continue;
      s += xp[iy * Win + ix] * wp[ky * 5 + kx];
    }
  }
  s += bias[c];
  float sc = gam[c] * rsqrtf(var[c] + BN_EPS);
  float r = (s - mu[c]) * sc + bet[c];
  bf16 hb = __float2bfloat16(r);
  Yh[idx] = hb;
  Yl[idx] = __float2bfloat16(r - __bfloat162float(hb));
}

// ---------------- attention v4: 128-thr CTA, 64 queries, register-resident P ----------------
#define A4_AQH 0
#define A4_AQL 5120
#define A4_KH  10240
#define A4_KL  28160
#define A4_VH  46080
#define A4_VL  60928
#define A4_BYTES 75776

__global__ __launch_bounds__(128, 2) void attn4_kernel(
    const bf16* __restrict__ Qh, const bf16* __restrict__ Ql,
    const bf16* __restrict__ KVh, const bf16* __restrict__ KVl,
    float* __restrict__ GF) {
  extern __shared__ __align__(1024) char sm[];
  uint32_t sb = smem_u32(sm);
  int tid = threadIdx.x, lane = tid & 31, warp = tid >> 5;
  int part = blockIdx.x % 7;
  int bh = blockIdx.x / 7;
  int b = bh >> 3, h = bh & 7;
  const bf16* kHh = KVh + ((size_t)b * 2 * DIM + h * 32) * HWP;
  const bf16* kHl = KVl + ((size_t)b * 2 * DIM + h * 32) * HWP;
  const bf16* vHh = kHh + (size_t)DIM * HWP;
  const bf16* vHl = kHl + (size_t)DIM * HWP;
  const float scal = 0.17677669529663687f;  // 32^-0.5

  // ---- stage K [j][40+d] (scatter) and V [d][232+j] (vector), hi/lo
  for (int t = tid; t < 896; t += 128) {
    int d = t & 31, jg = t >> 5;  // jg 0..27
    int j0 = jg * 8;
    bf16 th[8], tl[8], uh[8], ul[8];
    if (j0 + 8 <= HWP) {
      const char* pkh = (const char*)(kHh + (size_t)d * HWP + j0);
      const char* pkl = (const char*)(kHl + (size_t)d * HWP + j0);
      const char* pvh = (const char*)(vHh + (size_t)d * HWP + j0);
      const char* pvl = (const char*)(vHl + (size_t)d * HWP + j0);
      *(uint2*)th = *(const uint2*)pkh; *(uint2*)(th + 4) = *(const uint2*)(pkh + 8);
      *(uint2*)tl = *(const uint2*)pkl; *(uint2*)(tl + 4) = *(const uint2*)(pkl + 8);
      *(uint2*)uh = *(const uint2*)pvh; *(uint2*)(uh + 4) = *(const uint2*)(pvh + 8);
      *(uint2*)ul = *(const uint2*)pvl; *(uint2*)(ul + 4) = *(const uint2*)(pvl + 8);
    } else {
      bf16 z = __float2bfloat16(0.f);
#pragma unroll
      for (int j = 0; j < 8; j++) {
        int g = j0 + j;
        bool v = g < HWP;
        th[j] = v ? kHh[(size_t)d * HWP + g] : z;
        tl[j] = v ? kHl[(size_t)d * HWP + g] : z;
        uh[j] = v ? vHh[(size_t)d * HWP + g] : z;
        ul[j] = v ? vHl[(size_t)d * HWP + g] : z;
      }
    }
#pragma unroll
    for (int j = 0; j < 8; j++) {
      *(bf16*)(sm + A4_KH + ((j0 + j) * 40 + d) * 2) = th[j];
      *(bf16*)(sm + A4_KL + ((j0 + j) * 40 + d) * 2) = tl[j];
    }
    *(uint4*)(sm + A4_VH + (d * 232 + j0) * 2) = *(uint4*)uh;
    *(uint4*)(sm + A4_VL + (d * 232 + j0) * 2) = *(uint4*)ul;
  }

  const bf16* qbh = Qh + ((size_t)b * DIM + h * 32) * HWX;
  const bf16* qbl = Ql + ((size_t)b * DIM + h * 32) * HWX;
  float* GFb = GF + ((size_t)b * DIM + h * 32) * HWX;
  int mw = warp * 16;

  for (int it = 0; it < 7; it++) {
    int q0 = (part * 7 + it) * 64;
    __syncthreads();  // prev Obuf consumed (and K/V staged, iter 0)
    // ---- stage Q tile [m][40+d] from [d][q] (scatter)
    for (int t = tid; t < 256; t += 128) {
      int d = t & 31, mg = t >> 5;  // mg 0..7
      uint4 vh = *(const uint4*)(qbh + (size_t)d * HWX + q0 + mg * 8);
      uint4 vl = *(const uint4*)(qbl + (size_t)d * HWX + q0 + mg * 8);
      bf16* eh = (bf16*)&vh; bf16* el = (bf16*)&vl;
#pragma unroll
      for (int j = 0; j < 8; j++) {
        *(bf16*)(sm + A4_AQH + ((mg * 8 + j) * 40 + d) * 2) = eh[j];
        *(bf16*)(sm + A4_AQL + ((mg * 8 + j) * 40 + d) * 2) = el[j];
      }
    }
    __syncthreads();

    // ---- QK: 16 queries x 224 keys per warp
    float acc[28][4];
#pragma unroll
    for (int nt = 0; nt < 28; nt++)
#pragma unroll
      for (int c = 0; c < 4; c++) acc[nt][c] = 0.f;
#pragma unroll
    for (int s = 0; s < 2; s++) {
      uint32_t ah[4], al[4];
      uint32_t aoff = ((mw + (lane & 15)) * 40 + s * 16) * 2 + (lane >> 4) * 16;
      ldmA(ah, sb + A4_AQH + aoff);
      ldmA(al, sb + A4_AQL + aoff);
      int l = lane & 15;
#pragma unroll
      for (int nt = 0; nt < 28; nt++) {
        uint32_t bh[2], bl[2];
        uint32_t boff = ((nt * 8 + (l & 7)) * 40 + s * 16) * 2 + ((l >> 3) & 1) * 16;
        ldmB(bh, sb + A4_KH + boff);
        ldmB(bl, sb + A4_KL + boff);
        mma16816(acc[nt], ah, bh);
        mma16816(acc[nt], al, bh);
        mma16816(acc[nt], ah, bl);
      }
    }

    // ---- scale + mask + softmax (rows r1 = mw+(lane>>2), r2 = r1+8)
    float mx1 = -1e30f, mx2 = -1e30f;
#pragma unroll
    for (int nt = 0; nt < 28; nt++) {
      int jb = nt * 8 + (lane & 3) * 2;
      acc[nt][0] *= scal; acc[nt][1] *= scal; acc[nt][2] *= scal; acc[nt][3] *= scal;
      if (jb >= HWP)     { acc[nt][0] = -1e30f; acc[nt][2] = -1e30f; }
      if (jb + 1 >= HWP) { acc[nt][1] = -1e30f; acc[nt][3] = -1e30f; }
      mx1 = fmaxf(mx1, fmaxf(acc[nt][0], acc[nt][1]));
      mx2 = fmaxf(mx2, fmaxf(acc[nt][2], acc[nt][3]));
    }
#pragma unroll
    for (int o = 1; o <= 2; o <<= 1) {
      mx1 = fmaxf(mx1, __shfl_xor_sync(0xffffffffu, mx1, o));
      mx2 = fmaxf(mx2, __shfl_xor_sync(0xffffffffu, mx2, o));
    }
    float sum1 = 0.f, sum2 = 0.f;
#pragma unroll
    for (int nt = 0; nt < 28; nt++) {
      acc[nt][0] = __expf(acc[nt][0] - mx1);
      acc[nt][1] = __expf(acc[nt][1] - mx1);
      acc[nt][2] = __expf(acc[nt][2] - mx2);
      acc[nt][3] = __expf(acc[nt][3] - mx2);
      sum1 += acc[nt][0] + acc[nt][1];
      sum2 += acc[nt][2] + acc[nt][3];
    }
#pragma unroll
    for (int o = 1; o <= 2; o <<= 1) {
      sum1 += __shfl_xor_sync(0xffffffffu, sum1, o);
      sum2 += __shfl_xor_sync(0xffffffffu, sum2, o);
    }
    float rec1 = 1.f / sum1, rec2 = 1.f / sum2;

    // ---- PV with register-resident P (QK acc fragments ARE the A fragments)
    float acc2[4][4];
#pragma unroll
    for (int nt = 0; nt < 4; nt++)
#pragma unroll
      for (int c = 0; c < 4; c++) acc2[nt][c] = 0.f;
#pragma unroll 2
    for (int k = 0; k < 14; k++) {
      float p00 = acc[2*k][0] * rec1,   p01 = acc[2*k][1] * rec1;
      float p02 = acc[2*k][2] * rec2,   p03 = acc[2*k][3] * rec2;
      float p10 = acc[2*k+1][0] * rec1, p11 = acc[2*k+1][1] * rec1;
      float p12 = acc[2*k+1][2] * rec2, p13 = acc[2*k+1][3] * rec2;
      uint32_t ph[4], pl[4];
      ph[0] = bfpack(p00, p01); ph[1] = bfpack(p02, p03);
      ph[2] = bfpack(p10, p11); ph[3] = bfpack(p12, p13);
      pl[0] = bfpack_res(p00, p01, ph[0]); pl[1] = bfpack_res(p02, p03, ph[1]);
      pl[2] = bfpack_res(p10, p11, ph[2]); pl[3] = bfpack_res(p12, p13, ph[3]);
      int l = lane & 15;
#pragma unroll
      for (int nt = 0; nt < 4; nt++) {
        uint32_t vh[2], vl[2];
        uint32_t boff = ((nt * 8 + (l & 7)) * 232 + k * 16) * 2 + ((l >> 3) & 1) * 16;
        ldmB(vh, sb + A4_VH + boff);
        ldmB(vl, sb + A4_VL + boff);
        mma16816(acc2[nt], ph, vh);
        mma16816(acc2[nt], pl, vh);
        mma16816(acc2[nt], ph, vl);
      }
    }
    __syncthreads();  // all warps done reading AQ before Obuf overlay write

    // ---- transpose via Obuf f32 [32 d][68] (overlays AQ region)
    float* Ob = (float*)sm;
    {
      int m1 = mw + (lane >> 2), m2 = m1 + 8;
      int cb = (lane & 3) * 2;
#pragma unroll
      for (int nt = 0; nt < 4; nt++) {
        int dcol = nt * 8 + cb;
        Ob[dcol * 68 + m1]       = acc2[nt][0];
        Ob[(dcol + 1) * 68 + m1] = acc2[nt][1];
        Ob[dcol * 68 + m2]       = acc2[nt][2];
        Ob[(dcol + 1) * 68 + m2] = acc2[nt][3];
      }
    }
    __syncthreads();
    // ---- coalesced copy out: 32 d rows x 64 m (all tiles full: 3136 = 49*64)
    {
      int row = tid >> 2, i0 = (tid & 3) * 16;
#pragma unroll
      for (int c = 0; c < 4; c++) {
        int i = i0 + c * 4;
        *(float4*)&GFb[(size_t)row * HWX + q0 + i] = *(float4*)&Ob[row * 68 + i];
      }
    }
  }
}

// ---------------- local mixer -> bf16 hi/lo mixbuf ----------------
__global__ __launch_bounds__(256) void local_gate_bf_kernel(
    const float* __restrict__ Q, const float* __restrict__ Wd,
    const float* __restrict__ bias, const float* __restrict__ G,
    bf16* __restrict__ Oh, bf16* __restrict__ Ol) {
  int idx = blockIdx.x * 256 + threadIdx.x;
  int total = BATCH * DIM * HWX;
  if (idx >= total) return;
  int ox = idx % WW; int t = idx / WW;
  int oy = t % HH; t /= HH;
  int c = t % DIM; int b = t / DIM;
  const float* xp = Q + (size_t)(b * DIM + c) * HWX;
  const float* wp = Wd + c * 25;
  float s = 0.f;
#pragma unroll
  for (int ky = 0; ky < 5; ky++) {
    int iy = oy + ky - 2;
    if (iy < 0 || iy >= HH) continue;
#pragma unroll
    for (int kx = 0; kx < 5; kx++) {
      int ix = ox + kx - 2;
      if (ix < 0 || ix >= WW) continue;
      s += xp[iy * WW + ix] * wp[ky * 5 + kx];
    }
  }
  s += bias[c];
  float lf = s / (1.f + __expf(-s));
  float gv = G[idx];
  float sg = 1.f / (1.f + __expf(-gv));
  float r = lf * sg * gv;
  bf16 hb = __float2bfloat16(r);
  Oh[idx] = hb;
  Ol[idx] = __float2bfloat16(r - __bfloat162float(hb));
}

extern "C" void kernel_launch(void* const* d_in, const int* in_sizes, int n_in,
                              void* d_out, int out_size) {
  const float* x     = (const float*)d_in[0];
  const float* q_w   = (const float*)d_in[1];
  const float* q_b   = (const float*)d_in[2];
  const float* kv_w  = (const float*)d_in[3];
  const float* kv_b  = (const float*)d_in[4];
  const float* p0_w  = (const float*)d_in[5];
  const float* p0_b  = (const float*)d_in[6];
  const float* bn0_g = (const float*)d_in[7];
  const float* bn0_b = (const float*)d_in[8];
  const float* bn0_m = (const float*)d_in[9];
  const float* bn0_v = (const float*)d_in[10];
  const float* pl0_w = (const float*)d_in[11];
  const float* pl0_b = (const float*)d_in[12];
  const float* p1_w  = (const float*)d_in[13];
  const float* p1_b  = (const float*)d_in[14];
  const float* bn1_g = (const float*)d_in[15];
  const float* bn1_b = (const float*)d_in[16];
  const float* bn1_m = (const float*)d_in[17];
  const float* bn1_v = (const float*)d_in[18];
  const float* loc_w = (const float*)d_in[19];
  const float* loc_b = (const float*)d_in[20];
  const float* mix_w = (const float*)d_in[21];
  const float* mix_b = (const float*)d_in[22];
  float* out = (float*)d_out;

  float *qlocal, *pmid, *gf;
  cudaGetSymbolAddress((void**)&qlocal, g_qlocal);
  cudaGetSymbolAddress((void**)&pmid,   g_pmid);
  cudaGetSymbolAddress((void**)&gf,     g_gf);
  bf16 *xh, *xl, *qh, *ql, *mh, *ml, *p0h, *p0l, *pfh, *pfl, *kvh, *kvl, *wh, *wl;
  cudaGetSymbolAddress((void**)&xh, g_xh);   cudaGetSymbolAddress((void**)&xl, g_xl);
  cudaGetSymbolAddress((void**)&qh, g_qh);   cudaGetSymbolAddress((void**)&ql, g_ql);
  cudaGetSymbolAddress((void**)&mh, g_mh);   cudaGetSymbolAddress((void**)&ml, g_ml);
  cudaGetSymbolAddress((void**)&p0h, g_p0h); cudaGetSymbolAddress((void**)&p0l, g_p0l);
  cudaGetSymbolAddress((void**)&pfh, g_pfh); cudaGetSymbolAddress((void**)&pfl, g_pfl);
  cudaGetSymbolAddress((void**)&kvh, g_kvh); cudaGetSymbolAddress((void**)&kvl, g_kvl);
  cudaGetSymbolAddress((void**)&wh, g_wh);   cudaGetSymbolAddress((void**)&wl, g_wl);

  cudaFuncSetAttribute(conv1x1_bf_kernel, cudaFuncAttributeMaxDynamicSharedMemorySize, CV_SMEM);
  cudaFuncSetAttribute(attn4_kernel, cudaFuncAttributeMaxDynamicSharedMemorySize, A4_BYTES);

  // 0. pre-split weights + x to bf16 hi/lo
  cvt_hl_kernel<<<(NX/4 + 255)/256, 256>>>(x, xh, xl, NX/4);
  cvt_hl_kernel<<<(65536/4 + 255)/256, 256>>>(q_w,   wh + WOFF_Q,   wl + WOFF_Q,   65536/4);
  cvt_hl_kernel<<<(65536/4 + 255)/256, 256>>>(pl0_w, wh + WOFF_PL,  wl + WOFF_PL,  65536/4);
  cvt_hl_kernel<<<(131072/4 + 255)/256, 256>>>(kv_w, wh + WOFF_KV,  wl + WOFF_KV,  131072/4);
  cvt_hl_kernel<<<(65536/4 + 255)/256, 256>>>(mix_w, wh + WOFF_MIX, wl + WOFF_MIX, 65536/4);

  // 1. q_local (f32 + bf16 hi/lo)
  conv1x1_bf_kernel<<<dim3((HWX + 127)/128, DIM/128, BATCH), 256, CV_SMEM>>>(
      wh + WOFF_Q, wl + WOFF_Q, xh, xl, q_b, qlocal, qh, ql, DIM, DIM, HWX);
  // 2. p0 = BN0(dw5x5_s2(x)) -> bf16
  dw_s2_bn_bf_kernel<<<(BATCH*DIM*HW1 + 255)/256, 256>>>(
      x, p0_w, p0_b, bn0_g, bn0_b, bn0_m, bn0_v, p0h, p0l, HH, WW, HP1, HP1);
  // 3. pmid = conv1x1(p0) -> f32
  conv1x1_bf_kernel<<<dim3((HW1 + 127)/128, DIM/128, BATCH), 256, CV_SMEM>>>(
      wh + WOFF_PL, wl + WOFF_PL, p0h, p0l, pl0_b, pmid, (bf16*)nullptr, (bf16*)nullptr, DIM, DIM, HW1);
  // 4. pfin = BN1(dw5x5_s2(pmid)) -> bf16
  dw_s2_bn_bf_kernel<<<(BATCH*DIM*HWP + 255)/256, 256>>>(
      pmid, p1_w, p1_b, bn1_g, bn1_b, bn1_m, bn1_v, pfh, pfl, HP1, HP1, HP2, HP2);
  // 5. kv = conv1x1(pfin) -> bf16 only
  conv1x1_bf_kernel<<<dim3((HWP + 127)/128, (2*DIM)/128, BATCH), 256, CV_SMEM>>>(
      wh + WOFF_KV, wl + WOFF_KV, pfh, pfl, kv_b, (float*)nullptr, kvh, kvl, 2*DIM, DIM, HWP);
  // 6. attention -> gf
  attn4_kernel<<<BATCH*HEADS*7, 128, A4_BYTES>>>(qh, ql, kvh, kvl, gf);
  // 7. local mixer + gating -> bf16 mixbuf
  local_gate_bf_kernel<<<(BATCH*DIM*HWX + 255)/256, 256>>>(qlocal, loc_w, loc_b, gf, mh, ml);
  // 8. out = conv1x1(mixbuf) -> f32
  conv1x1_bf_kernel<<<dim3((HWX + 127)/128, DIM/128, BATCH), 256, CV_SMEM>>>(
      wh + WOFF_MIX, wl + WOFF_MIX, mh, ml, mix_b, out, (bf16*)nullptr, (bf16*)nullptr, DIM, DIM, HWX);
}

// round 8
// speedup vs baseline: 2.3413x; 1.0903x over previous
#include <cuda_runtime.h>
#include <cuda_fp16.h>
#include <cstdint>

#define BATCH 16
#define DIM 256
#define HH 56
#define WW 56
#define HWX (HH*WW)          // 3136
#define HEADS 8
#define DH 32
#define HP1 28
#define HW1 (HP1*HP1)        // 784
#define HP2 14
#define HWP (HP2*HP2)        // 196
#define BN_EPS 1e-5f

#define SW128(x) ((x) ^ (((x) >> 3) & 0x70))

typedef __half fp16;

__device__ __forceinline__ uint32_t smem_u32(const void* p) {
  uint32_t a;
  asm("{ .reg .u64 t; cvta.to.shared.u64 t, %1; cvt.u32.u64 %0, t; }" : "=r"(a) : "l"(p));
  return a;
}
__device__ __forceinline__ void ldmA(uint32_t a[4], uint32_t addr) {
  asm volatile("ldmatrix.sync.aligned.m8n8.x4.shared.b16 {%0,%1,%2,%3}, [%4];"
               : "=r"(a[0]), "=r"(a[1]), "=r"(a[2]), "=r"(a[3]) : "r"(addr));
}
__device__ __forceinline__ void ldmB(uint32_t b[2], uint32_t addr) {
  asm volatile("ldmatrix.sync.aligned.m8n8.x2.shared.b16 {%0,%1}, [%2];"
               : "=r"(b[0]), "=r"(b[1]) : "r"(addr));
}
__device__ __forceinline__ void ldmBT(uint32_t b[2], uint32_t addr) {
  asm volatile("ldmatrix.sync.aligned.m8n8.x2.trans.shared.b16 {%0,%1}, [%2];"
               : "=r"(b[0]), "=r"(b[1]) : "r"(addr));
}
// fp16 inputs, f32 accumulate (hi*hi pass)
__device__ __forceinline__ void mmaF32(float d[4], const uint32_t a[4], const uint32_t b[2]) {
  asm volatile("mma.sync.aligned.m16n8k16.row.col.f32.f16.f16.f32 "
               "{%0,%1,%2,%3}, {%4,%5,%6,%7}, {%8,%9}, {%0,%1,%2,%3};"
               : "+f"(d[0]), "+f"(d[1]), "+f"(d[2]), "+f"(d[3])
               : "r"(a[0]), "r"(a[1]), "r"(a[2]), "r"(a[3]), "r"(b[0]), "r"(b[1]));
}
// fp16 inputs, f16 accumulate (correction passes; values ~2^-11 scale)
__device__ __forceinline__ void mmaF16(uint32_t d[2], const uint32_t a[4], const uint32_t b[2]) {
  asm volatile("mma.sync.aligned.m16n8k16.row.col.f16.f16.f16.f16 "
               "{%0,%1}, {%2,%3,%4,%5}, {%6,%7}, {%0,%1};"
               : "+r"(d[0]), "+r"(d[1])
               : "r"(a[0]), "r"(a[1]), "r"(a[2]), "r"(a[3]), "r"(b[0]), "r"(b[1]));
}
__device__ __forceinline__ uint32_t hpack(float a, float b) {
  __half2 t = __floats2half2_rn(a, b);
  return *(uint32_t*)&t;
}
__device__ __forceinline__ uint32_t hpack_res(float a, float b, uint32_t hp) {
  __half2 h = *(__half2*)&hp;
  return hpack(a - __half2float(h.x), b - __half2float(h.y));
}
__device__ __forceinline__ float hlo(uint32_t v) { return __half2float(((__half2*)&v)->x); }
__device__ __forceinline__ float hhi(uint32_t v) { return __half2float(((__half2*)&v)->y); }

// ---------------- scratch (device globals; no allocations allowed) ----------------
__device__ float g_qlocal[BATCH*DIM*HWX];
__device__ float g_pmid[BATCH*DIM*HW1];
__device__ float g_gf[BATCH*DIM*HWX];
#define NX (BATCH*DIM*HWX)
#define NP0 (BATCH*DIM*HW1)
#define NPF (BATCH*DIM*HWP)
#define NKV (BATCH*2*DIM*HWP)
#define WOFF_Q 0
#define WOFF_PL 65536
#define WOFF_KV 131072
#define WOFF_MIX 262144
#define NW 327680
__device__ fp16 g_xh[NX],  g_xl[NX];
__device__ fp16 g_qh[NX],  g_ql[NX];
__device__ fp16 g_mh[NX],  g_ml[NX];
__device__ fp16 g_p0h[NP0], g_p0l[NP0];
__device__ fp16 g_pfh[NPF], g_pfl[NPF];
__device__ fp16 g_kvh[NKV], g_kvl[NKV];
__device__ fp16 g_wh[NW],  g_wl[NW];

// ---------------- f32 -> fp16 hi/lo split (vectorized) ----------------
__global__ __launch_bounds__(256) void cvt_hl_kernel(
    const float* __restrict__ s, fp16* __restrict__ h, fp16* __restrict__ l, int n4) {
  int i = blockIdx.x * 256 + threadIdx.x;
  if (i >= n4) return;
  float4 v = ((const float4*)s)[i];
  __half2 h0 = __floats2half2_rn(v.x, v.y);
  __half2 h1 = __floats2half2_rn(v.z, v.w);
  __half2 l0 = __floats2half2_rn(v.x - __half2float(h0.x), v.y - __half2float(h0.y));
  __half2 l1 = __floats2half2_rn(v.z - __half2float(h1.x), v.w - __half2float(h1.y));
  ((__half2*)h)[2*i] = h0; ((__half2*)h)[2*i+1] = h1;
  ((__half2*)l)[2*i] = l0; ((__half2*)l)[2*i+1] = l1;
}

// ---------------- 1x1 conv: split-fp16 HMMA ----------------
#define CV_SMEM 65536

__global__ __launch_bounds__(256) void conv1x1_hf_kernel(
    const fp16* __restrict__ Ah, const fp16* __restrict__ Al,
    const fp16* __restrict__ Bh, const fp16* __restrict__ Bl,
    const float* __restrict__ bias, float* __restrict__ Yf,
    fp16* __restrict__ Yh, fp16* __restrict__ Yl,
    int CO, int CI, int HW) {
  extern __shared__ __align__(1024) char smem[];
  char* sAh = smem;         char* sAl = smem + 16384;
  char* sBh = smem + 32768; char* sBl = smem + 49152;
  uint32_t aAh = smem_u32(sAh), aAl = smem_u32(sAl);
  uint32_t aBh = smem_u32(sBh), aBl = smem_u32(sBl);
  int tid = threadIdx.x, lane = tid & 31, wid = tid >> 5;
  int m0 = blockIdx.y * 128, n0 = blockIdx.x * 128;
  const fp16* Bhb = Bh + (size_t)blockIdx.z * CI * HW;
  const fp16* Blb = Bl + (size_t)blockIdx.z * CI * HW;
  int mw = (wid & 3) * 32, nw = (wid >> 2) * 64;

  float acc[2][8][4];
  uint32_t accH[2][8][2];
#pragma unroll
  for (int i = 0; i < 2; i++)
#pragma unroll
    for (int j = 0; j < 8; j++) {
#pragma unroll
      for (int c = 0; c < 4; c++) acc[i][j][c] = 0.f;
      accH[i][j][0] = 0u; accH[i][j][1] = 0u;
    }

  for (int k0 = 0; k0 < CI; k0 += 64) {
#pragma unroll
    for (int i = 0; i < 4; i++) {
      int t = tid + i * 256;
      int m = t >> 3, kg = t & 7;
      size_t src = (size_t)(m0 + m) * CI + k0 + kg * 8;
      uint32_t dst = SW128(m * 128 + kg * 16);
      *(uint4*)(sAh + dst) = *(const uint4*)(Ah + src);
      *(uint4*)(sAl + dst) = *(const uint4*)(Al + src);
    }
#pragma unroll
    for (int i = 0; i < 4; i++) {
      int t = tid + i * 256;
      int k = t & 63, c = t >> 6;
      int gn = n0 + c * 8;
      uint4 vh, vl;
      if (gn + 8 <= HW) {
        const char* ph = (const char*)(Bhb + (size_t)(k0 + k) * HW + gn);
        const char* pl = (const char*)(Blb + (size_t)(k0 + k) * HW + gn);
        uint2 h0 = *(const uint2*)ph, h1 = *(const uint2*)(ph + 8);
        uint2 l0 = *(const uint2*)pl, l1 = *(const uint2*)(pl + 8);
        vh = make_uint4(h0.x, h0.y, h1.x, h1.y);
        vl = make_uint4(l0.x, l0.y, l1.x, l1.y);
      } else {
        fp16 th[8], tl[8];
#pragma unroll
        for (int j = 0; j < 8; j++) {
          int g = gn + j;
          th[j] = (g < HW) ? Bhb[(size_t)(k0 + k) * HW + g] : __float2half(0.f);
          tl[j] = (g < HW) ? Blb[(size_t)(k0 + k) * HW + g] : __float2half(0.f);
        }
        vh = *(uint4*)th; vl = *(uint4*)tl;
      }
      uint32_t dst = k * 256 + ((c ^ (k & 15)) << 4);
      *(uint4*)(sBh + dst) = vh;
      *(uint4*)(sBl + dst) = vl;
    }
    __syncthreads();
#pragma unroll
    for (int s = 0; s < 4; s++) {
      uint32_t ah[2][4], al[2][4];
#pragma unroll
      for (int tm = 0; tm < 2; tm++) {
        uint32_t off = SW128((mw + tm * 16 + (lane & 15)) * 128 + s * 32 + (lane >> 4) * 16);
        ldmA(ah[tm], aAh + off);
        ldmA(al[tm], aAl + off);
      }
      int l = lane & 15;
      int kk = s * 16 + l;
#pragma unroll
      for (int nt = 0; nt < 8; nt++) {
        uint32_t boff = kk * 256 + ((((nw >> 3) + nt) ^ (kk & 15)) << 4);
        uint32_t bh[2], bl[2];
        ldmBT(bh, aBh + boff);
        ldmBT(bl, aBl + boff);
#pragma unroll
        for (int tm = 0; tm < 2; tm++) {
          mmaF32(acc[tm][nt], ah[tm], bh);
          mmaF16(accH[tm][nt], al[tm], bh);
          mmaF16(accH[tm][nt], ah[tm], bl);
        }
      }
    }
    __syncthreads();
  }
  // epilogue: merge f32 + f16-correction accumulators, + bias
#pragma unroll
  for (int tm = 0; tm < 2; tm++) {
    int r0 = m0 + mw + tm * 16 + (lane >> 2);
    float b0 = bias[r0], b1 = bias[r0 + 8];
#pragma unroll
    for (int tn = 0; tn < 8; tn++) {
      int col = n0 + nw + tn * 8 + (lane & 3) * 2;
      if (col < HW) {
        float o0 = acc[tm][tn][0] + hlo(accH[tm][tn][0]) + b0;
        float o1 = acc[tm][tn][1] + hhi(accH[tm][tn][0]) + b0;
        float o2 = acc[tm][tn][2] + hlo(accH[tm][tn][1]) + b1;
        float o3 = acc[tm][tn][3] + hhi(accH[tm][tn][1]) + b1;
        size_t i0 = (size_t)blockIdx.z * CO * HW + (size_t)r0 * HW + col;
        size_t i1 = i0 + (size_t)8 * HW;
        if (Yf) {
          *(float2*)&Yf[i0] = make_float2(o0, o1);
          *(float2*)&Yf[i1] = make_float2(o2, o3);
        }
        if (Yh) {
          __half2 h0 = __floats2half2_rn(o0, o1);
          __half2 h1 = __floats2half2_rn(o2, o3);
          __half2 l0 = __floats2half2_rn(o0 - __half2float(h0.x), o1 - __half2float(h0.y));
          __half2 l1 = __floats2half2_rn(o2 - __half2float(h1.x), o3 - __half2float(h1.y));
          *(__half2*)&Yh[i0] = h0; *(__half2*)&Yh[i1] = h1;
          *(__half2*)&Yl[i0] = l0; *(__half2*)&Yl[i1] = l1;
        }
      }
    }
  }
}

// ---------------- depthwise 5x5 stride2 pad2 + BatchNorm -> fp16 hi/lo ----------------
__global__ __launch_bounds__(256) void dw_s2_bn_hf_kernel(
    const float* __restrict__ X, const float* __restrict__ Wd,
    const float* __restrict__ bias, const float* __restrict__ gam,
    const float* __restrict__ bet, const float* __restrict__ mu,
    const float* __restrict__ var, fp16* __restrict__ Yh, fp16* __restrict__ Yl,
    int Hin, int Win, int Hout, int Wout) {
  int idx = blockIdx.x * 256 + threadIdx.x;
  int total = BATCH * DIM * Hout * Wout;
  if (idx >= total) return;
  int ox = idx % Wout; int t = idx / Wout;
  int oy = t % Hout; t /= Hout;
  int c = t % DIM; int b = t / DIM;
  const float* xp = X + (size_t)(b * DIM + c) * Hin * Win;
  const float* wp = Wd + c * 25;
  float s = 0.f;
#pragma unroll
  for (int ky = 0; ky < 5; ky++) {
    int iy = oy * 2 - 2 + ky;
    if (iy < 0 || iy >= Hin) continue;
#pragma unroll
    for (int kx = 0; kx < 5; kx++) {
      int ix = ox * 2 - 2 + kx;
      if (ix < 0 || ix >= Win) continue;
      s += xp[iy * Win + ix] * wp[ky * 5 + kx];
    }
  }
  s += bias[c];
  float sc = gam[c] * rsqrtf(var[c] + BN_EPS);
  float r = (s - mu[c]) * sc + bet[c];
  fp16 hb = __float2half_rn(r);
  Yh[idx] = hb;
  Yl[idx] = __float2half_rn(r - __half2float(hb));
}

// ---------------- attention v5: fp16 split, f16-accum corrections, 26/13 tiling ----------------
#define A5_AQH 0
#define A5_AQL 5120
#define A5_KH  10240
#define A5_KL  28160
#define A5_VH  46080
#define A5_VL  60928
#define A5_BYTES 75776

__global__ __launch_bounds__(128, 2) void attn5_kernel(
    const fp16* __restrict__ Qh, const fp16* __restrict__ Ql,
    const fp16* __restrict__ KVh, const fp16* __restrict__ KVl,
    float* __restrict__ GF) {
  extern __shared__ __align__(1024) char sm[];
  uint32_t sb = smem_u32(sm);
  int tid = threadIdx.x, lane = tid & 31, warp = tid >> 5;
  int part = blockIdx.x % 7;
  int bh = blockIdx.x / 7;
  int b = bh >> 3, h = bh & 7;
  const fp16* kHh = KVh + ((size_t)b * 2 * DIM + h * 32) * HWP;
  const fp16* kHl = KVl + ((size_t)b * 2 * DIM + h * 32) * HWP;
  const fp16* vHh = kHh + (size_t)DIM * HWP;
  const fp16* vHl = kHl + (size_t)DIM * HWP;
  const float scal = 0.17677669529663687f;  // 32^-0.5

  // stage K [j][40+d] and V [d][232+j] (zero-padded to 224 keys), hi/lo
  for (int t = tid; t < 896; t += 128) {
    int d = t & 31, jg = t >> 5;
    int j0 = jg * 8;
    fp16 th[8], tl[8], uh[8], ul[8];
    if (j0 + 8 <= HWP) {
      const char* pkh = (const char*)(kHh + (size_t)d * HWP + j0);
      const char* pkl = (const char*)(kHl + (size_t)d * HWP + j0);
      const char* pvh = (const char*)(vHh + (size_t)d * HWP + j0);
      const char* pvl = (const char*)(vHl + (size_t)d * HWP + j0);
      *(uint2*)th = *(const uint2*)pkh; *(uint2*)(th + 4) = *(const uint2*)(pkh + 8);
      *(uint2*)tl = *(const uint2*)pkl; *(uint2*)(tl + 4) = *(const uint2*)(pkl + 8);
      *(uint2*)uh = *(const uint2*)pvh; *(uint2*)(uh + 4) = *(const uint2*)(pvh + 8);
      *(uint2*)ul = *(const uint2*)pvl; *(uint2*)(ul + 4) = *(const uint2*)(pvl + 8);
    } else {
      fp16 z = __float2half(0.f);
#pragma unroll
      for (int j = 0; j < 8; j++) {
        int g = j0 + j;
        bool v = g < HWP;
        th[j] = v ? kHh[(size_t)d * HWP + g] : z;
        tl[j] = v ? kHl[(size_t)d * HWP + g] : z;
        uh[j] = v ? vHh[(size_t)d * HWP + g] : z;
        ul[j] = v ? vHl[(size_t)d * HWP + g] : z;
      }
    }
#pragma unroll
    for (int j = 0; j < 8; j++) {
      *(fp16*)(sm + A5_KH + ((j0 + j) * 40 + d) * 2) = th[j];
      *(fp16*)(sm + A5_KL + ((j0 + j) * 40 + d) * 2) = tl[j];
    }
    *(uint4*)(sm + A5_VH + (d * 232 + j0) * 2) = *(uint4*)uh;
    *(uint4*)(sm + A5_VL + (d * 232 + j0) * 2) = *(uint4*)ul;
  }

  const fp16* qbh = Qh + ((size_t)b * DIM + h * 32) * HWX;
  const fp16* qbl = Ql + ((size_t)b * DIM + h * 32) * HWX;
  float* GFb = GF + ((size_t)b * DIM + h * 32) * HWX;
  int mw = warp * 16;

  for (int it = 0; it < 7; it++) {
    int q0 = (part * 7 + it) * 64;
    __syncthreads();
    // stage Q tile [m][40+d]
    for (int t = tid; t < 256; t += 128) {
      int d = t & 31, mg = t >> 5;
      uint4 vh = *(const uint4*)(qbh + (size_t)d * HWX + q0 + mg * 8);
      uint4 vl = *(const uint4*)(qbl + (size_t)d * HWX + q0 + mg * 8);
      fp16* eh = (fp16*)&vh; fp16* el = (fp16*)&vl;
#pragma unroll
      for (int j = 0; j < 8; j++) {
        *(fp16*)(sm + A5_AQH + ((mg * 8 + j) * 40 + d) * 2) = eh[j];
        *(fp16*)(sm + A5_AQL + ((mg * 8 + j) * 40 + d) * 2) = el[j];
      }
    }
    __syncthreads();

    // ---- QK over 26 key-tiles (208 keys; 196..207 masked)
    float acc[26][4];
    uint32_t accH[26][2];
#pragma unroll
    for (int nt = 0; nt < 26; nt++) {
#pragma unroll
      for (int c = 0; c < 4; c++) acc[nt][c] = 0.f;
      accH[nt][0] = 0u; accH[nt][1] = 0u;
    }
#pragma unroll
    for (int s = 0; s < 2; s++) {
      uint32_t ah[4], al[4];
      uint32_t aoff = ((mw + (lane & 15)) * 40 + s * 16) * 2 + (lane >> 4) * 16;
      ldmA(ah, sb + A5_AQH + aoff);
      ldmA(al, sb + A5_AQL + aoff);
      int l = lane & 15;
#pragma unroll
      for (int nt = 0; nt < 26; nt++) {
        uint32_t bh[2], bl[2];
        uint32_t boff = ((nt * 8 + (l & 7)) * 40 + s * 16) * 2 + ((l >> 3) & 1) * 16;
        ldmB(bh, sb + A5_KH + boff);
        ldmB(bl, sb + A5_KL + boff);
        mmaF32(acc[nt], ah, bh);
        mmaF16(accH[nt], al, bh);
        mmaF16(accH[nt], ah, bl);
      }
    }

    // ---- merge + scale + mask + softmax
    float mx1 = -1e30f, mx2 = -1e30f;
#pragma unroll
    for (int nt = 0; nt < 26; nt++) {
      int jb = nt * 8 + (lane & 3) * 2;
      acc[nt][0] = (acc[nt][0] + hlo(accH[nt][0])) * scal;
      acc[nt][1] = (acc[nt][1] + hhi(accH[nt][0])) * scal;
      acc[nt][2] = (acc[nt][2] + hlo(accH[nt][1])) * scal;
      acc[nt][3] = (acc[nt][3] + hhi(accH[nt][1])) * scal;
      if (jb >= HWP)     { acc[nt][0] = -1e30f; acc[nt][2] = -1e30f; }
      if (jb + 1 >= HWP) { acc[nt][1] = -1e30f; acc[nt][3] = -1e30f; }
      mx1 = fmaxf(mx1, fmaxf(acc[nt][0], acc[nt][1]));
      mx2 = fmaxf(mx2, fmaxf(acc[nt][2], acc[nt][3]));
    }
#pragma unroll
    for (int o = 1; o <= 2; o <<= 1) {
      mx1 = fmaxf(mx1, __shfl_xor_sync(0xffffffffu, mx1, o));
      mx2 = fmaxf(mx2, __shfl_xor_sync(0xffffffffu, mx2, o));
    }
    float sum1 = 0.f, sum2 = 0.f;
#pragma unroll
    for (int nt = 0; nt < 26; nt++) {
      acc[nt][0] = __expf(acc[nt][0] - mx1);
      acc[nt][1] = __expf(acc[nt][1] - mx1);
      acc[nt][2] = __expf(acc[nt][2] - mx2);
      acc[nt][3] = __expf(acc[nt][3] - mx2);
      sum1 += acc[nt][0] + acc[nt][1];
      sum2 += acc[nt][2] + acc[nt][3];
    }
#pragma unroll
    for (int o = 1; o <= 2; o <<= 1) {
      sum1 += __shfl_xor_sync(0xffffffffu, sum1, o);
      sum2 += __shfl_xor_sync(0xffffffffu, sum2, o);
    }
    float rec1 = 1.f / sum1, rec2 = 1.f / sum2;

    // ---- PV over 13 k-steps (208 keys) with register-resident P
    float acc2[4][4];
    uint32_t acc2H[4][2];
#pragma unroll
    for (int nt = 0; nt < 4; nt++) {
#pragma unroll
      for (int c = 0; c < 4; c++) acc2[nt][c] = 0.f;
      acc2H[nt][0] = 0u; acc2H[nt][1] = 0u;
    }
#pragma unroll 1
    for (int k = 0; k < 13; k++) {
      float p00 = acc[2*k][0] * rec1,   p01 = acc[2*k][1] * rec1;
      float p02 = acc[2*k][2] * rec2,   p03 = acc[2*k][3] * rec2;
      float p10 = acc[2*k+1][0] * rec1, p11 = acc[2*k+1][1] * rec1;
      float p12 = acc[2*k+1][2] * rec2, p13 = acc[2*k+1][3] * rec2;
      uint32_t ph[4], pl[4];
      ph[0] = hpack(p00, p01); ph[1] = hpack(p02, p03);
      ph[2] = hpack(p10, p11); ph[3] = hpack(p12, p13);
      pl[0] = hpack_res(p00, p01, ph[0]); pl[1] = hpack_res(p02, p03, ph[1]);
      pl[2] = hpack_res(p10, p11, ph[2]); pl[3] = hpack_res(p12, p13, ph[3]);
      int l = lane & 15;
#pragma unroll
      for (int nt = 0; nt < 4; nt++) {
        uint32_t vh[2], vl[2];
        uint32_t boff = ((nt * 8 + (l & 7)) * 232 + k * 16) * 2 + ((l >> 3) & 1) * 16;
        ldmB(vh, sb + A5_VH + boff);
        ldmB(vl, sb + A5_VL + boff);
        mmaF32(acc2[nt], ph, vh);
        mmaF16(acc2H[nt], pl, vh);
        mmaF16(acc2H[nt], ph, vl);
      }
    }
    __syncthreads();

    // ---- merge + transpose via Obuf f32 [32 d][68]
    float* Ob = (float*)sm;
    {
      int m1 = mw + (lane >> 2), m2 = m1 + 8;
      int cb = (lane & 3) * 2;
#pragma unroll
      for (int nt = 0; nt < 4; nt++) {
        int dcol = nt * 8 + cb;
        Ob[dcol * 68 + m1]       = acc2[nt][0] + hlo(acc2H[nt][0]);
        Ob[(dcol + 1) * 68 + m1] = acc2[nt][1] + hhi(acc2H[nt][0]);
        Ob[dcol * 68 + m2]       = acc2[nt][2] + hlo(acc2H[nt][1]);
        Ob[(dcol + 1) * 68 + m2] = acc2[nt][3] + hhi(acc2H[nt][1]);
      }
    }
    __syncthreads();
    {
      int row = tid >> 2, i0 = (tid & 3) * 16;
#pragma unroll
      for (int c = 0; c < 4; c++) {
        int i = i0 + c * 4;
        *(float4*)&GFb[(size_t)row * HWX + q0 + i] = *(float4*)&Ob[row * 68 + i];
      }
    }
  }
}

// ---------------- local mixer -> fp16 hi/lo mixbuf ----------------
__global__ __launch_bounds__(256) void local_gate_hf_kernel(
    const float* __restrict__ Q, const float* __restrict__ Wd,
    const float* __restrict__ bias, const float* __restrict__ G,
    fp16* __restrict__ Oh, fp16* __restrict__ Ol) {
  int idx = blockIdx.x * 256 + threadIdx.x;
  int total = BATCH * DIM * HWX;
  if (idx >= total) return;
  int ox = idx % WW; int t = idx / WW;
  int oy = t % HH; t /= HH;
  int c = t % DIM; int b = t / DIM;
  const float* xp = Q + (size_t)(b * DIM + c) * HWX;
  const float* wp = Wd + c * 25;
  float s = 0.f;
#pragma unroll
  for (int ky = 0; ky < 5; ky++) {
    int iy = oy + ky - 2;
    if (iy < 0 || iy >= HH) continue;
#pragma unroll
    for (int kx = 0; kx < 5; kx++) {
      int ix = ox + kx - 2;
      if (ix < 0 || ix >= WW) continue;
      s += xp[iy * WW + ix] * wp[ky * 5 + kx];
    }
  }
  s += bias[c];
  float lf = s / (1.f + __expf(-s));
  float gv = G[idx];
  float sg = 1.f / (1.f + __expf(-gv));
  float r = lf * sg * gv;
  fp16 hb = __float2half_rn(r);
  Oh[idx] = hb;
  Ol[idx] = __float2half_rn(r - __half2float(hb));
}

extern "C" void kernel_launch(void* const* d_in, const int* in_sizes, int n_in,
                              void* d_out, int out_size) {
  const float* x     = (const float*)d_in[0];
  const float* q_w   = (const float*)d_in[1];
  const float* q_b   = (const float*)d_in[2];
  const float* kv_w  = (const float*)d_in[3];
  const float* kv_b  = (const float*)d_in[4];
  const float* p0_w  = (const float*)d_in[5];
  const float* p0_b  = (const float*)d_in[6];
  const float* bn0_g = (const float*)d_in[7];
  const float* bn0_b = (const float*)d_in[8];
  const float* bn0_m = (const float*)d_in[9];
  const float* bn0_v = (const float*)d_in[10];
  const float* pl0_w = (const float*)d_in[11];
  const float* pl0_b = (const float*)d_in[12];
  const float* p1_w  = (const float*)d_in[13];
  const float* p1_b  = (const float*)d_in[14];
  const float* bn1_g = (const float*)d_in[15];
  const float* bn1_b = (const float*)d_in[16];
  const float* bn1_m = (const float*)d_in[17];
  const float* bn1_v = (const float*)d_in[18];
  const float* loc_w = (const float*)d_in[19];
  const float* loc_b = (const float*)d_in[20];
  const float* mix_w = (const float*)d_in[21];
  const float* mix_b = (const float*)d_in[22];
  float* out = (float*)d_out;

  float *qlocal, *pmid, *gf;
  cudaGetSymbolAddress((void**)&qlocal, g_qlocal);
  cudaGetSymbolAddress((void**)&pmid,   g_pmid);
  cudaGetSymbolAddress((void**)&gf,     g_gf);
  fp16 *xh, *xl, *qh, *ql, *mh, *ml, *p0h, *p0l, *pfh, *pfl, *kvh, *kvl, *wh, *wl;
  cudaGetSymbolAddress((void**)&xh, g_xh);   cudaGetSymbolAddress((void**)&xl, g_xl);
  cudaGetSymbolAddress((void**)&qh, g_qh);   cudaGetSymbolAddress((void**)&ql, g_ql);
  cudaGetSymbolAddress((void**)&mh, g_mh);   cudaGetSymbolAddress((void**)&ml, g_ml);
  cudaGetSymbolAddress((void**)&p0h, g_p0h); cudaGetSymbolAddress((void**)&p0l, g_p0l);
  cudaGetSymbolAddress((void**)&pfh, g_pfh); cudaGetSymbolAddress((void**)&pfl, g_pfl);
  cudaGetSymbolAddress((void**)&kvh, g_kvh); cudaGetSymbolAddress((void**)&kvl, g_kvl);
  cudaGetSymbolAddress((void**)&wh, g_wh);   cudaGetSymbolAddress((void**)&wl, g_wl);

  cudaFuncSetAttribute(conv1x1_hf_kernel, cudaFuncAttributeMaxDynamicSharedMemorySize, CV_SMEM);
  cudaFuncSetAttribute(attn5_kernel, cudaFuncAttributeMaxDynamicSharedMemorySize, A5_BYTES);

  // 0. pre-split weights + x to fp16 hi/lo
  cvt_hl_kernel<<<(NX/4 + 255)/256, 256>>>(x, xh, xl, NX/4);
  cvt_hl_kernel<<<(65536/4 + 255)/256, 256>>>(q_w,   wh + WOFF_Q,   wl + WOFF_Q,   65536/4);
  cvt_hl_kernel<<<(65536/4 + 255)/256, 256>>>(pl0_w, wh + WOFF_PL,  wl + WOFF_PL,  65536/4);
  cvt_hl_kernel<<<(131072/4 + 255)/256, 256>>>(kv_w, wh + WOFF_KV,  wl + WOFF_KV,  131072/4);
  cvt_hl_kernel<<<(65536/4 + 255)/256, 256>>>(mix_w, wh + WOFF_MIX, wl + WOFF_MIX, 65536/4);

  // 1. q_local (f32 + fp16 hi/lo)
  conv1x1_hf_kernel<<<dim3((HWX + 127)/128, DIM/128, BATCH), 256, CV_SMEM>>>(
      wh + WOFF_Q, wl + WOFF_Q, xh, xl, q_b, qlocal, qh, ql, DIM, DIM, HWX);
  // 2. p0 = BN0(dw5x5_s2(x)) -> fp16
  dw_s2_bn_hf_kernel<<<(BATCH*DIM*HW1 + 255)/256, 256>>>(
      x, p0_w, p0_b, bn0_g, bn0_b, bn0_m, bn0_v, p0h, p0l, HH, WW, HP1, HP1);
  // 3. pmid = conv1x1(p0) -> f32
  conv1x1_hf_kernel<<<dim3((HW1 + 127)/128, DIM/128, BATCH), 256, CV_SMEM>>>(
      wh + WOFF_PL, wl + WOFF_PL, p0h, p0l, pl0_b, pmid, (fp16*)nullptr, (fp16*)nullptr, DIM, DIM, HW1);
  // 4. pfin = BN1(dw5x5_s2(pmid)) -> fp16
  dw_s2_bn_hf_kernel<<<(BATCH*DIM*HWP + 255)/256, 256>>>(
      pmid, p1_w, p1_b, bn1_g, bn1_b, bn1_m, bn1_v, pfh, pfl, HP1, HP1, HP2, HP2);
  // 5. kv = conv1x1(pfin) -> fp16 only
  conv1x1_hf_kernel<<<dim3((HWP + 127)/128, (2*DIM)/128, BATCH), 256, CV_SMEM>>>(
      wh + WOFF_KV, wl + WOFF_KV, pfh, pfl, kv_b, (float*)nullptr, kvh, kvl, 2*DIM, DIM, HWP);
  // 6. attention -> gf
  attn5_kernel<<<BATCH*HEADS*7, 128, A5_BYTES>>>(qh, ql, kvh, kvl, gf);
  // 7. local mixer + gating -> fp16 mixbuf
  local_gate_hf_kernel<<<(BATCH*DIM*HWX + 255)/256, 256>>>(qlocal, loc_w, loc_b, gf, mh, ml);
  // 8. out = conv1x1(mixbuf) -> f32
  conv1x1_hf_kernel<<<dim3((HWX + 127)/128, DIM/128, BATCH), 256, CV_SMEM>>>(
      wh + WOFF_MIX, wl + WOFF_MIX, mh, ml, mix_b, out, (fp16*)nullptr, (fp16*)nullptr, DIM, DIM, HWX);
}

// round 9
// speedup vs baseline: 2.4328x; 1.0391x over previous
#include <cuda_runtime.h>
#include <cuda_fp16.h>
#include <cstdint>

#define BATCH 16
#define DIM 256
#define HH 56
#define WW 56
#define HWX (HH*WW)          // 3136
#define HEADS 8
#define DH 32
#define HP1 28
#define HW1 (HP1*HP1)        // 784
#define HP2 14
#define HWP (HP2*HP2)        // 196
#define BN_EPS 1e-5f

#define SW128(x) ((x) ^ (((x) >> 3) & 0x70))

typedef __half fp16;

__device__ __forceinline__ uint32_t smem_u32(const void* p) {
  uint32_t a;
  asm("{ .reg .u64 t; cvta.to.shared.u64 t, %1; cvt.u32.u64 %0, t; }" : "=r"(a) : "l"(p));
  return a;
}
__device__ __forceinline__ void ldmA(uint32_t a[4], uint32_t addr) {
  asm volatile("ldmatrix.sync.aligned.m8n8.x4.shared.b16 {%0,%1,%2,%3}, [%4];"
               : "=r"(a[0]), "=r"(a[1]), "=r"(a[2]), "=r"(a[3]) : "r"(addr));
}
__device__ __forceinline__ void ldmB(uint32_t b[2], uint32_t addr) {
  asm volatile("ldmatrix.sync.aligned.m8n8.x2.shared.b16 {%0,%1}, [%2];"
               : "=r"(b[0]), "=r"(b[1]) : "r"(addr));
}
__device__ __forceinline__ void ldmBT(uint32_t b[2], uint32_t addr) {
  asm volatile("ldmatrix.sync.aligned.m8n8.x2.trans.shared.b16 {%0,%1}, [%2];"
               : "=r"(b[0]), "=r"(b[1]) : "r"(addr));
}
// fp16 inputs, f32 accumulate (hi*hi pass)
__device__ __forceinline__ void mmaF32(float d[4], const uint32_t a[4], const uint32_t b[2]) {
  asm volatile("mma.sync.aligned.m16n8k16.row.col.f32.f16.f16.f32 "
               "{%0,%1,%2,%3}, {%4,%5,%6,%7}, {%8,%9}, {%0,%1,%2,%3};"
               : "+f"(d[0]), "+f"(d[1]), "+f"(d[2]), "+f"(d[3])
               : "r"(a[0]), "r"(a[1]), "r"(a[2]), "r"(a[3]), "r"(b[0]), "r"(b[1]));
}
// fp16 inputs, f16 accumulate (correction passes; values ~2^-11 scale)
__device__ __forceinline__ void mmaF16(uint32_t d[2], const uint32_t a[4], const uint32_t b[2]) {
  asm volatile("mma.sync.aligned.m16n8k16.row.col.f16.f16.f16.f16 "
               "{%0,%1}, {%2,%3,%4,%5}, {%6,%7}, {%0,%1};"
               : "+r"(d[0]), "+r"(d[1])
               : "r"(a[0]), "r"(a[1]), "r"(a[2]), "r"(a[3]), "r"(b[0]), "r"(b[1]));
}
__device__ __forceinline__ uint32_t hpack(float a, float b) {
  __half2 t = __floats2half2_rn(a, b);
  return *(uint32_t*)&t;
}
__device__ __forceinline__ float hlo(uint32_t v) { return __half2float(((__half2*)&v)->x); }
__device__ __forceinline__ float hhi(uint32_t v) { return __half2float(((__half2*)&v)->y); }

// ---------------- scratch (device globals; no allocations allowed) ----------------
__device__ float g_qlocal[BATCH*DIM*HWX];
__device__ float g_pmid[BATCH*DIM*HW1];
__device__ float g_gf[BATCH*DIM*HWX];
#define NX (BATCH*DIM*HWX)
#define NP0 (BATCH*DIM*HW1)
#define NPF (BATCH*DIM*HWP)
#define NKV (BATCH*2*DIM*HWP)
#define WOFF_Q 0
#define WOFF_PL 65536
#define WOFF_KV 131072
#define WOFF_MIX 262144
#define NW 327680
__device__ fp16 g_xh[NX],  g_xl[NX];
__device__ fp16 g_qh[NX],  g_ql[NX];
__device__ fp16 g_mh[NX],  g_ml[NX];
__device__ fp16 g_p0h[NP0], g_p0l[NP0];
__device__ fp16 g_pfh[NPF], g_pfl[NPF];
__device__ fp16 g_kvh[NKV], g_kvl[NKV];
__device__ fp16 g_wh[NW],  g_wl[NW];

// ---------------- f32 -> fp16 hi/lo split (vectorized) ----------------
__global__ __launch_bounds__(256) void cvt_hl_kernel(
    const float* __restrict__ s, fp16* __restrict__ h, fp16* __restrict__ l, int n4) {
  int i = blockIdx.x * 256 + threadIdx.x;
  if (i >= n4) return;
  float4 v = ((const float4*)s)[i];
  __half2 h0 = __floats2half2_rn(v.x, v.y);
  __half2 h1 = __floats2half2_rn(v.z, v.w);
  __half2 l0 = __floats2half2_rn(v.x - __half2float(h0.x), v.y - __half2float(h0.y));
  __half2 l1 = __floats2half2_rn(v.z - __half2float(h1.x), v.w - __half2float(h1.y));
  ((__half2*)h)[2*i] = h0; ((__half2*)h)[2*i+1] = h1;
  ((__half2*)l)[2*i] = l0; ((__half2*)l)[2*i+1] = l1;
}

// ---------------- 1x1 conv: split-fp16 HMMA (3-pass, f16-accum corrections) ----------------
#define CV_SMEM 65536

__global__ __launch_bounds__(256) void conv1x1_hf_kernel(
    const fp16* __restrict__ Ah, const fp16* __restrict__ Al,
    const fp16* __restrict__ Bh, const fp16* __restrict__ Bl,
    const float* __restrict__ bias, float* __restrict__ Yf,
    fp16* __restrict__ Yh, fp16* __restrict__ Yl,
    int CO, int CI, int HW) {
  extern __shared__ __align__(1024) char smem[];
  char* sAh = smem;         char* sAl = smem + 16384;
  char* sBh = smem + 32768; char* sBl = smem + 49152;
  uint32_t aAh = smem_u32(sAh), aAl = smem_u32(sAl);
  uint32_t aBh = smem_u32(sBh), aBl = smem_u32(sBl);
  int tid = threadIdx.x, lane = tid & 31, wid = tid >> 5;
  int m0 = blockIdx.y * 128, n0 = blockIdx.x * 128;
  const fp16* Bhb = Bh + (size_t)blockIdx.z * CI * HW;
  const fp16* Blb = Bl + (size_t)blockIdx.z * CI * HW;
  int mw = (wid & 3) * 32, nw = (wid >> 2) * 64;

  float acc[2][8][4];
  uint32_t accH[2][8][2];
#pragma unroll
  for (int i = 0; i < 2; i++)
#pragma unroll
    for (int j = 0; j < 8; j++) {
#pragma unroll
      for (int c = 0; c < 4; c++) acc[i][j][c] = 0.f;
      accH[i][j][0] = 0u; accH[i][j][1] = 0u;
    }

  for (int k0 = 0; k0 < CI; k0 += 64) {
#pragma unroll
    for (int i = 0; i < 4; i++) {
      int t = tid + i * 256;
      int m = t >> 3, kg = t & 7;
      size_t src = (size_t)(m0 + m) * CI + k0 + kg * 8;
      uint32_t dst = SW128(m * 128 + kg * 16);
      *(uint4*)(sAh + dst) = *(const uint4*)(Ah + src);
      *(uint4*)(sAl + dst) = *(const uint4*)(Al + src);
    }
#pragma unroll
    for (int i = 0; i < 4; i++) {
      int t = tid + i * 256;
      int k = t & 63, c = t >> 6;
      int gn = n0 + c * 8;
      uint4 vh, vl;
      if (gn + 8 <= HW) {
        const char* ph = (const char*)(Bhb + (size_t)(k0 + k) * HW + gn);
        const char* pl = (const char*)(Blb + (size_t)(k0 + k) * HW + gn);
        uint2 h0 = *(const uint2*)ph, h1 = *(const uint2*)(ph + 8);
        uint2 l0 = *(const uint2*)pl, l1 = *(const uint2*)(pl + 8);
        vh = make_uint4(h0.x, h0.y, h1.x, h1.y);
        vl = make_uint4(l0.x, l0.y, l1.x, l1.y);
      } else {
        fp16 th[8], tl[8];
#pragma unroll
        for (int j = 0; j < 8; j++) {
          int g = gn + j;
          th[j] = (g < HW) ? Bhb[(size_t)(k0 + k) * HW + g] : __float2half(0.f);
          tl[j] = (g < HW) ? Blb[(size_t)(k0 + k) * HW + g] : __float2half(0.f);
        }
        vh = *(uint4*)th; vl = *(uint4*)tl;
      }
      uint32_t dst = k * 256 + ((c ^ (k & 15)) << 4);
      *(uint4*)(sBh + dst) = vh;
      *(uint4*)(sBl + dst) = vl;
    }
    __syncthreads();
#pragma unroll
    for (int s = 0; s < 4; s++) {
      uint32_t ah[2][4], al[2][4];
#pragma unroll
      for (int tm = 0; tm < 2; tm++) {
        uint32_t off = SW128((mw + tm * 16 + (lane & 15)) * 128 + s * 32 + (lane >> 4) * 16);
        ldmA(ah[tm], aAh + off);
        ldmA(al[tm], aAl + off);
      }
      int l = lane & 15;
      int kk = s * 16 + l;
#pragma unroll
      for (int nt = 0; nt < 8; nt++) {
        uint32_t boff = kk * 256 + ((((nw >> 3) + nt) ^ (kk & 15)) << 4);
        uint32_t bh[2], bl[2];
        ldmBT(bh, aBh + boff);
        ldmBT(bl, aBl + boff);
#pragma unroll
        for (int tm = 0; tm < 2; tm++) {
          mmaF32(acc[tm][nt], ah[tm], bh);
          mmaF16(accH[tm][nt], al[tm], bh);
          mmaF16(accH[tm][nt], ah[tm], bl);
        }
      }
    }
    __syncthreads();
  }
  // epilogue: merge f32 + f16-correction accumulators, + bias
#pragma unroll
  for (int tm = 0; tm < 2; tm++) {
    int r0 = m0 + mw + tm * 16 + (lane >> 2);
    float b0 = bias[r0], b1 = bias[r0 + 8];
#pragma unroll
    for (int tn = 0; tn < 8; tn++) {
      int col = n0 + nw + tn * 8 + (lane & 3) * 2;
      if (col < HW) {
        float o0 = acc[tm][tn][0] + hlo(accH[tm][tn][0]) + b0;
        float o1 = acc[tm][tn][1] + hhi(accH[tm][tn][0]) + b0;
        float o2 = acc[tm][tn][2] + hlo(accH[tm][tn][1]) + b1;
        float o3 = acc[tm][tn][3] + hhi(accH[tm][tn][1]) + b1;
        size_t i0 = (size_t)blockIdx.z * CO * HW + (size_t)r0 * HW + col;
        size_t i1 = i0 + (size_t)8 * HW;
        if (Yf) {
          *(float2*)&Yf[i0] = make_float2(o0, o1);
          *(float2*)&Yf[i1] = make_float2(o2, o3);
        }
        if (Yh) {
          __half2 h0 = __floats2half2_rn(o0, o1);
          __half2 h1 = __floats2half2_rn(o2, o3);
          __half2 l0 = __floats2half2_rn(o0 - __half2float(h0.x), o1 - __half2float(h0.y));
          __half2 l1 = __floats2half2_rn(o2 - __half2float(h1.x), o3 - __half2float(h1.y));
          *(__half2*)&Yh[i0] = h0; *(__half2*)&Yh[i1] = h1;
          *(__half2*)&Yl[i0] = l0; *(__half2*)&Yl[i1] = l1;
        }
      }
    }
  }
}

// ---------------- depthwise 5x5 stride2 pad2 + BatchNorm -> fp16 hi/lo ----------------
__global__ __launch_bounds__(256) void dw_s2_bn_hf_kernel(
    const float* __restrict__ X, const float* __restrict__ Wd,
    const float* __restrict__ bias, const float* __restrict__ gam,
    const float* __restrict__ bet, const float* __restrict__ mu,
    const float* __restrict__ var, fp16* __restrict__ Yh, fp16* __restrict__ Yl,
    int Hin, int Win, int Hout, int Wout) {
  int idx = blockIdx.x * 256 + threadIdx.x;
  int total = BATCH * DIM * Hout * Wout;
  if (idx >= total) return;
  int ox = idx % Wout; int t = idx / Wout;
  int oy = t % Hout; t /= Hout;
  int c = t % DIM; int b = t / DIM;
  const float* xp = X + (size_t)(b * DIM + c) * Hin * Win;
  const float* wp = Wd + c * 25;
  float s = 0.f;
#pragma unroll
  for (int ky = 0; ky < 5; ky++) {
    int iy = oy * 2 - 2 + ky;
    if (iy < 0 || iy >= Hin) continue;
#pragma unroll
    for (int kx = 0; kx < 5; kx++) {
      int ix = ox * 2 - 2 + kx;
      if (ix < 0 || ix >= Win) continue;
      s += xp[iy * Win + ix] * wp[ky * 5 + kx];
    }
  }
  s += bias[c];
  float sc = gam[c] * rsqrtf(var[c] + BN_EPS);
  float r = (s - mu[c]) * sc + bet[c];
  fp16 hb = __float2half_rn(r);
  Yh[idx] = hb;
  Yl[idx] = __float2half_rn(r - __half2float(hb));
}

// ---------------- attention v6: 2-pass QK (Qh·Kh + Qh·Kl), 2-pass PV (Ph·Vh + Ph·Vl) ----
// No Q-lo staging at all; no P-lo packing. Obuf (32x68 f32 = 8704B) overlays the
// 8704-byte region at offset 0 (AQH 5120B + pad).
#define A6_AQH 0
#define A6_KH  8704
#define A6_KL  26624
#define A6_VH  44544
#define A6_VL  59392
#define A6_BYTES 74240

__global__ __launch_bounds__(128, 2) void attn6_kernel(
    const fp16* __restrict__ Qh,
    const fp16* __restrict__ KVh, const fp16* __restrict__ KVl,
    float* __restrict__ GF) {
  extern __shared__ __align__(1024) char sm[];
  uint32_t sb = smem_u32(sm);
  int tid = threadIdx.x, lane = tid & 31, warp = tid >> 5;
  int part = blockIdx.x % 7;
  int bh = blockIdx.x / 7;
  int b = bh >> 3, h = bh & 7;
  const fp16* kHh = KVh + ((size_t)b * 2 * DIM + h * 32) * HWP;
  const fp16* kHl = KVl + ((size_t)b * 2 * DIM + h * 32) * HWP;
  const fp16* vHh = kHh + (size_t)DIM * HWP;
  const fp16* vHl = kHl + (size_t)DIM * HWP;
  const float scal = 0.17677669529663687f;  // 32^-0.5

  // stage K [j][40+d] and V [d][232+j] (zero-padded to 224 keys), hi/lo
  for (int t = tid; t < 896; t += 128) {
    int d = t & 31, jg = t >> 5;
    int j0 = jg * 8;
    fp16 th[8], tl[8], uh[8], ul[8];
    if (j0 + 8 <= HWP) {
      const char* pkh = (const char*)(kHh + (size_t)d * HWP + j0);
      const char* pkl = (const char*)(kHl + (size_t)d * HWP + j0);
      const char* pvh = (const char*)(vHh + (size_t)d * HWP + j0);
      const char* pvl = (const char*)(vHl + (size_t)d * HWP + j0);
      *(uint2*)th = *(const uint2*)pkh; *(uint2*)(th + 4) = *(const uint2*)(pkh + 8);
      *(uint2*)tl = *(const uint2*)pkl; *(uint2*)(tl + 4) = *(const uint2*)(pkl + 8);
      *(uint2*)uh = *(const uint2*)pvh; *(uint2*)(uh + 4) = *(const uint2*)(pvh + 8);
      *(uint2*)ul = *(const uint2*)pvl; *(uint2*)(ul + 4) = *(const uint2*)(pvl + 8);
    } else {
      fp16 z = __float2half(0.f);
#pragma unroll
      for (int j = 0; j < 8; j++) {
        int g = j0 + j;
        bool v = g < HWP;
        th[j] = v ? kHh[(size_t)d * HWP + g] : z;
        tl[j] = v ? kHl[(size_t)d * HWP + g] : z;
        uh[j] = v ? vHh[(size_t)d * HWP + g] : z;
        ul[j] = v ? vHl[(size_t)d * HWP + g] : z;
      }
    }
#pragma unroll
    for (int j = 0; j < 8; j++) {
      *(fp16*)(sm + A6_KH + ((j0 + j) * 40 + d) * 2) = th[j];
      *(fp16*)(sm + A6_KL + ((j0 + j) * 40 + d) * 2) = tl[j];
    }
    *(uint4*)(sm + A6_VH + (d * 232 + j0) * 2) = *(uint4*)uh;
    *(uint4*)(sm + A6_VL + (d * 232 + j0) * 2) = *(uint4*)ul;
  }

  const fp16* qbh = Qh + ((size_t)b * DIM + h * 32) * HWX;
  float* GFb = GF + ((size_t)b * DIM + h * 32) * HWX;
  int mw = warp * 16;

  for (int it = 0; it < 7; it++) {
    int q0 = (part * 7 + it) * 64;
    __syncthreads();
    // stage Q tile [m][40+d] (hi only)
    for (int t = tid; t < 256; t += 128) {
      int d = t & 31, mg = t >> 5;
      uint4 vh = *(const uint4*)(qbh + (size_t)d * HWX + q0 + mg * 8);
      fp16* eh = (fp16*)&vh;
#pragma unroll
      for (int j = 0; j < 8; j++)
        *(fp16*)(sm + A6_AQH + ((mg * 8 + j) * 40 + d) * 2) = eh[j];
    }
    __syncthreads();

    // ---- QK over 26 key-tiles (208 keys; 196..207 masked), 2-pass
    float acc[26][4];
    uint32_t accH[26][2];
#pragma unroll
    for (int nt = 0; nt < 26; nt++) {
#pragma unroll
      for (int c = 0; c < 4; c++) acc[nt][c] = 0.f;
      accH[nt][0] = 0u; accH[nt][1] = 0u;
    }
#pragma unroll
    for (int s = 0; s < 2; s++) {
      uint32_t ah[4];
      uint32_t aoff = ((mw + (lane & 15)) * 40 + s * 16) * 2 + (lane >> 4) * 16;
      ldmA(ah, sb + A6_AQH + aoff);
      int l = lane & 15;
#pragma unroll
      for (int nt = 0; nt < 26; nt++) {
        uint32_t bh[2], bl[2];
        uint32_t boff = ((nt * 8 + (l & 7)) * 40 + s * 16) * 2 + ((l >> 3) & 1) * 16;
        ldmB(bh, sb + A6_KH + boff);
        ldmB(bl, sb + A6_KL + boff);
        mmaF32(acc[nt], ah, bh);
        mmaF16(accH[nt], ah, bl);
      }
    }

    // ---- merge + scale + mask + softmax
    float mx1 = -1e30f, mx2 = -1e30f;
#pragma unroll
    for (int nt = 0; nt < 26; nt++) {
      int jb = nt * 8 + (lane & 3) * 2;
      acc[nt][0] = (acc[nt][0] + hlo(accH[nt][0])) * scal;
      acc[nt][1] = (acc[nt][1] + hhi(accH[nt][0])) * scal;
      acc[nt][2] = (acc[nt][2] + hlo(accH[nt][1])) * scal;
      acc[nt][3] = (acc[nt][3] + hhi(accH[nt][1])) * scal;
      if (jb >= HWP)     { acc[nt][0] = -1e30f; acc[nt][2] = -1e30f; }
      if (jb + 1 >= HWP) { acc[nt][1] = -1e30f; acc[nt][3] = -1e30f; }
      mx1 = fmaxf(mx1, fmaxf(acc[nt][0], acc[nt][1]));
      mx2 = fmaxf(mx2, fmaxf(acc[nt][2], acc[nt][3]));
    }
#pragma unroll
    for (int o = 1; o <= 2; o <<= 1) {
      mx1 = fmaxf(mx1, __shfl_xor_sync(0xffffffffu, mx1, o));
      mx2 = fmaxf(mx2, __shfl_xor_sync(0xffffffffu, mx2, o));
    }
    float sum1 = 0.f, sum2 = 0.f;
#pragma unroll
    for (int nt = 0; nt < 26; nt++) {
      acc[nt][0] = __expf(acc[nt][0] - mx1);
      acc[nt][1] = __expf(acc[nt][1] - mx1);
      acc[nt][2] = __expf(acc[nt][2] - mx2);
      acc[nt][3] = __expf(acc[nt][3] - mx2);
      sum1 += acc[nt][0] + acc[nt][1];
      sum2 += acc[nt][2] + acc[nt][3];
    }
#pragma unroll
    for (int o = 1; o <= 2; o <<= 1) {
      sum1 += __shfl_xor_sync(0xffffffffu, sum1, o);
      sum2 += __shfl_xor_sync(0xffffffffu, sum2, o);
    }
    float rec1 = 1.f / sum1, rec2 = 1.f / sum2;

    // ---- PV over 13 k-steps, register-resident P (hi only), 2-pass
    float acc2[4][4];
    uint32_t acc2H[4][2];
#pragma unroll
    for (int nt = 0; nt < 4; nt++) {
#pragma unroll
      for (int c = 0; c < 4; c++) acc2[nt][c] = 0.f;
      acc2H[nt][0] = 0u; acc2H[nt][1] = 0u;
    }
#pragma unroll 1
    for (int k = 0; k < 13; k++) {
      uint32_t ph[4];
      ph[0] = hpack(acc[2*k][0] * rec1,   acc[2*k][1] * rec1);
      ph[1] = hpack(acc[2*k][2] * rec2,   acc[2*k][3] * rec2);
      ph[2] = hpack(acc[2*k+1][0] * rec1, acc[2*k+1][1] * rec1);
      ph[3] = hpack(acc[2*k+1][2] * rec2, acc[2*k+1][3] * rec2);
      int l = lane & 15;
#pragma unroll
      for (int nt = 0; nt < 4; nt++) {
        uint32_t vh[2], vl[2];
        uint32_t boff = ((nt * 8 + (l & 7)) * 232 + k * 16) * 2 + ((l >> 3) & 1) * 16;
        ldmB(vh, sb + A6_VH + boff);
        ldmB(vl, sb + A6_VL + boff);
        mmaF32(acc2[nt], ph, vh);
        mmaF16(acc2H[nt], ph, vl);
      }
    }
    __syncthreads();

    // ---- merge + transpose via Obuf f32 [32 d][68] (overlays AQ region)
    float* Ob = (float*)sm;
    {
      int m1 = mw + (lane >> 2), m2 = m1 + 8;
      int cb = (lane & 3) * 2;
#pragma unroll
      for (int nt = 0; nt < 4; nt++) {
        int dcol = nt * 8 + cb;
        Ob[dcol * 68 + m1]       = acc2[nt][0] + hlo(acc2H[nt][0]);
        Ob[(dcol + 1) * 68 + m1] = acc2[nt][1] + hhi(acc2H[nt][0]);
        Ob[dcol * 68 + m2]       = acc2[nt][2] + hlo(acc2H[nt][1]);
        Ob[(dcol + 1) * 68 + m2] = acc2[nt][3] + hhi(acc2H[nt][1]);
      }
    }
    __syncthreads();
    {
      int row = tid >> 2, i0 = (tid & 3) * 16;
#pragma unroll
      for (int c = 0; c < 4; c++) {
        int i = i0 + c * 4;
        *(float4*)&GFb[(size_t)row * HWX + q0 + i] = *(float4*)&Ob[row * 68 + i];
      }
    }
  }
}

// ---------------- local mixer -> fp16 hi/lo mixbuf ----------------
__global__ __launch_bounds__(256) void local_gate_hf_kernel(
    const float* __restrict__ Q, const float* __restrict__ Wd,
    const float* __restrict__ bias, const float* __restrict__ G,
    fp16* __restrict__ Oh, fp16* __restrict__ Ol) {
  int idx = blockIdx.x * 256 + threadIdx.x;
  int total = BATCH * DIM * HWX;
  if (idx >= total) return;
  int ox = idx % WW; int t = idx / WW;
  int oy = t % HH; t /= HH;
  int c = t % DIM; int b = t / DIM;
  const float* xp = Q + (size_t)(b * DIM + c) * HWX;
  const float* wp = Wd + c * 25;
  float s = 0.f;
#pragma unroll
  for (int ky = 0; ky < 5; ky++) {
    int iy = oy + ky - 2;
    if (iy < 0 || iy >= HH) continue;
#pragma unroll
    for (int kx = 0; kx < 5; kx++) {
      int ix = ox + kx - 2;
      if (ix < 0 || ix >= WW) continue;
      s += xp[iy * WW + ix] * wp[ky * 5 + kx];
    }
  }
  s += bias[c];
  float lf = s / (1.f + __expf(-s));
  float gv = G[idx];
  float sg = 1.f / (1.f + __expf(-gv));
  float r = lf * sg * gv;
  fp16 hb = __float2half_rn(r);
  Oh[idx] = hb;
  Ol[idx] = __float2half_rn(r - __half2float(hb));
}

extern "C" void kernel_launch(void* const* d_in, const int* in_sizes, int n_in,
                              void* d_out, int out_size) {
  const float* x     = (const float*)d_in[0];
  const float* q_w   = (const float*)d_in[1];
  const float* q_b   = (const float*)d_in[2];
  const float* kv_w  = (const float*)d_in[3];
  const float* kv_b  = (const float*)d_in[4];
  const float* p0_w  = (const float*)d_in[5];
  const float* p0_b  = (const float*)d_in[6];
  const float* bn0_g = (const float*)d_in[7];
  const float* bn0_b = (const float*)d_in[8];
  const float* bn0_m = (const float*)d_in[9];
  const float* bn0_v = (const float*)d_in[10];
  const float* pl0_w = (const float*)d_in[11];
  const float* pl0_b = (const float*)d_in[12];
  const float* p1_w  = (const float*)d_in[13];
  const float* p1_b  = (const float*)d_in[14];
  const float* bn1_g = (const float*)d_in[15];
  const float* bn1_b = (const float*)d_in[16];
  const float* bn1_m = (const float*)d_in[17];
  const float* bn1_v = (const float*)d_in[18];
  const float* loc_w = (const float*)d_in[19];
  const float* loc_b = (const float*)d_in[20];
  const float* mix_w = (const float*)d_in[21];
  const float* mix_b = (const float*)d_in[22];
  float* out = (float*)d_out;

  float *qlocal, *pmid, *gf;
  cudaGetSymbolAddress((void**)&qlocal, g_qlocal);
  cudaGetSymbolAddress((void**)&pmid,   g_pmid);
  cudaGetSymbolAddress((void**)&gf,     g_gf);
  fp16 *xh, *xl, *qh, *ql, *mh, *ml, *p0h, *p0l, *pfh, *pfl, *kvh, *kvl, *wh, *wl;
  cudaGetSymbolAddress((void**)&xh, g_xh);   cudaGetSymbolAddress((void**)&xl, g_xl);
  cudaGetSymbolAddress((void**)&qh, g_qh);   cudaGetSymbolAddress((void**)&ql, g_ql);
  cudaGetSymbolAddress((void**)&mh, g_mh);   cudaGetSymbolAddress((void**)&ml, g_ml);
  cudaGetSymbolAddress((void**)&p0h, g_p0h); cudaGetSymbolAddress((void**)&p0l, g_p0l);
  cudaGetSymbolAddress((void**)&pfh, g_pfh); cudaGetSymbolAddress((void**)&pfl, g_pfl);
  cudaGetSymbolAddress((void**)&kvh, g_kvh); cudaGetSymbolAddress((void**)&kvl, g_kvl);
  cudaGetSymbolAddress((void**)&wh, g_wh);   cudaGetSymbolAddress((void**)&wl, g_wl);

  cudaFuncSetAttribute(conv1x1_hf_kernel, cudaFuncAttributeMaxDynamicSharedMemorySize, CV_SMEM);
  cudaFuncSetAttribute(attn6_kernel, cudaFuncAttributeMaxDynamicSharedMemorySize, A6_BYTES);

  // 0. pre-split weights + x to fp16 hi/lo
  cvt_hl_kernel<<<(NX/4 + 255)/256, 256>>>(x, xh, xl, NX/4);
  cvt_hl_kernel<<<(65536/4 + 255)/256, 256>>>(q_w,   wh + WOFF_Q,   wl + WOFF_Q,   65536/4);
  cvt_hl_kernel<<<(65536/4 + 255)/256, 256>>>(pl0_w, wh + WOFF_PL,  wl + WOFF_PL,  65536/4);
  cvt_hl_kernel<<<(131072/4 + 255)/256, 256>>>(kv_w, wh + WOFF_KV,  wl + WOFF_KV,  131072/4);
  cvt_hl_kernel<<<(65536/4 + 255)/256, 256>>>(mix_w, wh + WOFF_MIX, wl + WOFF_MIX, 65536/4);

  // 1. q_local (f32 + fp16 hi/lo)
  conv1x1_hf_kernel<<<dim3((HWX + 127)/128, DIM/128, BATCH), 256, CV_SMEM>>>(
      wh + WOFF_Q, wl + WOFF_Q, xh, xl, q_b, qlocal, qh, ql, DIM, DIM, HWX);
  // 2. p0 = BN0(dw5x5_s2(x)) -> fp16
  dw_s2_bn_hf_kernel<<<(BATCH*DIM*HW1 + 255)/256, 256>>>(
      x, p0_w, p0_b, bn0_g, bn0_b, bn0_m, bn0_v, p0h, p0l, HH, WW, HP1, HP1);
  // 3. pmid = conv1x1(p0) -> f32
  conv1x1_hf_kernel<<<dim3((HW1 + 127)/128, DIM/128, BATCH), 256, CV_SMEM>>>(
      wh + WOFF_PL, wl + WOFF_PL, p0h, p0l, pl0_b, pmid, (fp16*)nullptr, (fp16*)nullptr, DIM, DIM, HW1);
  // 4. pfin = BN1(dw5x5_s2(pmid)) -> fp16
  dw_s2_bn_hf_kernel<<<(BATCH*DIM*HWP + 255)/256, 256>>>(
      pmid, p1_w, p1_b, bn1_g, bn1_b, bn1_m, bn1_v, pfh, pfl, HP1, HP1, HP2, HP2);
  // 5. kv = conv1x1(pfin) -> fp16 only
  conv1x1_hf_kernel<<<dim3((HWP + 127)/128, (2*DIM)/128, BATCH), 256, CV_SMEM>>>(
      wh + WOFF_KV, wl + WOFF_KV, pfh, pfl, kv_b, (float*)nullptr, kvh, kvl, 2*DIM, DIM, HWP);
  // 6. attention -> gf
  attn6_kernel<<<BATCH*HEADS*7, 128, A6_BYTES>>>(qh, kvh, kvl, gf);
  // 7. local mixer + gating -> fp16 mixbuf
  local_gate_hf_kernel<<<(BATCH*DIM*HWX + 255)/256, 256>>>(qlocal, loc_w, loc_b, gf, mh, ml);
  // 8. out = conv1x1(mixbuf) -> f32
  conv1x1_hf_kernel<<<dim3((HWX + 127)/128, DIM/128, BATCH), 256, CV_SMEM>>>(
      wh + WOFF_MIX, wl + WOFF_MIX, mh, ml, mix_b, out, (fp16*)nullptr, (fp16*)nullptr, DIM, DIM, HWX);
}

// round 10
// speedup vs baseline: 2.8052x; 1.1530x over previous
#include <cuda_runtime.h>
#include <cuda_fp16.h>
#include <cstdint>

#define BATCH 16
#define DIM 256
#define HH 56
#define WW 56
#define HWX (HH*WW)          // 3136
#define HEADS 8
#define DH 32
#define HP1 28
#define HW1 (HP1*HP1)        // 784
#define HP2 14
#define HWP (HP2*HP2)        // 196
#define BN_EPS 1e-5f

#define SW128(x) ((x) ^ (((x) >> 3) & 0x70))

typedef __half fp16;

__device__ __forceinline__ uint32_t smem_u32(const void* p) {
  uint32_t a;
  asm("{ .reg .u64 t; cvta.to.shared.u64 t, %1; cvt.u32.u64 %0, t; }" : "=r"(a) : "l"(p));
  return a;
}
__device__ __forceinline__ void ldmA(uint32_t a[4], uint32_t addr) {
  asm volatile("ldmatrix.sync.aligned.m8n8.x4.shared.b16 {%0,%1,%2,%3}, [%4];"
               : "=r"(a[0]), "=r"(a[1]), "=r"(a[2]), "=r"(a[3]) : "r"(addr));
}
__device__ __forceinline__ void ldmB(uint32_t b[2], uint32_t addr) {
  asm volatile("ldmatrix.sync.aligned.m8n8.x2.shared.b16 {%0,%1}, [%2];"
               : "=r"(b[0]), "=r"(b[1]) : "r"(addr));
}
__device__ __forceinline__ void ldmBT(uint32_t b[2], uint32_t addr) {
  asm volatile("ldmatrix.sync.aligned.m8n8.x2.trans.shared.b16 {%0,%1}, [%2];"
               : "=r"(b[0]), "=r"(b[1]) : "r"(addr));
}
// fp16 inputs, f32 accumulate (hi*hi pass)
__device__ __forceinline__ void mmaF32(float d[4], const uint32_t a[4], const uint32_t b[2]) {
  asm volatile("mma.sync.aligned.m16n8k16.row.col.f32.f16.f16.f32 "
               "{%0,%1,%2,%3}, {%4,%5,%6,%7}, {%8,%9}, {%0,%1,%2,%3};"
               : "+f"(d[0]), "+f"(d[1]), "+f"(d[2]), "+f"(d[3])
               : "r"(a[0]), "r"(a[1]), "r"(a[2]), "r"(a[3]), "r"(b[0]), "r"(b[1]));
}
// fp16 inputs, f16 accumulate (correction pass; values ~2^-11 scale)
__device__ __forceinline__ void mmaF16(uint32_t d[2], const uint32_t a[4], const uint32_t b[2]) {
  asm volatile("mma.sync.aligned.m16n8k16.row.col.f16.f16.f16.f16 "
               "{%0,%1}, {%2,%3,%4,%5}, {%6,%7}, {%0,%1};"
               : "+r"(d[0]), "+r"(d[1])
               : "r"(a[0]), "r"(a[1]), "r"(a[2]), "r"(a[3]), "r"(b[0]), "r"(b[1]));
}
__device__ __forceinline__ uint32_t hpack(float a, float b) {
  __half2 t = __floats2half2_rn(a, b);
  return *(uint32_t*)&t;
}
__device__ __forceinline__ float hlo(uint32_t v) { return __half2float(((__half2*)&v)->x); }
__device__ __forceinline__ float hhi(uint32_t v) { return __half2float(((__half2*)&v)->y); }

// ---------------- scratch (device globals; no allocations allowed) ----------------
__device__ float g_qlocal[BATCH*DIM*HWX];
__device__ float g_pmid[BATCH*DIM*HW1];
__device__ float g_gf[BATCH*DIM*HWX];
#define NX (BATCH*DIM*HWX)
#define NP0 (BATCH*DIM*HW1)
#define NPF (BATCH*DIM*HWP)
#define NKV (BATCH*2*DIM*HWP)
#define WOFF_Q 0
#define WOFF_PL 65536
#define WOFF_KV 131072
#define WOFF_MIX 262144
#define NW 327680
__device__ fp16 g_xh[NX];
__device__ fp16 g_qh[NX],  g_ql[NX];
__device__ fp16 g_mh[NX];
__device__ fp16 g_p0h[NP0];
__device__ fp16 g_pfh[NPF];
__device__ fp16 g_kvh[NKV], g_kvl[NKV];
__device__ fp16 g_wh[NW],  g_wl[NW];

// ---------------- f32 -> fp16 hi/lo split (weights) ----------------
__global__ __launch_bounds__(256) void cvt_hl_kernel(
    const float* __restrict__ s, fp16* __restrict__ h, fp16* __restrict__ l, int n4) {
  int i = blockIdx.x * 256 + threadIdx.x;
  if (i >= n4) return;
  float4 v = ((const float4*)s)[i];
  __half2 h0 = __floats2half2_rn(v.x, v.y);
  __half2 h1 = __floats2half2_rn(v.z, v.w);
  __half2 l0 = __floats2half2_rn(v.x - __half2float(h0.x), v.y - __half2float(h0.y));
  __half2 l1 = __floats2half2_rn(v.z - __half2float(h1.x), v.w - __half2float(h1.y));
  ((__half2*)h)[2*i] = h0; ((__half2*)h)[2*i+1] = h1;
  ((__half2*)l)[2*i] = l0; ((__half2*)l)[2*i+1] = l1;
}
// ---------------- f32 -> fp16 hi only (activations) ----------------
__global__ __launch_bounds__(256) void cvt_h_kernel(
    const float* __restrict__ s, fp16* __restrict__ h, int n4) {
  int i = blockIdx.x * 256 + threadIdx.x;
  if (i >= n4) return;
  float4 v = ((const float4*)s)[i];
  ((__half2*)h)[2*i]   = __floats2half2_rn(v.x, v.y);
  ((__half2*)h)[2*i+1] = __floats2half2_rn(v.z, v.w);
}

// ---------------- 1x1 conv: 2-pass split-fp16 HMMA (Ah.Bh f32acc + Al.Bh f16acc) ----------
// A (weights) hi/lo staged; B (acts) hi ONLY. smem = 48KB -> 4 CTAs/SM.
#define CV_SMEM 49152

__global__ __launch_bounds__(256) void conv1x1_hf_kernel(
    const fp16* __restrict__ Ah, const fp16* __restrict__ Al,
    const fp16* __restrict__ Bh,
    const float* __restrict__ bias, float* __restrict__ Yf,
    fp16* __restrict__ Yh, fp16* __restrict__ Yl,
    int CO, int CI, int HW) {
  extern __shared__ __align__(1024) char smem[];
  char* sAh = smem;         char* sAl = smem + 16384;
  char* sBh = smem + 32768;
  uint32_t aAh = smem_u32(sAh), aAl = smem_u32(sAl);
  uint32_t aBh = smem_u32(sBh);
  int tid = threadIdx.x, lane = tid & 31, wid = tid >> 5;
  int m0 = blockIdx.y * 128, n0 = blockIdx.x * 128;
  const fp16* Bhb = Bh + (size_t)blockIdx.z * CI * HW;
  int mw = (wid & 3) * 32, nw = (wid >> 2) * 64;

  float acc[2][8][4];
  uint32_t accH[2][8][2];
#pragma unroll
  for (int i = 0; i < 2; i++)
#pragma unroll
    for (int j = 0; j < 8; j++) {
#pragma unroll
      for (int c = 0; c < 4; c++) acc[i][j][c] = 0.f;
      accH[i][j][0] = 0u; accH[i][j][1] = 0u;
    }

  for (int k0 = 0; k0 < CI; k0 += 64) {
    // A stage: hi + lo, 16B copies
#pragma unroll
    for (int i = 0; i < 4; i++) {
      int t = tid + i * 256;
      int m = t >> 3, kg = t & 7;
      size_t src = (size_t)(m0 + m) * CI + k0 + kg * 8;
      uint32_t dst = SW128(m * 128 + kg * 16);
      *(uint4*)(sAh + dst) = *(const uint4*)(Ah + src);
      *(uint4*)(sAl + dst) = *(const uint4*)(Al + src);
    }
    // B stage: hi only
#pragma unroll
    for (int i = 0; i < 4; i++) {
      int t = tid + i * 256;
      int k = t & 63, c = t >> 6;
      int gn = n0 + c * 8;
      uint4 vh;
      if (gn + 8 <= HW) {
        const char* ph = (const char*)(Bhb + (size_t)(k0 + k) * HW + gn);
        uint2 h0 = *(const uint2*)ph, h1 = *(const uint2*)(ph + 8);
        vh = make_uint4(h0.x, h0.y, h1.x, h1.y);
      } else {
        fp16 th[8];
#pragma unroll
        for (int j = 0; j < 8; j++) {
          int g = gn + j;
          th[j] = (g < HW) ? Bhb[(size_t)(k0 + k) * HW + g] : __float2half(0.f);
        }
        vh = *(uint4*)th;
      }
      *(uint4*)(sBh + (k * 256 + ((c ^ (k & 15)) << 4))) = vh;
    }
    __syncthreads();
#pragma unroll
    for (int s = 0; s < 4; s++) {
      uint32_t ah[2][4], al[2][4];
#pragma unroll
      for (int tm = 0; tm < 2; tm++) {
        uint32_t off = SW128((mw + tm * 16 + (lane & 15)) * 128 + s * 32 + (lane >> 4) * 16);
        ldmA(ah[tm], aAh + off);
        ldmA(al[tm], aAl + off);
      }
      int l = lane & 15;
      int kk = s * 16 + l;
#pragma unroll
      for (int nt = 0; nt < 8; nt++) {
        uint32_t boff = kk * 256 + ((((nw >> 3) + nt) ^ (kk & 15)) << 4);
        uint32_t bh[2];
        ldmBT(bh, aBh + boff);
#pragma unroll
        for (int tm = 0; tm < 2; tm++) {
          mmaF32(acc[tm][nt], ah[tm], bh);
          mmaF16(accH[tm][nt], al[tm], bh);
        }
      }
    }
    __syncthreads();
  }
  // epilogue: merge accumulators, + bias
#pragma unroll
  for (int tm = 0; tm < 2; tm++) {
    int r0 = m0 + mw + tm * 16 + (lane >> 2);
    float b0 = bias[r0], b1 = bias[r0 + 8];
#pragma unroll
    for (int tn = 0; tn < 8; tn++) {
      int col = n0 + nw + tn * 8 + (lane & 3) * 2;
      if (col < HW) {
        float o0 = acc[tm][tn][0] + hlo(accH[tm][tn][0]) + b0;
        float o1 = acc[tm][tn][1] + hhi(accH[tm][tn][0]) + b0;
        float o2 = acc[tm][tn][2] + hlo(accH[tm][tn][1]) + b1;
        float o3 = acc[tm][tn][3] + hhi(accH[tm][tn][1]) + b1;
        size_t i0 = (size_t)blockIdx.z * CO * HW + (size_t)r0 * HW + col;
        size_t i1 = i0 + (size_t)8 * HW;
        if (Yf) {
          *(float2*)&Yf[i0] = make_float2(o0, o1);
          *(float2*)&Yf[i1] = make_float2(o2, o3);
        }
        if (Yh) {
          __half2 h0 = __floats2half2_rn(o0, o1);
          __half2 h1 = __floats2half2_rn(o2, o3);
          *(__half2*)&Yh[i0] = h0; *(__half2*)&Yh[i1] = h1;
          if (Yl) {
            __half2 l0 = __floats2half2_rn(o0 - __half2float(h0.x), o1 - __half2float(h0.y));
            __half2 l1 = __floats2half2_rn(o2 - __half2float(h1.x), o3 - __half2float(h1.y));
            *(__half2*)&Yl[i0] = l0; *(__half2*)&Yl[i1] = l1;
          }
        }
      }
    }
  }
}

// ---------------- depthwise 5x5 stride2 pad2 + BatchNorm -> fp16 hi ----------------
__global__ __launch_bounds__(256) void dw_s2_bn_hf_kernel(
    const float* __restrict__ X, const float* __restrict__ Wd,
    const float* __restrict__ bias, const float* __restrict__ gam,
    const float* __restrict__ bet, const float* __restrict__ mu,
    const float* __restrict__ var, fp16* __restrict__ Yh,
    int Hin, int Win, int Hout, int Wout) {
  int idx = blockIdx.x * 256 + threadIdx.x;
  int total = BATCH * DIM * Hout * Wout;
  if (idx >= total) return;
  int ox = idx % Wout; int t = idx / Wout;
  int oy = t % Hout; t /= Hout;
  int c = t % DIM; int b = t / DIM;
  const float* xp = X + (size_t)(b * DIM + c) * Hin * Win;
  const float* wp = Wd + c * 25;
  float s = 0.f;
#pragma unroll
  for (int ky = 0; ky < 5; ky++) {
    int iy = oy * 2 - 2 + ky;
    if (iy < 0 || iy >= Hin) continue;
#pragma unroll
    for (int kx = 0; kx < 5; kx++) {
      int ix = ox * 2 - 2 + kx;
      if (ix < 0 || ix >= Win) continue;
      s += xp[iy * Win + ix] * wp[ky * 5 + kx];
    }
  }
  s += bias[c];
  float sc = gam[c] * rsqrtf(var[c] + BN_EPS);
  float r = (s - mu[c]) * sc + bet[c];
  Yh[idx] = __float2half_rn(r);
}

// ---------------- attention v6: 2-pass QK, 2-pass PV (unchanged from R9) ----------------
#define A6_AQH 0
#define A6_KH  8704
#define A6_KL  26624
#define A6_VH  44544
#define A6_VL  59392
#define A6_BYTES 74240

__global__ __launch_bounds__(128, 2) void attn6_kernel(
    const fp16* __restrict__ Qh,
    const fp16* __restrict__ KVh, const fp16* __restrict__ KVl,
    float* __restrict__ GF) {
  extern __shared__ __align__(1024) char sm[];
  uint32_t sb = smem_u32(sm);
  int tid = threadIdx.x, lane = tid & 31, warp = tid >> 5;
  int part = blockIdx.x % 7;
  int bh = blockIdx.x / 7;
  int b = bh >> 3, h = bh & 7;
  const fp16* kHh = KVh + ((size_t)b * 2 * DIM + h * 32) * HWP;
  const fp16* kHl = KVl + ((size_t)b * 2 * DIM + h * 32) * HWP;
  const fp16* vHh = kHh + (size_t)DIM * HWP;
  const fp16* vHl = kHl + (size_t)DIM * HWP;
  const float scal = 0.17677669529663687f;  // 32^-0.5

  for (int t = tid; t < 896; t += 128) {
    int d = t & 31, jg = t >> 5;
    int j0 = jg * 8;
    fp16 th[8], tl[8], uh[8], ul[8];
    if (j0 + 8 <= HWP) {
      const char* pkh = (const char*)(kHh + (size_t)d * HWP + j0);
      const char* pkl = (const char*)(kHl + (size_t)d * HWP + j0);
      const char* pvh = (const char*)(vHh + (size_t)d * HWP + j0);
      const char* pvl = (const char*)(vHl + (size_t)d * HWP + j0);
      *(uint2*)th = *(const uint2*)pkh; *(uint2*)(th + 4) = *(const uint2*)(pkh + 8);
      *(uint2*)tl = *(const uint2*)pkl; *(uint2*)(tl + 4) = *(const uint2*)(pkl + 8);
      *(uint2*)uh = *(const uint2*)pvh; *(uint2*)(uh + 4) = *(const uint2*)(pvh + 8);
      *(uint2*)ul = *(const uint2*)pvl; *(uint2*)(ul + 4) = *(const uint2*)(pvl + 8);
    } else {
      fp16 z = __float2half(0.f);
#pragma unroll
      for (int j = 0; j < 8; j++) {
        int g = j0 + j;
        bool v = g < HWP;
        th[j] = v ? kHh[(size_t)d * HWP + g] : z;
        tl[j] = v ? kHl[(size_t)d * HWP + g] : z;
        uh[j] = v ? vHh[(size_t)d * HWP + g] : z;
        ul[j] = v ? vHl[(size_t)d * HWP + g] : z;
      }
    }
#pragma unroll
    for (int j = 0; j < 8; j++) {
      *(fp16*)(sm + A6_KH + ((j0 + j) * 40 + d) * 2) = th[j];
      *(fp16*)(sm + A6_KL + ((j0 + j) * 40 + d) * 2) = tl[j];
    }
    *(uint4*)(sm + A6_VH + (d * 232 + j0) * 2) = *(uint4*)uh;
    *(uint4*)(sm + A6_VL + (d * 232 + j0) * 2) = *(uint4*)ul;
  }

  const fp16* qbh = Qh + ((size_t)b * DIM + h * 32) * HWX;
  float* GFb = GF + ((size_t)b * DIM + h * 32) * HWX;
  int mw = warp * 16;

  for (int it = 0; it < 7; it++) {
    int q0 = (part * 7 + it) * 64;
    __syncthreads();
    for (int t = tid; t < 256; t += 128) {
      int d = t & 31, mg = t >> 5;
      uint4 vh = *(const uint4*)(qbh + (size_t)d * HWX + q0 + mg * 8);
      fp16* eh = (fp16*)&vh;
#pragma unroll
      for (int j = 0; j < 8; j++)
        *(fp16*)(sm + A6_AQH + ((mg * 8 + j) * 40 + d) * 2) = eh[j];
    }
    __syncthreads();

    float acc[26][4];
    uint32_t accH[26][2];
#pragma unroll
    for (int nt = 0; nt < 26; nt++) {
#pragma unroll
      for (int c = 0; c < 4; c++) acc[nt][c] = 0.f;
      accH[nt][0] = 0u; accH[nt][1] = 0u;
    }
#pragma unroll
    for (int s = 0; s < 2; s++) {
      uint32_t ah[4];
      uint32_t aoff = ((mw + (lane & 15)) * 40 + s * 16) * 2 + (lane >> 4) * 16;
      ldmA(ah, sb + A6_AQH + aoff);
      int l = lane & 15;
#pragma unroll
      for (int nt = 0; nt < 26; nt++) {
        uint32_t bh[2], bl[2];
        uint32_t boff = ((nt * 8 + (l & 7)) * 40 + s * 16) * 2 + ((l >> 3) & 1) * 16;
        ldmB(bh, sb + A6_KH + boff);
        ldmB(bl, sb + A6_KL + boff);
        mmaF32(acc[nt], ah, bh);
        mmaF16(accH[nt], ah, bl);
      }
    }

    float mx1 = -1e30f, mx2 = -1e30f;
#pragma unroll
    for (int nt = 0; nt < 26; nt++) {
      int jb = nt * 8 + (lane & 3) * 2;
      acc[nt][0] = (acc[nt][0] + hlo(accH[nt][0])) * scal;
      acc[nt][1] = (acc[nt][1] + hhi(accH[nt][0])) * scal;
      acc[nt][2] = (acc[nt][2] + hlo(accH[nt][1])) * scal;
      acc[nt][3] = (acc[nt][3] + hhi(accH[nt][1])) * scal;
      if (jb >= HWP)     { acc[nt][0] = -1e30f; acc[nt][2] = -1e30f; }
      if (jb + 1 >= HWP) { acc[nt][1] = -1e30f; acc[nt][3] = -1e30f; }
      mx1 = fmaxf(mx1, fmaxf(acc[nt][0], acc[nt][1]));
      mx2 = fmaxf(mx2, fmaxf(acc[nt][2], acc[nt][3]));
    }
#pragma unroll
    for (int o = 1; o <= 2; o <<= 1) {
      mx1 = fmaxf(mx1, __shfl_xor_sync(0xffffffffu, mx1, o));
      mx2 = fmaxf(mx2, __shfl_xor_sync(0xffffffffu, mx2, o));
    }
    float sum1 = 0.f, sum2 = 0.f;
#pragma unroll
    for (int nt = 0; nt < 26; nt++) {
      acc[nt][0] = __expf(acc[nt][0] - mx1);
      acc[nt][1] = __expf(acc[nt][1] - mx1);
      acc[nt][2] = __expf(acc[nt][2] - mx2);
      acc[nt][3] = __expf(acc[nt][3] - mx2);
      sum1 += acc[nt][0] + acc[nt][1];
      sum2 += acc[nt][2] + acc[nt][3];
    }
#pragma unroll
    for (int o = 1; o <= 2; o <<= 1) {
      sum1 += __shfl_xor_sync(0xffffffffu, sum1, o);
      sum2 += __shfl_xor_sync(0xffffffffu, sum2, o);
    }
    float rec1 = 1.f / sum1, rec2 = 1.f / sum2;

    float acc2[4][4];
    uint32_t acc2H[4][2];
#pragma unroll
    for (int nt = 0; nt < 4; nt++) {
#pragma unroll
      for (int c = 0; c < 4; c++) acc2[nt][c] = 0.f;
      acc2H[nt][0] = 0u; acc2H[nt][1] = 0u;
    }
#pragma unroll 1
    for (int k = 0; k < 13; k++) {
      uint32_t ph[4];
      ph[0] = hpack(acc[2*k][0] * rec1,   acc[2*k][1] * rec1);
      ph[1] = hpack(acc[2*k][2] * rec2,   acc[2*k][3] * rec2);
      ph[2] = hpack(acc[2*k+1][0] * rec1, acc[2*k+1][1] * rec1);
      ph[3] = hpack(acc[2*k+1][2] * rec2, acc[2*k+1][3] * rec2);
      int l = lane & 15;
#pragma unroll
      for (int nt = 0; nt < 4; nt++) {
        uint32_t vh[2], vl[2];
        uint32_t boff = ((nt * 8 + (l & 7)) * 232 + k * 16) * 2 + ((l >> 3) & 1) * 16;
        ldmB(vh, sb + A6_VH + boff);
        ldmB(vl, sb + A6_VL + boff);
        mmaF32(acc2[nt], ph, vh);
        mmaF16(acc2H[nt], ph, vl);
      }
    }
    __syncthreads();

    float* Ob = (float*)sm;
    {
      int m1 = mw + (lane >> 2), m2 = m1 + 8;
      int cb = (lane & 3) * 2;
#pragma unroll
      for (int nt = 0; nt < 4; nt++) {
        int dcol = nt * 8 + cb;
        Ob[dcol * 68 + m1]       = acc2[nt][0] + hlo(acc2H[nt][0]);
        Ob[(dcol + 1) * 68 + m1] = acc2[nt][1] + hhi(acc2H[nt][0]);
        Ob[dcol * 68 + m2]       = acc2[nt][2] + hlo(acc2H[nt][1]);
        Ob[(dcol + 1) * 68 + m2] = acc2[nt][3] + hhi(acc2H[nt][1]);
      }
    }
    __syncthreads();
    {
      int row = tid >> 2, i0 = (tid & 3) * 16;
#pragma unroll
      for (int c = 0; c < 4; c++) {
        int i = i0 + c * 4;
        *(float4*)&GFb[(size_t)row * HWX + q0 + i] = *(float4*)&Ob[row * 68 + i];
      }
    }
  }
}

// ---------------- local mixer -> fp16 hi mixbuf ----------------
__global__ __launch_bounds__(256) void local_gate_hf_kernel(
    const float* __restrict__ Q, const float* __restrict__ Wd,
    const float* __restrict__ bias, const float* __restrict__ G,
    fp16* __restrict__ Oh) {
  int idx = blockIdx.x * 256 + threadIdx.x;
  int total = BATCH * DIM * HWX;
  if (idx >= total) return;
  int ox = idx % WW; int t = idx / WW;
  int oy = t % HH; t /= HH;
  int c = t % DIM; int b = t / DIM;
  const float* xp = Q + (size_t)(b * DIM + c) * HWX;
  const float* wp = Wd + c * 25;
  float s = 0.f;
#pragma unroll
  for (int ky = 0; ky < 5; ky++) {
    int iy = oy + ky - 2;
    if (iy < 0 || iy >= HH) continue;
#pragma unroll
    for (int kx = 0; kx < 5; kx++) {
      int ix = ox + kx - 2;
      if (ix < 0 || ix >= WW) continue;
      s += xp[iy * WW + ix] * wp[ky * 5 + kx];
    }
  }
  s += bias[c];
  float lf = s / (1.f + __expf(-s));
  float gv = G[idx];
  float sg = 1.f / (1.f + __expf(-gv));
  Oh[idx] = __float2half_rn(lf * sg * gv);
}

extern "C" void kernel_launch(void* const* d_in, const int* in_sizes, int n_in,
                              void* d_out, int out_size) {
  const float* x     = (const float*)d_in[0];
  const float* q_w   = (const float*)d_in[1];
  const float* q_b   = (const float*)d_in[2];
  const float* kv_w  = (const float*)d_in[3];
  const float* kv_b  = (const float*)d_in[4];
  const float* p0_w  = (const float*)d_in[5];
  const float* p0_b  = (const float*)d_in[6];
  const float* bn0_g = (const float*)d_in[7];
  const float* bn0_b = (const float*)d_in[8];
  const float* bn0_m = (const float*)d_in[9];
  const float* bn0_v = (const float*)d_in[10];
  const float* pl0_w = (const float*)d_in[11];
  const float* pl0_b = (const float*)d_in[12];
  const float* p1_w  = (const float*)d_in[13];
  const float* p1_b  = (const float*)d_in[14];
  const float* bn1_g = (const float*)d_in[15];
  const float* bn1_b = (const float*)d_in[16];
  const float* bn1_m = (const float*)d_in[17];
  const float* bn1_v = (const float*)d_in[18];
  const float* loc_w = (const float*)d_in[19];
  const float* loc_b = (const float*)d_in[20];
  const float* mix_w = (const float*)d_in[21];
  const float* mix_b = (const float*)d_in[22];
  float* out = (float*)d_out;

  float *qlocal, *pmid, *gf;
  cudaGetSymbolAddress((void**)&qlocal, g_qlocal);
  cudaGetSymbolAddress((void**)&pmid,   g_pmid);
  cudaGetSymbolAddress((void**)&gf,     g_gf);
  fp16 *xh, *qh, *ql, *mh, *p0h, *pfh, *kvh, *kvl, *wh, *wl;
  cudaGetSymbolAddress((void**)&xh, g_xh);
  cudaGetSymbolAddress((void**)&qh, g_qh);   cudaGetSymbolAddress((void**)&ql, g_ql);
  cudaGetSymbolAddress((void**)&mh, g_mh);
  cudaGetSymbolAddress((void**)&p0h, g_p0h);
  cudaGetSymbolAddress((void**)&pfh, g_pfh);
  cudaGetSymbolAddress((void**)&kvh, g_kvh); cudaGetSymbolAddress((void**)&kvl, g_kvl);
  cudaGetSymbolAddress((void**)&wh, g_wh);   cudaGetSymbolAddress((void**)&wl, g_wl);

  cudaFuncSetAttribute(conv1x1_hf_kernel, cudaFuncAttributeMaxDynamicSharedMemorySize, CV_SMEM);
  cudaFuncSetAttribute(attn6_kernel, cudaFuncAttributeMaxDynamicSharedMemorySize, A6_BYTES);

  // 0. pre-split: weights hi/lo; x hi only
  cvt_h_kernel<<<(NX/4 + 255)/256, 256>>>(x, xh, NX/4);
  cvt_hl_kernel<<<(65536/4 + 255)/256, 256>>>(q_w,   wh + WOFF_Q,   wl + WOFF_Q,   65536/4);
  cvt_hl_kernel<<<(65536/4 + 255)/256, 256>>>(pl0_w, wh + WOFF_PL,  wl + WOFF_PL,  65536/4);
  cvt_hl_kernel<<<(131072/4 + 255)/256, 256>>>(kv_w, wh + WOFF_KV,  wl + WOFF_KV,  131072/4);
  cvt_hl_kernel<<<(65536/4 + 255)/256, 256>>>(mix_w, wh + WOFF_MIX, wl + WOFF_MIX, 65536/4);

  // 1. q_local (f32 + fp16 hi for attention Q)
  conv1x1_hf_kernel<<<dim3((HWX + 127)/128, DIM/128, BATCH), 256, CV_SMEM>>>(
      wh + WOFF_Q, wl + WOFF_Q, xh, q_b, qlocal, qh, (fp16*)nullptr, DIM, DIM, HWX);
  // 2. p0 = BN0(dw5x5_s2(x)) -> fp16 hi
  dw_s2_bn_hf_kernel<<<(BATCH*DIM*HW1 + 255)/256, 256>>>(
      x, p0_w, p0_b, bn0_g, bn0_b, bn0_m, bn0_v, p0h, HH, WW, HP1, HP1);
  // 3. pmid = conv1x1(p0) -> f32
  conv1x1_hf_kernel<<<dim3((HW1 + 127)/128, DIM/128, BATCH), 256, CV_SMEM>>>(
      wh + WOFF_PL, wl + WOFF_PL, p0h, pl0_b, pmid, (fp16*)nullptr, (fp16*)nullptr, DIM, DIM, HW1);
  // 4. pfin = BN1(dw5x5_s2(pmid)) -> fp16 hi
  dw_s2_bn_hf_kernel<<<(BATCH*DIM*HWP + 255)/256, 256>>>(
      pmid, p1_w, p1_b, bn1_g, bn1_b, bn1_m, bn1_v, pfh, HP1, HP1, HP2, HP2);
  // 5. kv = conv1x1(pfin) -> fp16 hi/lo (attention K/V keep full split)
  conv1x1_hf_kernel<<<dim3((HWP + 127)/128, (2*DIM)/128, BATCH), 256, CV_SMEM>>>(
      wh + WOFF_KV, wl + WOFF_KV, pfh, kv_b, (float*)nullptr, kvh, kvl, 2*DIM, DIM, HWP);
  // 6. attention -> gf
  attn6_kernel<<<BATCH*HEADS*7, 128, A6_BYTES>>>(qh, kvh, kvl, gf);
  // 7. local mixer + gating -> fp16 hi mixbuf
  local_gate_hf_kernel<<<(BATCH*DIM*HWX + 255)/256, 256>>>(qlocal, loc_w, loc_b, gf, mh);
  // 8. out = conv1x1(mixbuf) -> f32
  conv1x1_hf_kernel<<<dim3((HWX + 127)/128, DIM/128, BATCH), 256, CV_SMEM>>>(
      wh + WOFF_MIX, wl + WOFF_MIX, mh, mix_b, out, (fp16*)nullptr, (fp16*)nullptr, DIM, DIM, HWX);
}

// round 11
// speedup vs baseline: 3.2067x; 1.1431x over previous
#include <cuda_runtime.h>
#include <cuda_fp16.h>
#include <cstdint>

#define BATCH 16
#define DIM 256
#define HH 56
#define WW 56
#define HWX (HH*WW)          // 3136
#define HEADS 8
#define DH 32
#define HP1 28
#define HW1 (HP1*HP1)        // 784
#define HP2 14
#define HWP (HP2*HP2)        // 196
#define BN_EPS 1e-5f

#define SW128(x) ((x) ^ (((x) >> 3) & 0x70))

typedef __half fp16;

__device__ __forceinline__ uint32_t smem_u32(const void* p) {
  uint32_t a;
  asm("{ .reg .u64 t; cvta.to.shared.u64 t, %1; cvt.u32.u64 %0, t; }" : "=r"(a) : "l"(p));
  return a;
}
__device__ __forceinline__ void ldm4(uint32_t a[4], uint32_t addr) {
  asm volatile("ldmatrix.sync.aligned.m8n8.x4.shared.b16 {%0,%1,%2,%3}, [%4];"
               : "=r"(a[0]), "=r"(a[1]), "=r"(a[2]), "=r"(a[3]) : "r"(addr));
}
__device__ __forceinline__ void ldm4t(uint32_t a[4], uint32_t addr) {
  asm volatile("ldmatrix.sync.aligned.m8n8.x4.trans.shared.b16 {%0,%1,%2,%3}, [%4];"
               : "=r"(a[0]), "=r"(a[1]), "=r"(a[2]), "=r"(a[3]) : "r"(addr));
}
// fp16 inputs, f32 accumulate (hi*hi pass)
__device__ __forceinline__ void mmaF32(float d[4], const uint32_t a[4], const uint32_t b[2]) {
  asm volatile("mma.sync.aligned.m16n8k16.row.col.f32.f16.f16.f32 "
               "{%0,%1,%2,%3}, {%4,%5,%6,%7}, {%8,%9}, {%0,%1,%2,%3};"
               : "+f"(d[0]), "+f"(d[1]), "+f"(d[2]), "+f"(d[3])
               : "r"(a[0]), "r"(a[1]), "r"(a[2]), "r"(a[3]), "r"(b[0]), "r"(b[1]));
}
// fp16 inputs, f16 accumulate (correction pass; values ~2^-11 scale)
__device__ __forceinline__ void mmaF16(uint32_t d[2], const uint32_t a[4], const uint32_t b[2]) {
  asm volatile("mma.sync.aligned.m16n8k16.row.col.f16.f16.f16.f16 "
               "{%0,%1}, {%2,%3,%4,%5}, {%6,%7}, {%0,%1};"
               : "+r"(d[0]), "+r"(d[1])
               : "r"(a[0]), "r"(a[1]), "r"(a[2]), "r"(a[3]), "r"(b[0]), "r"(b[1]));
}
__device__ __forceinline__ uint32_t hpack(float a, float b) {
  __half2 t = __floats2half2_rn(a, b);
  return *(uint32_t*)&t;
}
__device__ __forceinline__ float hlo(uint32_t v) { return __half2float(((__half2*)&v)->x); }
__device__ __forceinline__ float hhi(uint32_t v) { return __half2float(((__half2*)&v)->y); }

// ---------------- scratch (device globals; no allocations allowed) ----------------
__device__ float g_qlocal[BATCH*DIM*HWX];
__device__ float g_pmid[BATCH*DIM*HW1];
__device__ float g_gf[BATCH*DIM*HWX];
#define NX (BATCH*DIM*HWX)
#define NP0 (BATCH*DIM*HW1)
#define NPF (BATCH*DIM*HWP)
#define NKV (BATCH*2*DIM*HWP)
#define WOFF_Q 0
#define WOFF_PL 65536
#define WOFF_KV 131072
#define WOFF_MIX 262144
#define NW 327680
__device__ fp16 g_xh[NX];
__device__ fp16 g_qh[NX];
__device__ fp16 g_mh[NX];
__device__ fp16 g_p0h[NP0];
__device__ fp16 g_pfh[NPF];
__device__ fp16 g_kvh[NKV], g_kvl[NKV];
__device__ fp16 g_wh[NW],  g_wl[NW];

// ---------------- f32 -> fp16 hi/lo split (weights) ----------------
__global__ __launch_bounds__(256) void cvt_hl_kernel(
    const float* __restrict__ s, fp16* __restrict__ h, fp16* __restrict__ l, int n4) {
  int i = blockIdx.x * 256 + threadIdx.x;
  if (i >= n4) return;
  float4 v = ((const float4*)s)[i];
  __half2 h0 = __floats2half2_rn(v.x, v.y);
  __half2 h1 = __floats2half2_rn(v.z, v.w);
  __half2 l0 = __floats2half2_rn(v.x - __half2float(h0.x), v.y - __half2float(h0.y));
  __half2 l1 = __floats2half2_rn(v.z - __half2float(h1.x), v.w - __half2float(h1.y));
  ((__half2*)h)[2*i] = h0; ((__half2*)h)[2*i+1] = h1;
  ((__half2*)l)[2*i] = l0; ((__half2*)l)[2*i+1] = l1;
}
// ---------------- f32 -> fp16 hi only (activations) ----------------
__global__ __launch_bounds__(256) void cvt_h_kernel(
    const float* __restrict__ s, fp16* __restrict__ h, int n4) {
  int i = blockIdx.x * 256 + threadIdx.x;
  if (i >= n4) return;
  float4 v = ((const float4*)s)[i];
  ((__half2*)h)[2*i]   = __floats2half2_rn(v.x, v.y);
  ((__half2*)h)[2*i+1] = __floats2half2_rn(v.z, v.w);
}

// ---------------- 1x1 conv: 2-pass split-fp16 HMMA, x4-trans B loads ----------------
#define CV_SMEM 49152

__global__ __launch_bounds__(256) void conv1x1_hf_kernel(
    const fp16* __restrict__ Ah, const fp16* __restrict__ Al,
    const fp16* __restrict__ Bh,
    const float* __restrict__ bias, float* __restrict__ Yf,
    fp16* __restrict__ Yh, fp16* __restrict__ Yl,
    int CO, int CI, int HW) {
  extern __shared__ __align__(1024) char smem[];
  char* sAh = smem;         char* sAl = smem + 16384;
  char* sBh = smem + 32768;
  uint32_t aAh = smem_u32(sAh), aAl = smem_u32(sAl);
  uint32_t aBh = smem_u32(sBh);
  int tid = threadIdx.x, lane = tid & 31, wid = tid >> 5;
  int m0 = blockIdx.y * 128, n0 = blockIdx.x * 128;
  const fp16* Bhb = Bh + (size_t)blockIdx.z * CI * HW;
  int mw = (wid & 3) * 32, nw = (wid >> 2) * 64;

  float acc[2][8][4];
  uint32_t accH[2][8][2];
#pragma unroll
  for (int i = 0; i < 2; i++)
#pragma unroll
    for (int j = 0; j < 8; j++) {
#pragma unroll
      for (int c = 0; c < 4; c++) acc[i][j][c] = 0.f;
      accH[i][j][0] = 0u; accH[i][j][1] = 0u;
    }

  for (int k0 = 0; k0 < CI; k0 += 64) {
#pragma unroll
    for (int i = 0; i < 4; i++) {
      int t = tid + i * 256;
      int m = t >> 3, kg = t & 7;
      size_t src = (size_t)(m0 + m) * CI + k0 + kg * 8;
      uint32_t dst = SW128(m * 128 + kg * 16);
      *(uint4*)(sAh + dst) = *(const uint4*)(Ah + src);
      *(uint4*)(sAl + dst) = *(const uint4*)(Al + src);
    }
#pragma unroll
    for (int i = 0; i < 4; i++) {
      int t = tid + i * 256;
      int k = t & 63, c = t >> 6;
      int gn = n0 + c * 8;
      uint4 vh;
      if (gn + 8 <= HW) {
        const char* ph = (const char*)(Bhb + (size_t)(k0 + k) * HW + gn);
        uint2 h0 = *(const uint2*)ph, h1 = *(const uint2*)(ph + 8);
        vh = make_uint4(h0.x, h0.y, h1.x, h1.y);
      } else {
        fp16 th[8];
#pragma unroll
        for (int j = 0; j < 8; j++) {
          int g = gn + j;
          th[j] = (g < HW) ? Bhb[(size_t)(k0 + k) * HW + g] : __float2half(0.f);
        }
        vh = *(uint4*)th;
      }
      *(uint4*)(sBh + (k * 256 + ((c ^ (k & 15)) << 4))) = vh;
    }
    __syncthreads();
#pragma unroll
    for (int s = 0; s < 4; s++) {
      uint32_t ah[2][4], al[2][4];
#pragma unroll
      for (int tm = 0; tm < 2; tm++) {
        uint32_t off = SW128((mw + tm * 16 + (lane & 15)) * 128 + s * 32 + (lane >> 4) * 16);
        ldm4(ah[tm], aAh + off);
        ldm4(al[tm], aAl + off);
      }
      int kk = s * 16 + (lane & 15);
#pragma unroll
      for (int ntp = 0; ntp < 4; ntp++) {
        int nt_eff = 2 * ntp + (lane >> 4);
        uint32_t cIdx = (uint32_t)(((nw >> 3) + nt_eff) ^ (kk & 15));
        uint32_t bq[4];
        ldm4t(bq, aBh + kk * 256 + (cIdx << 4));
#pragma unroll
        for (int tm = 0; tm < 2; tm++) {
          mmaF32(acc[tm][2*ntp],   ah[tm], bq);
          mmaF16(accH[tm][2*ntp],  al[tm], bq);
          mmaF32(acc[tm][2*ntp+1], ah[tm], bq + 2);
          mmaF16(accH[tm][2*ntp+1],al[tm], bq + 2);
        }
      }
    }
    __syncthreads();
  }
  // epilogue
#pragma unroll
  for (int tm = 0; tm < 2; tm++) {
    int r0 = m0 + mw + tm * 16 + (lane >> 2);
    float b0 = bias[r0], b1 = bias[r0 + 8];
#pragma unroll
    for (int tn = 0; tn < 8; tn++) {
      int col = n0 + nw + tn * 8 + (lane & 3) * 2;
      if (col < HW) {
        float o0 = acc[tm][tn][0] + hlo(accH[tm][tn][0]) + b0;
        float o1 = acc[tm][tn][1] + hhi(accH[tm][tn][0]) + b0;
        float o2 = acc[tm][tn][2] + hlo(accH[tm][tn][1]) + b1;
        float o3 = acc[tm][tn][3] + hhi(accH[tm][tn][1]) + b1;
        size_t i0 = (size_t)blockIdx.z * CO * HW + (size_t)r0 * HW + col;
        size_t i1 = i0 + (size_t)8 * HW;
        if (Yf) {
          *(float2*)&Yf[i0] = make_float2(o0, o1);
          *(float2*)&Yf[i1] = make_float2(o2, o3);
        }
        if (Yh) {
          __half2 h0 = __floats2half2_rn(o0, o1);
          __half2 h1 = __floats2half2_rn(o2, o3);
          *(__half2*)&Yh[i0] = h0; *(__half2*)&Yh[i1] = h1;
          if (Yl) {
            __half2 l0 = __floats2half2_rn(o0 - __half2float(h0.x), o1 - __half2float(h0.y));
            __half2 l1 = __floats2half2_rn(o2 - __half2float(h1.x), o3 - __half2float(h1.y));
            *(__half2*)&Yl[i0] = l0; *(__half2*)&Yl[i1] = l1;
          }
        }
      }
    }
  }
}

// ---------------- depthwise 5x5 stride2 + BN -> fp16 hi, 4-wide outputs ----------------
__global__ __launch_bounds__(256) void dw_s2_bn_hf4_kernel(
    const float* __restrict__ X, const float* __restrict__ Wd,
    const float* __restrict__ bias, const float* __restrict__ gam,
    const float* __restrict__ bet, const float* __restrict__ mu,
    const float* __restrict__ var, fp16* __restrict__ Yh,
    int Hin, int Win, int Hout, int Wout, int gpr) {
  int idx = blockIdx.x * 256 + threadIdx.x;
  int total = BATCH * DIM * Hout * gpr;
  if (idx >= total) return;
  int gx = idx % gpr; int t = idx / gpr;
  int oy = t % Hout; t /= Hout;
  int c = t % DIM; int b = t / DIM;
  int ox0 = gx * 4;
  const float* xp = X + (size_t)(b * DIM + c) * Hin * Win;
  const float* wp = Wd + c * 25;
  float sums[4] = {0.f, 0.f, 0.f, 0.f};
#pragma unroll
  for (int ky = 0; ky < 5; ky++) {
    int iy = oy * 2 - 2 + ky;
    if (iy < 0 || iy >= Hin) continue;
    const float* row = xp + iy * Win;
    int ix0 = ox0 * 2 - 2;
    float rv[11];
#pragma unroll
    for (int j = 0; j < 11; j++) {
      int ix = ix0 + j;
      rv[j] = (ix >= 0 && ix < Win) ? row[ix] : 0.f;
    }
#pragma unroll
    for (int kx = 0; kx < 5; kx++) {
      float w = wp[ky * 5 + kx];
      sums[0] += rv[kx] * w;
      sums[1] += rv[2 + kx] * w;
      sums[2] += rv[4 + kx] * w;
      sums[3] += rv[6 + kx] * w;
    }
  }
  float bsv = bias[c];
  float sc = gam[c] * rsqrtf(var[c] + BN_EPS);
  float muv = mu[c], bev = bet[c];
  size_t ob = ((size_t)(b * DIM + c) * Hout + oy) * Wout + ox0;
#pragma unroll
  for (int o = 0; o < 4; o++) {
    if (ox0 + o < Wout)
      Yh[ob + o] = __float2half_rn((sums[o] + bsv - muv) * sc + bev);
  }
}

// ---------------- attention v7: x4 B-loads, no max-pass ----------------
#define A6_AQH 0
#define A6_KH  8704
#define A6_KL  26624
#define A6_VH  44544
#define A6_VL  59392
#define A6_BYTES 74240

__global__ __launch_bounds__(128, 2) void attn7_kernel(
    const fp16* __restrict__ Qh,
    const fp16* __restrict__ KVh, const fp16* __restrict__ KVl,
    float* __restrict__ GF) {
  extern __shared__ __align__(1024) char sm[];
  uint32_t sb = smem_u32(sm);
  int tid = threadIdx.x, lane = tid & 31, warp = tid >> 5;
  int part = blockIdx.x % 7;
  int bh = blockIdx.x / 7;
  int b = bh >> 3, h = bh & 7;
  const fp16* kHh = KVh + ((size_t)b * 2 * DIM + h * 32) * HWP;
  const fp16* kHl = KVl + ((size_t)b * 2 * DIM + h * 32) * HWP;
  const fp16* vHh = kHh + (size_t)DIM * HWP;
  const fp16* vHl = kHl + (size_t)DIM * HWP;
  const float scal = 0.17677669529663687f;  // 32^-0.5

  for (int t = tid; t < 896; t += 128) {
    int d = t & 31, jg = t >> 5;
    int j0 = jg * 8;
    fp16 th[8], tl[8], uh[8], ul[8];
    if (j0 + 8 <= HWP) {
      const char* pkh = (const char*)(kHh + (size_t)d * HWP + j0);
      const char* pkl = (const char*)(kHl + (size_t)d * HWP + j0);
      const char* pvh = (const char*)(vHh + (size_t)d * HWP + j0);
      const char* pvl = (const char*)(vHl + (size_t)d * HWP + j0);
      *(uint2*)th = *(const uint2*)pkh; *(uint2*)(th + 4) = *(const uint2*)(pkh + 8);
      *(uint2*)tl = *(const uint2*)pkl; *(uint2*)(tl + 4) = *(const uint2*)(pkl + 8);
      *(uint2*)uh = *(const uint2*)pvh; *(uint2*)(uh + 4) = *(const uint2*)(pvh + 8);
      *(uint2*)ul = *(const uint2*)pvl; *(uint2*)(ul + 4) = *(const uint2*)(pvl + 8);
    } else {
      fp16 z = __float2half(0.f);
#pragma unroll
      for (int j = 0; j < 8; j++) {
        int g = j0 + j;
        bool v = g < HWP;
        th[j] = v ? kHh[(size_t)d * HWP + g] : z;
        tl[j] = v ? kHl[(size_t)d * HWP + g] : z;
        uh[j] = v ? vHh[(size_t)d * HWP + g] : z;
        ul[j] = v ? vHl[(size_t)d * HWP + g] : z;
      }
    }
#pragma unroll
    for (int j = 0; j < 8; j++) {
      *(fp16*)(sm + A6_KH + ((j0 + j) * 40 + d) * 2) = th[j];
      *(fp16*)(sm + A6_KL + ((j0 + j) * 40 + d) * 2) = tl[j];
    }
    *(uint4*)(sm + A6_VH + (d * 232 + j0) * 2) = *(uint4*)uh;
    *(uint4*)(sm + A6_VL + (d * 232 + j0) * 2) = *(uint4*)ul;
  }

  const fp16* qbh = Qh + ((size_t)b * DIM + h * 32) * HWX;
  float* GFb = GF + ((size_t)b * DIM + h * 32) * HWX;
  int mw = warp * 16;

  for (int it = 0; it < 7; it++) {
    int q0 = (part * 7 + it) * 64;
    __syncthreads();
    for (int t = tid; t < 256; t += 128) {
      int d = t & 31, mg = t >> 5;
      uint4 vh = *(const uint4*)(qbh + (size_t)d * HWX + q0 + mg * 8);
      fp16* eh = (fp16*)&vh;
#pragma unroll
      for (int j = 0; j < 8; j++)
        *(fp16*)(sm + A6_AQH + ((mg * 8 + j) * 40 + d) * 2) = eh[j];
    }
    __syncthreads();

    // ---- QK over 26 key-tiles, x4 B-loads
    float acc[26][4];
    uint32_t accH[26][2];
#pragma unroll
    for (int nt = 0; nt < 26; nt++) {
#pragma unroll
      for (int c = 0; c < 4; c++) acc[nt][c] = 0.f;
      accH[nt][0] = 0u; accH[nt][1] = 0u;
    }
    int rn = ((lane >> 4) << 3) + (lane & 7);      // B x4 row-lane mapping
    uint32_t kb = ((lane >> 3) & 1) * 16;
#pragma unroll
    for (int s = 0; s < 2; s++) {
      uint32_t ah[4];
      uint32_t aoff = ((mw + (lane & 15)) * 40 + s * 16) * 2 + (lane >> 4) * 16;
      ldm4(ah, sb + A6_AQH + aoff);
#pragma unroll
      for (int np = 0; np < 13; np++) {
        uint32_t boff = (uint32_t)(((np * 16 + rn) * 40 + s * 16) * 2) + kb;
        uint32_t bh4[4], bl4[4];
        ldm4(bh4, sb + A6_KH + boff);
        ldm4(bl4, sb + A6_KL + boff);
        mmaF32(acc[2*np],   ah, bh4);
        mmaF16(accH[2*np],  ah, bl4);
        mmaF32(acc[2*np+1], ah, bh4 + 2);
        mmaF16(accH[2*np+1],ah, bl4 + 2);
      }
    }

    // ---- merge + scale + mask + softmax (no max-pass; scores are bounded)
    float sum1 = 0.f, sum2 = 0.f;
#pragma unroll
    for (int nt = 0; nt < 26; nt++) {
      int jb = nt * 8 + (lane & 3) * 2;
      float e0 = (acc[nt][0] + hlo(accH[nt][0])) * scal;
      float e1 = (acc[nt][1] + hhi(accH[nt][0])) * scal;
      float e2 = (acc[nt][2] + hlo(accH[nt][1])) * scal;
      float e3 = (acc[nt][3] + hhi(accH[nt][1])) * scal;
      e0 = (jb < HWP)     ? __expf(e0) : 0.f;
      e1 = (jb + 1 < HWP) ? __expf(e1) : 0.f;
      e2 = (jb < HWP)     ? __expf(e2) : 0.f;
      e3 = (jb + 1 < HWP) ? __expf(e3) : 0.f;
      acc[nt][0] = e0; acc[nt][1] = e1; acc[nt][2] = e2; acc[nt][3] = e3;
      sum1 += e0 + e1;
      sum2 += e2 + e3;
    }
#pragma unroll
    for (int o = 1; o <= 2; o <<= 1) {
      sum1 += __shfl_xor_sync(0xffffffffu, sum1, o);
      sum2 += __shfl_xor_sync(0xffffffffu, sum2, o);
    }
    float rec1 = 1.f / sum1, rec2 = 1.f / sum2;

    // ---- PV over 13 k-steps, register-resident P, x4 V-loads
    float acc2[4][4];
    uint32_t acc2H[4][2];
#pragma unroll
    for (int nt = 0; nt < 4; nt++) {
#pragma unroll
      for (int c = 0; c < 4; c++) acc2[nt][c] = 0.f;
      acc2H[nt][0] = 0u; acc2H[nt][1] = 0u;
    }
#pragma unroll 1
    for (int k = 0; k < 13; k++) {
      uint32_t ph[4];
      ph[0] = hpack(acc[2*k][0] * rec1,   acc[2*k][1] * rec1);
      ph[1] = hpack(acc[2*k][2] * rec2,   acc[2*k][3] * rec2);
      ph[2] = hpack(acc[2*k+1][0] * rec1, acc[2*k+1][1] * rec1);
      ph[3] = hpack(acc[2*k+1][2] * rec2, acc[2*k+1][3] * rec2);
#pragma unroll
      for (int np = 0; np < 2; np++) {
        uint32_t boff = (uint32_t)(((np * 16 + rn) * 232 + k * 16) * 2) + kb;
        uint32_t vh4[4], vl4[4];
        ldm4(vh4, sb + A6_VH + boff);
        ldm4(vl4, sb + A6_VL + boff);
        mmaF32(acc2[2*np],   ph, vh4);
        mmaF16(acc2H[2*np],  ph, vl4);
        mmaF32(acc2[2*np+1], ph, vh4 + 2);
        mmaF16(acc2H[2*np+1],ph, vl4 + 2);
      }
    }
    __syncthreads();

    float* Ob = (float*)sm;
    {
      int m1 = mw + (lane >> 2), m2 = m1 + 8;
      int cb = (lane & 3) * 2;
#pragma unroll
      for (int nt = 0; nt < 4; nt++) {
        int dcol = nt * 8 + cb;
        Ob[dcol * 68 + m1]       = acc2[nt][0] + hlo(acc2H[nt][0]);
        Ob[(dcol + 1) * 68 + m1] = acc2[nt][1] + hhi(acc2H[nt][0]);
        Ob[dcol * 68 + m2]       = acc2[nt][2] + hlo(acc2H[nt][1]);
        Ob[(dcol + 1) * 68 + m2] = acc2[nt][3] + hhi(acc2H[nt][1]);
      }
    }
    __syncthreads();
    {
      int row = tid >> 2, i0 = (tid & 3) * 16;
#pragma unroll
      for (int c = 0; c < 4; c++) {
        int i = i0 + c * 4;
        *(float4*)&GFb[(size_t)row * HWX + q0 + i] = *(float4*)&Ob[row * 68 + i];
      }
    }
  }
}

// ---------------- local mixer, 4-wide outputs -> fp16 hi mixbuf ----------------
__global__ __launch_bounds__(256) void local_gate_hf4_kernel(
    const float* __restrict__ Q, const float* __restrict__ Wd,
    const float* __restrict__ bias, const float* __restrict__ G,
    fp16* __restrict__ Oh) {
  int idx = blockIdx.x * 256 + threadIdx.x;
  int total = BATCH * DIM * HH * 14;   // 14 groups of 4 per row
  if (idx >= total) return;
  int gx = idx % 14; int t = idx / 14;
  int oy = t % HH; t /= HH;
  int c = t % DIM; int b = t / DIM;
  int ox0 = gx * 4;
  const float* xp = Q + (size_t)(b * DIM + c) * HWX;
  const float* wp = Wd + c * 25;
  float sums[4] = {0.f, 0.f, 0.f, 0.f};
#pragma unroll
  for (int ky = 0; ky < 5; ky++) {
    int iy = oy + ky - 2;
    if (iy < 0 || iy >= HH) continue;
    const float* row = xp + iy * WW;
    int ix0 = ox0 - 2;
    float rv[8];
#pragma unroll
    for (int j = 0; j < 8; j++) {
      int ix = ix0 + j;
      rv[j] = (ix >= 0 && ix < WW) ? row[ix] : 0.f;
    }
#pragma unroll
    for (int kx = 0; kx < 5; kx++) {
      float w = wp[ky * 5 + kx];
      sums[0] += rv[kx] * w;
      sums[1] += rv[1 + kx] * w;
      sums[2] += rv[2 + kx] * w;
      sums[3] += rv[3 + kx] * w;
    }
  }
  float bsv = bias[c];
  size_t ob = (size_t)(b * DIM + c) * HWX + oy * WW + ox0;
  float4 gv = *(const float4*)&G[ob];
  float g[4] = {gv.x, gv.y, gv.z, gv.w};
  fp16 o[4];
#pragma unroll
  for (int j = 0; j < 4; j++) {
    float s = sums[j] + bsv;
    float lf = s / (1.f + __expf(-s));
    float sg = 1.f / (1.f + __expf(-g[j]));
    o[j] = __float2half_rn(lf * sg * g[j]);
  }
  *(uint2*)&Oh[ob] = *(uint2*)o;
}

extern "C" void kernel_launch(void* const* d_in, const int* in_sizes, int n_in,
                              void* d_out, int out_size) {
  const float* x     = (const float*)d_in[0];
  const float* q_w   = (const float*)d_in[1];
  const float* q_b   = (const float*)d_in[2];
  const float* kv_w  = (const float*)d_in[3];
  const float* kv_b  = (const float*)d_in[4];
  const float* p0_w  = (const float*)d_in[5];
  const float* p0_b  = (const float*)d_in[6];
  const float* bn0_g = (const float*)d_in[7];
  const float* bn0_b = (const float*)d_in[8];
  const float* bn0_m = (const float*)d_in[9];
  const float* bn0_v = (const float*)d_in[10];
  const float* pl0_w = (const float*)d_in[11];
  const float* pl0_b = (const float*)d_in[12];
  const float* p1_w  = (const float*)d_in[13];
  const float* p1_b  = (const float*)d_in[14];
  const float* bn1_g = (const float*)d_in[15];
  const float* bn1_b = (const float*)d_in[16];
  const float* bn1_m = (const float*)d_in[17];
  const float* bn1_v = (const float*)d_in[18];
  const float* loc_w = (const float*)d_in[19];
  const float* loc_b = (const float*)d_in[20];
  const float* mix_w = (const float*)d_in[21];
  const float* mix_b = (const float*)d_in[22];
  float* out = (float*)d_out;

  float *qlocal, *pmid, *gf;
  cudaGetSymbolAddress((void**)&qlocal, g_qlocal);
  cudaGetSymbolAddress((void**)&pmid,   g_pmid);
  cudaGetSymbolAddress((void**)&gf,     g_gf);
  fp16 *xh, *qh, *mh, *p0h, *pfh, *kvh, *kvl, *wh, *wl;
  cudaGetSymbolAddress((void**)&xh, g_xh);
  cudaGetSymbolAddress((void**)&qh, g_qh);
  cudaGetSymbolAddress((void**)&mh, g_mh);
  cudaGetSymbolAddress((void**)&p0h, g_p0h);
  cudaGetSymbolAddress((void**)&pfh, g_pfh);
  cudaGetSymbolAddress((void**)&kvh, g_kvh); cudaGetSymbolAddress((void**)&kvl, g_kvl);
  cudaGetSymbolAddress((void**)&wh, g_wh);   cudaGetSymbolAddress((void**)&wl, g_wl);

  cudaFuncSetAttribute(conv1x1_hf_kernel, cudaFuncAttributeMaxDynamicSharedMemorySize, CV_SMEM);
  cudaFuncSetAttribute(attn7_kernel, cudaFuncAttributeMaxDynamicSharedMemorySize, A6_BYTES);

  // 0. pre-split: weights hi/lo; x hi only
  cvt_h_kernel<<<(NX/4 + 255)/256, 256>>>(x, xh, NX/4);
  cvt_hl_kernel<<<(65536/4 + 255)/256, 256>>>(q_w,   wh + WOFF_Q,   wl + WOFF_Q,   65536/4);
  cvt_hl_kernel<<<(65536/4 + 255)/256, 256>>>(pl0_w, wh + WOFF_PL,  wl + WOFF_PL,  65536/4);
  cvt_hl_kernel<<<(131072/4 + 255)/256, 256>>>(kv_w, wh + WOFF_KV,  wl + WOFF_KV,  131072/4);
  cvt_hl_kernel<<<(65536/4 + 255)/256, 256>>>(mix_w, wh + WOFF_MIX, wl + WOFF_MIX, 65536/4);

  // 1. q_local (f32 + fp16 hi for attention Q)
  conv1x1_hf_kernel<<<dim3((HWX + 127)/128, DIM/128, BATCH), 256, CV_SMEM>>>(
      wh + WOFF_Q, wl + WOFF_Q, xh, q_b, qlocal, qh, (fp16*)nullptr, DIM, DIM, HWX);
  // 2. p0 = BN0(dw5x5_s2(x)) -> fp16 hi   (Wout=28: gpr=7)
  dw_s2_bn_hf4_kernel<<<(BATCH*DIM*HP1*7 + 255)/256, 256>>>(
      x, p0_w, p0_b, bn0_g, bn0_b, bn0_m, bn0_v, p0h, HH, WW, HP1, HP1, 7);
  // 3. pmid = conv1x1(p0) -> f32
  conv1x1_hf_kernel<<<dim3((HW1 + 127)/128, DIM/128, BATCH), 256, CV_SMEM>>>(
      wh + WOFF_PL, wl + WOFF_PL, p0h, pl0_b, pmid, (fp16*)nullptr, (fp16*)nullptr, DIM, DIM, HW1);
  // 4. pfin = BN1(dw5x5_s2(pmid)) -> fp16 hi   (Wout=14: gpr=4, last group partial)
  dw_s2_bn_hf4_kernel<<<(BATCH*DIM*HP2*4 + 255)/256, 256>>>(
      pmid, p1_w, p1_b, bn1_g, bn1_b, bn1_m, bn1_v, pfh, HP1, HP1, HP2, HP2, 4);
  // 5. kv = conv1x1(pfin) -> fp16 hi/lo
  conv1x1_hf_kernel<<<dim3((HWP + 127)/128, (2*DIM)/128, BATCH), 256, CV_SMEM>>>(
      wh + WOFF_KV, wl + WOFF_KV, pfh, kv_b, (float*)nullptr, kvh, kvl, 2*DIM, DIM, HWP);
  // 6. attention -> gf
  attn7_kernel<<<BATCH*HEADS*7, 128, A6_BYTES>>>(qh, kvh, kvl, gf);
  // 7. local mixer + gating (4-wide) -> fp16 hi mixbuf
  local_gate_hf4_kernel<<<(BATCH*DIM*HH*14 + 255)/256, 256>>>(qlocal, loc_w, loc_b, gf, mh);
  // 8. out = conv1x1(mixbuf) -> f32
  conv1x1_hf_kernel<<<dim3((HWX + 127)/128, DIM/128, BATCH), 256, CV_SMEM>>>(
      wh + WOFF_MIX, wl + WOFF_MIX, mh, mix_b, out, (fp16*)nullptr, (fp16*)nullptr, DIM, DIM, HWX);
}

// round 12
// speedup vs baseline: 3.4031x; 1.0612x over previous
#include <cuda_runtime.h>
#include <cuda_fp16.h>
#include <cstdint>

#define BATCH 16
#define DIM 256
#define HH 56
#define WW 56
#define HWX (HH*WW)          // 3136
#define HEADS 8
#define DH 32
#define HP1 28
#define HW1 (HP1*HP1)        // 784
#define HP2 14
#define HWP (HP2*HP2)        // 196
#define BN_EPS 1e-5f

#define SW128(x) ((x) ^ (((x) >> 3) & 0x70))

typedef __half fp16;

__device__ __forceinline__ uint32_t smem_u32(const void* p) {
  uint32_t a;
  asm("{ .reg .u64 t; cvta.to.shared.u64 t, %1; cvt.u32.u64 %0, t; }" : "=r"(a) : "l"(p));
  return a;
}
__device__ __forceinline__ void ldm4(uint32_t a[4], uint32_t addr) {
  asm volatile("ldmatrix.sync.aligned.m8n8.x4.shared.b16 {%0,%1,%2,%3}, [%4];"
               : "=r"(a[0]), "=r"(a[1]), "=r"(a[2]), "=r"(a[3]) : "r"(addr));
}
__device__ __forceinline__ void ldm4t(uint32_t a[4], uint32_t addr) {
  asm volatile("ldmatrix.sync.aligned.m8n8.x4.trans.shared.b16 {%0,%1,%2,%3}, [%4];"
               : "=r"(a[0]), "=r"(a[1]), "=r"(a[2]), "=r"(a[3]) : "r"(addr));
}
__device__ __forceinline__ void mmaF32(float d[4], const uint32_t a[4], const uint32_t b[2]) {
  asm volatile("mma.sync.aligned.m16n8k16.row.col.f32.f16.f16.f32 "
               "{%0,%1,%2,%3}, {%4,%5,%6,%7}, {%8,%9}, {%0,%1,%2,%3};"
               : "+f"(d[0]), "+f"(d[1]), "+f"(d[2]), "+f"(d[3])
               : "r"(a[0]), "r"(a[1]), "r"(a[2]), "r"(a[3]), "r"(b[0]), "r"(b[1]));
}
__device__ __forceinline__ void mmaF16(uint32_t d[2], const uint32_t a[4], const uint32_t b[2]) {
  asm volatile("mma.sync.aligned.m16n8k16.row.col.f16.f16.f16.f16 "
               "{%0,%1}, {%2,%3,%4,%5}, {%6,%7}, {%0,%1};"
               : "+r"(d[0]), "+r"(d[1])
               : "r"(a[0]), "r"(a[1]), "r"(a[2]), "r"(a[3]), "r"(b[0]), "r"(b[1]));
}
__device__ __forceinline__ uint32_t hpack(float a, float b) {
  __half2 t = __floats2half2_rn(a, b);
  return *(uint32_t*)&t;
}
__device__ __forceinline__ float hlo(uint32_t v) { return __half2float(((__half2*)&v)->x); }
__device__ __forceinline__ float hhi(uint32_t v) { return __half2float(((__half2*)&v)->y); }

// ---------------- scratch (device globals; no allocations allowed) ----------------
#define NX (BATCH*DIM*HWX)
#define NP0 (BATCH*DIM*HW1)
#define NPF (BATCH*DIM*HWP)
#define NKV (BATCH*2*DIM*HWP)
#define WOFF_Q 0
#define WOFF_PL 65536
#define WOFF_KV 131072
#define WOFF_MIX 262144
#define NW 327680
__device__ fp16 g_xh[NX];
__device__ fp16 g_qh[NX];
__device__ fp16 g_mh[NX];
__device__ fp16 g_gf16[NX];
__device__ fp16 g_p0h[NP0];
__device__ fp16 g_pm16[NP0];
__device__ fp16 g_pfh[NPF];
__device__ fp16 g_kvh[NKV], g_kvl[NKV];
__device__ fp16 g_wh[NW],  g_wl[NW];

// ---------------- x -> fp16 hi ----------------
__global__ __launch_bounds__(256) void cvt_h_kernel(
    const float* __restrict__ s, fp16* __restrict__ h, int n4) {
  int i = blockIdx.x * 256 + threadIdx.x;
  if (i >= n4) return;
  float4 v = ((const float4*)s)[i];
  ((__half2*)h)[2*i]   = __floats2half2_rn(v.x, v.y);
  ((__half2*)h)[2*i+1] = __floats2half2_rn(v.z, v.w);
}
// ---------------- fused weight hi/lo split (all 4 weight tensors, one launch) ----------
__global__ __launch_bounds__(256) void cvt_w_kernel(
    const float* __restrict__ qw, const float* __restrict__ plw,
    const float* __restrict__ kvw, const float* __restrict__ mxw,
    fp16* __restrict__ h, fp16* __restrict__ l) {
  int i = blockIdx.x * 256 + threadIdx.x;          // float4 index; NW/4 = 81920 total
  if (i >= NW / 4) return;
  const float* src;
  int li;
  if (i < 16384)      { src = qw;  li = i; }
  else if (i < 32768) { src = plw; li = i - 16384; }
  else if (i < 65536) { src = kvw; li = i - 32768; }
  else                { src = mxw; li = i - 65536; }
  float4 v = ((const float4*)src)[li];
  __half2 h0 = __floats2half2_rn(v.x, v.y);
  __half2 h1 = __floats2half2_rn(v.z, v.w);
  __half2 l0 = __floats2half2_rn(v.x - __half2float(h0.x), v.y - __half2float(h0.y));
  __half2 l1 = __floats2half2_rn(v.z - __half2float(h1.x), v.w - __half2float(h1.y));
  ((__half2*)h)[2*i] = h0; ((__half2*)h)[2*i+1] = h1;
  ((__half2*)l)[2*i] = l0; ((__half2*)l)[2*i+1] = l1;
}

// ---------------- 1x1 conv: 2-pass split-fp16 HMMA, x4-trans B loads ----------------
#define CV_SMEM 49152

__global__ __launch_bounds__(256) void conv1x1_hf_kernel(
    const fp16* __restrict__ Ah, const fp16* __restrict__ Al,
    const fp16* __restrict__ Bh,
    const float* __restrict__ bias, float* __restrict__ Yf,
    fp16* __restrict__ Yh, fp16* __restrict__ Yl,
    int CO, int CI, int HW) {
  extern __shared__ __align__(1024) char smem[];
  char* sAh = smem;         char* sAl = smem + 16384;
  char* sBh = smem + 32768;
  uint32_t aAh = smem_u32(sAh), aAl = smem_u32(sAl);
  uint32_t aBh = smem_u32(sBh);
  int tid = threadIdx.x, lane = tid & 31, wid = tid >> 5;
  int m0 = blockIdx.y * 128, n0 = blockIdx.x * 128;
  const fp16* Bhb = Bh + (size_t)blockIdx.z * CI * HW;
  int mw = (wid & 3) * 32, nw = (wid >> 2) * 64;

  float acc[2][8][4];
  uint32_t accH[2][8][2];
#pragma unroll
  for (int i = 0; i < 2; i++)
#pragma unroll
    for (int j = 0; j < 8; j++) {
#pragma unroll
      for (int c = 0; c < 4; c++) acc[i][j][c] = 0.f;
      accH[i][j][0] = 0u; accH[i][j][1] = 0u;
    }

  for (int k0 = 0; k0 < CI; k0 += 64) {
#pragma unroll
    for (int i = 0; i < 4; i++) {
      int t = tid + i * 256;
      int m = t >> 3, kg = t & 7;
      size_t src = (size_t)(m0 + m) * CI + k0 + kg * 8;
      uint32_t dst = SW128(m * 128 + kg * 16);
      *(uint4*)(sAh + dst) = *(const uint4*)(Ah + src);
      *(uint4*)(sAl + dst) = *(const uint4*)(Al + src);
    }
#pragma unroll
    for (int i = 0; i < 4; i++) {
      int t = tid + i * 256;
      int k = t & 63, c = t >> 6;
      int gn = n0 + c * 8;
      uint4 vh;
      if (gn + 8 <= HW) {
        const char* ph = (const char*)(Bhb + (size_t)(k0 + k) * HW + gn);
        uint2 h0 = *(const uint2*)ph, h1 = *(const uint2*)(ph + 8);
        vh = make_uint4(h0.x, h0.y, h1.x, h1.y);
      } else {
        fp16 th[8];
#pragma unroll
        for (int j = 0; j < 8; j++) {
          int g = gn + j;
          th[j] = (g < HW) ? Bhb[(size_t)(k0 + k) * HW + g] : __float2half(0.f);
        }
        vh = *(uint4*)th;
      }
      *(uint4*)(sBh + (k * 256 + ((c ^ (k & 15)) << 4))) = vh;
    }
    __syncthreads();
#pragma unroll
    for (int s = 0; s < 4; s++) {
      uint32_t ah[2][4], al[2][4];
#pragma unroll
      for (int tm = 0; tm < 2; tm++) {
        uint32_t off = SW128((mw + tm * 16 + (lane & 15)) * 128 + s * 32 + (lane >> 4) * 16);
        ldm4(ah[tm], aAh + off);
        ldm4(al[tm], aAl + off);
      }
      int kk = s * 16 + (lane & 15);
#pragma unroll
      for (int ntp = 0; ntp < 4; ntp++) {
        int nt_eff = 2 * ntp + (lane >> 4);
        uint32_t cIdx = (uint32_t)(((nw >> 3) + nt_eff) ^ (kk & 15));
        uint32_t bq[4];
        ldm4t(bq, aBh + kk * 256 + (cIdx << 4));
#pragma unroll
        for (int tm = 0; tm < 2; tm++) {
          mmaF32(acc[tm][2*ntp],   ah[tm], bq);
          mmaF16(accH[tm][2*ntp],  al[tm], bq);
          mmaF32(acc[tm][2*ntp+1], ah[tm], bq + 2);
          mmaF16(accH[tm][2*ntp+1],al[tm], bq + 2);
        }
      }
    }
    __syncthreads();
  }
  // epilogue
#pragma unroll
  for (int tm = 0; tm < 2; tm++) {
    int r0 = m0 + mw + tm * 16 + (lane >> 2);
    float b0 = bias[r0], b1 = bias[r0 + 8];
#pragma unroll
    for (int tn = 0; tn < 8; tn++) {
      int col = n0 + nw + tn * 8 + (lane & 3) * 2;
      if (col < HW) {
        float o0 = acc[tm][tn][0] + hlo(accH[tm][tn][0]) + b0;
        float o1 = acc[tm][tn][1] + hhi(accH[tm][tn][0]) + b0;
        float o2 = acc[tm][tn][2] + hlo(accH[tm][tn][1]) + b1;
        float o3 = acc[tm][tn][3] + hhi(accH[tm][tn][1]) + b1;
        size_t i0 = (size_t)blockIdx.z * CO * HW + (size_t)r0 * HW + col;
        size_t i1 = i0 + (size_t)8 * HW;
        if (Yf) {
          *(float2*)&Yf[i0] = make_float2(o0, o1);
          *(float2*)&Yf[i1] = make_float2(o2, o3);
        }
        if (Yh) {
          __half2 h0 = __floats2half2_rn(o0, o1);
          __half2 h1 = __floats2half2_rn(o2, o3);
          *(__half2*)&Yh[i0] = h0; *(__half2*)&Yh[i1] = h1;
          if (Yl) {
            __half2 l0 = __floats2half2_rn(o0 - __half2float(h0.x), o1 - __half2float(h0.y));
            __half2 l1 = __floats2half2_rn(o2 - __half2float(h1.x), o3 - __half2float(h1.y));
            *(__half2*)&Yl[i0] = l0; *(__half2*)&Yl[i1] = l1;
          }
        }
      }
    }
  }
}

// ---------------- depthwise 5x5 stride2 + BN, fp16 in -> fp16 hi, 4-wide ----------------
__global__ __launch_bounds__(256) void dw_s2_bn_hf4_kernel(
    const fp16* __restrict__ X, const float* __restrict__ Wd,
    const float* __restrict__ bias, const float* __restrict__ gam,
    const float* __restrict__ bet, const float* __restrict__ mu,
    const float* __restrict__ var, fp16* __restrict__ Yh,
    int Hin, int Win, int Hout, int Wout, int gpr) {
  int idx = blockIdx.x * 256 + threadIdx.x;
  int total = BATCH * DIM * Hout * gpr;
  if (idx >= total) return;
  int gx = idx % gpr; int t = idx / gpr;
  int oy = t % Hout; t /= Hout;
  int c = t % DIM; int b = t / DIM;
  int ox0 = gx * 4;
  const fp16* xp = X + (size_t)(b * DIM + c) * Hin * Win;
  const float* wp = Wd + c * 25;
  float sums[4] = {0.f, 0.f, 0.f, 0.f};
#pragma unroll
  for (int ky = 0; ky < 5; ky++) {
    int iy = oy * 2 - 2 + ky;
    if (iy < 0 || iy >= Hin) continue;
    const fp16* row = xp + iy * Win;
    int ix0 = ox0 * 2 - 2;
    float rv[11];
#pragma unroll
    for (int j = 0; j < 11; j++) {
      int ix = ix0 + j;
      rv[j] = (ix >= 0 && ix < Win) ? __half2float(row[ix]) : 0.f;
    }
#pragma unroll
    for (int kx = 0; kx < 5; kx++) {
      float w = wp[ky * 5 + kx];
      sums[0] += rv[kx] * w;
      sums[1] += rv[2 + kx] * w;
      sums[2] += rv[4 + kx] * w;
      sums[3] += rv[6 + kx] * w;
    }
  }
  float bsv = bias[c];
  float sc = gam[c] * rsqrtf(var[c] + BN_EPS);
  float muv = mu[c], bev = bet[c];
  size_t ob = ((size_t)(b * DIM + c) * Hout + oy) * Wout + ox0;
#pragma unroll
  for (int o = 0; o < 4; o++) {
    if (ox0 + o < Wout)
      Yh[ob + o] = __float2half_rn((sums[o] + bsv - muv) * sc + bev);
  }
}
// same, fp32 input (for the very first dw which reads x)
__global__ __launch_bounds__(256) void dw_s2_bn_f4_kernel(
    const float* __restrict__ X, const float* __restrict__ Wd,
    const float* __restrict__ bias, const float* __restrict__ gam,
    const float* __restrict__ bet, const float* __restrict__ mu,
    const float* __restrict__ var, fp16* __restrict__ Yh,
    int Hin, int Win, int Hout, int Wout, int gpr) {
  int idx = blockIdx.x * 256 + threadIdx.x;
  int total = BATCH * DIM * Hout * gpr;
  if (idx >= total) return;
  int gx = idx % gpr; int t = idx / gpr;
  int oy = t % Hout; t /= Hout;
  int c = t % DIM; int b = t / DIM;
  int ox0 = gx * 4;
  const float* xp = X + (size_t)(b * DIM + c) * Hin * Win;
  const float* wp = Wd + c * 25;
  float sums[4] = {0.f, 0.f, 0.f, 0.f};
#pragma unroll
  for (int ky = 0; ky < 5; ky++) {
    int iy = oy * 2 - 2 + ky;
    if (iy < 0 || iy >= Hin) continue;
    const float* row = xp + iy * Win;
    int ix0 = ox0 * 2 - 2;
    float rv[11];
#pragma unroll
    for (int j = 0; j < 11; j++) {
      int ix = ix0 + j;
      rv[j] = (ix >= 0 && ix < Win) ? row[ix] : 0.f;
    }
#pragma unroll
    for (int kx = 0; kx < 5; kx++) {
      float w = wp[ky * 5 + kx];
      sums[0] += rv[kx] * w;
      sums[1] += rv[2 + kx] * w;
      sums[2] += rv[4 + kx] * w;
      sums[3] += rv[6 + kx] * w;
    }
  }
  float bsv = bias[c];
  float sc = gam[c] * rsqrtf(var[c] + BN_EPS);
  float muv = mu[c], bev = bet[c];
  size_t ob = ((size_t)(b * DIM + c) * Hout + oy) * Wout + ox0;
#pragma unroll
  for (int o = 0; o < 4; o++) {
    if (ox0 + o < Wout)
      Yh[ob + o] = __float2half_rn((sums[o] + bsv - muv) * sc + bev);
  }
}

// ---------------- attention v7: x4 B-loads, no max-pass, fp16 output ----------------
#define A6_AQH 0
#define A6_KH  8704
#define A6_KL  26624
#define A6_VH  44544
#define A6_VL  59392
#define A6_BYTES 74240

__global__ __launch_bounds__(128, 2) void attn7_kernel(
    const fp16* __restrict__ Qh,
    const fp16* __restrict__ KVh, const fp16* __restrict__ KVl,
    fp16* __restrict__ GF) {
  extern __shared__ __align__(1024) char sm[];
  uint32_t sb = smem_u32(sm);
  int tid = threadIdx.x, lane = tid & 31, warp = tid >> 5;
  int part = blockIdx.x % 7;
  int bh = blockIdx.x / 7;
  int b = bh >> 3, h = bh & 7;
  const fp16* kHh = KVh + ((size_t)b * 2 * DIM + h * 32) * HWP;
  const fp16* kHl = KVl + ((size_t)b * 2 * DIM + h * 32) * HWP;
  const fp16* vHh = kHh + (size_t)DIM * HWP;
  const fp16* vHl = kHl + (size_t)DIM * HWP;
  const float scal = 0.17677669529663687f;  // 32^-0.5

  for (int t = tid; t < 896; t += 128) {
    int d = t & 31, jg = t >> 5;
    int j0 = jg * 8;
    fp16 th[8], tl[8], uh[8], ul[8];
    if (j0 + 8 <= HWP) {
      const char* pkh = (const char*)(kHh + (size_t)d * HWP + j0);
      const char* pkl = (const char*)(kHl + (size_t)d * HWP + j0);
      const char* pvh = (const char*)(vHh + (size_t)d * HWP + j0);
      const char* pvl = (const char*)(vHl + (size_t)d * HWP + j0);
      *(uint2*)th = *(const uint2*)pkh; *(uint2*)(th + 4) = *(const uint2*)(pkh + 8);
      *(uint2*)tl = *(const uint2*)pkl; *(uint2*)(tl + 4) = *(const uint2*)(pkl + 8);
      *(uint2*)uh = *(const uint2*)pvh; *(uint2*)(uh + 4) = *(const uint2*)(pvh + 8);
      *(uint2*)ul = *(const uint2*)pvl; *(uint2*)(ul + 4) = *(const uint2*)(pvl + 8);
    } else {
      fp16 z = __float2half(0.f);
#pragma unroll
      for (int j = 0; j < 8; j++) {
        int g = j0 + j;
        bool v = g < HWP;
        th[j] = v ? kHh[(size_t)d * HWP + g] : z;
        tl[j] = v ? kHl[(size_t)d * HWP + g] : z;
        uh[j] = v ? vHh[(size_t)d * HWP + g] : z;
        ul[j] = v ? vHl[(size_t)d * HWP + g] : z;
      }
    }
#pragma unroll
    for (int j = 0; j < 8; j++) {
      *(fp16*)(sm + A6_KH + ((j0 + j) * 40 + d) * 2) = th[j];
      *(fp16*)(sm + A6_KL + ((j0 + j) * 40 + d) * 2) = tl[j];
    }
    *(uint4*)(sm + A6_VH + (d * 232 + j0) * 2) = *(uint4*)uh;
    *(uint4*)(sm + A6_VL + (d * 232 + j0) * 2) = *(uint4*)ul;
  }

  const fp16* qbh = Qh + ((size_t)b * DIM + h * 32) * HWX;
  fp16* GFb = GF + ((size_t)b * DIM + h * 32) * HWX;
  int mw = warp * 16;

  for (int it = 0; it < 7; it++) {
    int q0 = (part * 7 + it) * 64;
    __syncthreads();
    for (int t = tid; t < 256; t += 128) {
      int d = t & 31, mg = t >> 5;
      uint4 vh = *(const uint4*)(qbh + (size_t)d * HWX + q0 + mg * 8);
      fp16* eh = (fp16*)&vh;
#pragma unroll
      for (int j = 0; j < 8; j++)
        *(fp16*)(sm + A6_AQH + ((mg * 8 + j) * 40 + d) * 2) = eh[j];
    }
    __syncthreads();

    float acc[26][4];
    uint32_t accH[26][2];
#pragma unroll
    for (int nt = 0; nt < 26; nt++) {
#pragma unroll
      for (int c = 0; c < 4; c++) acc[nt][c] = 0.f;
      accH[nt][0] = 0u; accH[nt][1] = 0u;
    }
    int rn = ((lane >> 4) << 3) + (lane & 7);
    uint32_t kb = ((lane >> 3) & 1) * 16;
#pragma unroll
    for (int s = 0; s < 2; s++) {
      uint32_t ah[4];
      uint32_t aoff = ((mw + (lane & 15)) * 40 + s * 16) * 2 + (lane >> 4) * 16;
      ldm4(ah, sb + A6_AQH + aoff);
#pragma unroll
      for (int np = 0; np < 13; np++) {
        uint32_t boff = (uint32_t)(((np * 16 + rn) * 40 + s * 16) * 2) + kb;
        uint32_t bh4[4], bl4[4];
        ldm4(bh4, sb + A6_KH + boff);
        ldm4(bl4, sb + A6_KL + boff);
        mmaF32(acc[2*np],   ah, bh4);
        mmaF16(accH[2*np],  ah, bl4);
        mmaF32(acc[2*np+1], ah, bh4 + 2);
        mmaF16(accH[2*np+1],ah, bl4 + 2);
      }
    }

    float sum1 = 0.f, sum2 = 0.f;
#pragma unroll
    for (int nt = 0; nt < 26; nt++) {
      int jb = nt * 8 + (lane & 3) * 2;
      float e0 = (acc[nt][0] + hlo(accH[nt][0])) * scal;
      float e1 = (acc[nt][1] + hhi(accH[nt][0])) * scal;
      float e2 = (acc[nt][2] + hlo(accH[nt][1])) * scal;
      float e3 = (acc[nt][3] + hhi(accH[nt][1])) * scal;
      e0 = (jb < HWP)     ? __expf(e0) : 0.f;
      e1 = (jb + 1 < HWP) ? __expf(e1) : 0.f;
      e2 = (jb < HWP)     ? __expf(e2) : 0.f;
      e3 = (jb + 1 < HWP) ? __expf(e3) : 0.f;
      acc[nt][0] = e0; acc[nt][1] = e1; acc[nt][2] = e2; acc[nt][3] = e3;
      sum1 += e0 + e1;
      sum2 += e2 + e3;
    }
#pragma unroll
    for (int o = 1; o <= 2; o <<= 1) {
      sum1 += __shfl_xor_sync(0xffffffffu, sum1, o);
      sum2 += __shfl_xor_sync(0xffffffffu, sum2, o);
    }
    float rec1 = 1.f / sum1, rec2 = 1.f / sum2;

    float acc2[4][4];
    uint32_t acc2H[4][2];
#pragma unroll
    for (int nt = 0; nt < 4; nt++) {
#pragma unroll
      for (int c = 0; c < 4; c++) acc2[nt][c] = 0.f;
      acc2H[nt][0] = 0u; acc2H[nt][1] = 0u;
    }
#pragma unroll 1
    for (int k = 0; k < 13; k++) {
      uint32_t ph[4];
      ph[0] = hpack(acc[2*k][0] * rec1,   acc[2*k][1] * rec1);
      ph[1] = hpack(acc[2*k][2] * rec2,   acc[2*k][3] * rec2);
      ph[2] = hpack(acc[2*k+1][0] * rec1, acc[2*k+1][1] * rec1);
      ph[3] = hpack(acc[2*k+1][2] * rec2, acc[2*k+1][3] * rec2);
#pragma unroll
      for (int np = 0; np < 2; np++) {
        uint32_t boff = (uint32_t)(((np * 16 + rn) * 232 + k * 16) * 2) + kb;
        uint32_t vh4[4], vl4[4];
        ldm4(vh4, sb + A6_VH + boff);
        ldm4(vl4, sb + A6_VL + boff);
        mmaF32(acc2[2*np],   ph, vh4);
        mmaF16(acc2H[2*np],  ph, vl4);
        mmaF32(acc2[2*np+1], ph, vh4 + 2);
        mmaF16(acc2H[2*np+1],ph, vl4 + 2);
      }
    }
    __syncthreads();

    float* Ob = (float*)sm;
    {
      int m1 = mw + (lane >> 2), m2 = m1 + 8;
      int cb = (lane & 3) * 2;
#pragma unroll
      for (int nt = 0; nt < 4; nt++) {
        int dcol = nt * 8 + cb;
        Ob[dcol * 68 + m1]       = acc2[nt][0] + hlo(acc2H[nt][0]);
        Ob[(dcol + 1) * 68 + m1] = acc2[nt][1] + hhi(acc2H[nt][0]);
        Ob[dcol * 68 + m2]       = acc2[nt][2] + hlo(acc2H[nt][1]);
        Ob[(dcol + 1) * 68 + m2] = acc2[nt][3] + hhi(acc2H[nt][1]);
      }
    }
    __syncthreads();
    {
      int row = tid >> 2, i0 = (tid & 3) * 16;
#pragma unroll
      for (int c = 0; c < 4; c++) {
        int i = i0 + c * 4;
        float4 v = *(float4*)&Ob[row * 68 + i];
        __half2 p0 = __floats2half2_rn(v.x, v.y);
        __half2 p1 = __floats2half2_rn(v.z, v.w);
        uint2 pk = make_uint2(*(uint32_t*)&p0, *(uint32_t*)&p1);
        *(uint2*)&GFb[(size_t)row * HWX + q0 + i] = pk;
      }
    }
  }
}

// ---------------- local mixer, fp16 in/out, 4-wide ----------------
__global__ __launch_bounds__(256) void local_gate_hf4_kernel(
    const fp16* __restrict__ Q, const float* __restrict__ Wd,
    const float* __restrict__ bias, const fp16* __restrict__ G,
    fp16* __restrict__ Oh) {
  int idx = blockIdx.x * 256 + threadIdx.x;
  int total = BATCH * DIM * HH * 14;
  if (idx >= total) return;
  int gx = idx % 14; int t = idx / 14;
  int oy = t % HH; t /= HH;
  int c = t % DIM; int b = t / DIM;
  int ox0 = gx * 4;
  const fp16* xp = Q + (size_t)(b * DIM + c) * HWX;
  const float* wp = Wd + c * 25;
  float sums[4] = {0.f, 0.f, 0.f, 0.f};
#pragma unroll
  for (int ky = 0; ky < 5; ky++) {
    int iy = oy + ky - 2;
    if (iy < 0 || iy >= HH) continue;
    const fp16* row = xp + iy * WW;
    int ix0 = ox0 - 2;
    float rv[8];
#pragma unroll
    for (int j = 0; j < 8; j++) {
      int ix = ix0 + j;
      rv[j] = (ix >= 0 && ix < WW) ? __half2float(row[ix]) : 0.f;
    }
#pragma unroll
    for (int kx = 0; kx < 5; kx++) {
      float w = wp[ky * 5 + kx];
      sums[0] += rv[kx] * w;
      sums[1] += rv[1 + kx] * w;
      sums[2] += rv[2 + kx] * w;
      sums[3] += rv[3 + kx] * w;
    }
  }
  float bsv = bias[c];
  size_t ob = (size_t)(b * DIM + c) * HWX + oy * WW + ox0;
  uint2 gp = *(const uint2*)&G[ob];
  __half2 g01 = *(__half2*)&gp.x, g23 = *(__half2*)&gp.y;
  float g[4] = {__half2float(g01.x), __half2float(g01.y),
                __half2float(g23.x), __half2float(g23.y)};
  fp16 o[4];
#pragma unroll
  for (int j = 0; j < 4; j++) {
    float s = sums[j] + bsv;
    float lf = s / (1.f + __expf(-s));
    float sg = 1.f / (1.f + __expf(-g[j]));
    o[j] = __float2half_rn(lf * sg * g[j]);
  }
  *(uint2*)&Oh[ob] = *(uint2*)o;
}

extern "C" void kernel_launch(void* const* d_in, const int* in_sizes, int n_in,
                              void* d_out, int out_size) {
  const float* x     = (const float*)d_in[0];
  const float* q_w   = (const float*)d_in[1];
  const float* q_b   = (const float*)d_in[2];
  const float* kv_w  = (const float*)d_in[3];
  const float* kv_b  = (const float*)d_in[4];
  const float* p0_w  = (const float*)d_in[5];
  const float* p0_b  = (const float*)d_in[6];
  const float* bn0_g = (const float*)d_in[7];
  const float* bn0_b = (const float*)d_in[8];
  const float* bn0_m = (const float*)d_in[9];
  const float* bn0_v = (const float*)d_in[10];
  const float* pl0_w = (const float*)d_in[11];
  const float* pl0_b = (const float*)d_in[12];
  const float* p1_w  = (const float*)d_in[13];
  const float* p1_b  = (const float*)d_in[14];
  const float* bn1_g = (const float*)d_in[15];
  const float* bn1_b = (const float*)d_in[16];
  const float* bn1_m = (const float*)d_in[17];
  const float* bn1_v = (const float*)d_in[18];
  const float* loc_w = (const float*)d_in[19];
  const float* loc_b = (const float*)d_in[20];
  const float* mix_w = (const float*)d_in[21];
  const float* mix_b = (const float*)d_in[22];
  float* out = (float*)d_out;

  fp16 *xh, *qh, *mh, *gf16, *p0h, *pm16, *pfh, *kvh, *kvl, *wh, *wl;
  cudaGetSymbolAddress((void**)&xh, g_xh);
  cudaGetSymbolAddress((void**)&qh, g_qh);
  cudaGetSymbolAddress((void**)&mh, g_mh);
  cudaGetSymbolAddress((void**)&gf16, g_gf16);
  cudaGetSymbolAddress((void**)&p0h, g_p0h);
  cudaGetSymbolAddress((void**)&pm16, g_pm16);
  cudaGetSymbolAddress((void**)&pfh, g_pfh);
  cudaGetSymbolAddress((void**)&kvh, g_kvh); cudaGetSymbolAddress((void**)&kvl, g_kvl);
  cudaGetSymbolAddress((void**)&wh, g_wh);   cudaGetSymbolAddress((void**)&wl, g_wl);

  cudaFuncSetAttribute(conv1x1_hf_kernel, cudaFuncAttributeMaxDynamicSharedMemorySize, CV_SMEM);
  cudaFuncSetAttribute(attn7_kernel, cudaFuncAttributeMaxDynamicSharedMemorySize, A6_BYTES);

  // 0. pre-split: all weights in one launch; x hi
  cvt_h_kernel<<<(NX/4 + 255)/256, 256>>>(x, xh, NX/4);
  cvt_w_kernel<<<(NW/4 + 255)/256, 256>>>(q_w, pl0_w, kv_w, mix_w, wh, wl);

  // 1. q_local -> fp16 hi only (feeds attention Q and local-gate dw)
  conv1x1_hf_kernel<<<dim3((HWX + 127)/128, DIM/128, BATCH), 256, CV_SMEM>>>(
      wh + WOFF_Q, wl + WOFF_Q, xh, q_b, (float*)nullptr, qh, (fp16*)nullptr, DIM, DIM, HWX);
  // 2. p0 = BN0(dw5x5_s2(x)) -> fp16 hi
  dw_s2_bn_f4_kernel<<<(BATCH*DIM*HP1*7 + 255)/256, 256>>>(
      x, p0_w, p0_b, bn0_g, bn0_b, bn0_m, bn0_v, p0h, HH, WW, HP1, HP1, 7);
  // 3. pmid = conv1x1(p0) -> fp16 hi
  conv1x1_hf_kernel<<<dim3((HW1 + 127)/128, DIM/128, BATCH), 256, CV_SMEM>>>(
      wh + WOFF_PL, wl + WOFF_PL, p0h, pl0_b, (float*)nullptr, pm16, (fp16*)nullptr, DIM, DIM, HW1);
  // 4. pfin = BN1(dw5x5_s2(pmid)) -> fp16 hi
  dw_s2_bn_hf4_kernel<<<(BATCH*DIM*HP2*4 + 255)/256, 256>>>(
      pm16, p1_w, p1_b, bn1_g, bn1_b, bn1_m, bn1_v, pfh, HP1, HP1, HP2, HP2, 4);
  // 5. kv = conv1x1(pfin) -> fp16 hi/lo
  conv1x1_hf_kernel<<<dim3((HWP + 127)/128, (2*DIM)/128, BATCH), 256, CV_SMEM>>>(
      wh + WOFF_KV, wl + WOFF_KV, pfh, kv_b, (float*)nullptr, kvh, kvl, 2*DIM, DIM, HWP);
  // 6. attention -> gf16
  attn7_kernel<<<BATCH*HEADS*7, 128, A6_BYTES>>>(qh, kvh, kvl, gf16);
  // 7. local mixer + gating (fp16 in/out, 4-wide) -> mh
  local_gate_hf4_kernel<<<(BATCH*DIM*HH*14 + 255)/256, 256>>>(qh, loc_w, loc_b, gf16, mh);
  // 8. out = conv1x1(mixbuf) -> f32
  conv1x1_hf_kernel<<<dim3((HWX + 127)/128, DIM/128, BATCH), 256, CV_SMEM>>>(
      wh + WOFF_MIX, wl + WOFF_MIX, mh, mix_b, out, (fp16*)nullptr, (fp16*)nullptr, DIM, DIM, HWX);
}